// round 3
// baseline (speedup 1.0000x reference)
#include <cuda_runtime.h>
#include <cstdint>

#define BB 32
#define SS 128
#define TT 96
#define HH 1024
#define VV 32000
#define H3 3072
#define H2 2048
#define SPLITK 8

// ---------------- scratch (static device globals; no allocation) ----------------
__device__ float g_values[BB * SS * HH];      // 16 MB
__device__ float g_vw[BB * SS * HH];          // 16 MB
__device__ float g_gi[BB * TT * H3];          // 36 MB
__device__ float g_ghp[SPLITK * BB * H3];     // 3 MB
__device__ float g_qwp[SPLITK * BB * HH];     // 1 MB
__device__ float g_qw[BB * HH];
__device__ float g_h[BB * HH];
__device__ float g_scores[BB * SS];
__device__ float g_combined[BB * TT * H2];    // 24 MB

// ---------------- fast-accurate transcendentals (MUFU-based, ~1e-7 rel) --------
__device__ __forceinline__ float ex2f(float x) {
    float y; asm("ex2.approx.f32 %0, %1;" : "=f"(y) : "f"(x)); return y;
}
__device__ __forceinline__ float rcpf(float x) {
    float y; asm("rcp.approx.f32 %0, %1;" : "=f"(y) : "f"(x)); return y;
}
__device__ __forceinline__ float sigmf(float x) {
    return rcpf(1.0f + ex2f(-1.4426950408889634f * x));
}
__device__ __forceinline__ float tanhx(float x) {
    // tanh(x) = 1 - 2/(e^{2x}+1), e^{2x} = 2^{2x*log2(e)}
    float e = ex2f(2.8853900817779268f * x);
    return 1.0f - 2.0f * rcpf(e + 1.0f);
}

// ---------------- main tiled SGEMM: C = A @ B + bias -----------------------------
// A: [M,K] row-major (optionally row-gathered), B: [K,N] row-major, C: [M,N].
// N must be a multiple of 128, K a multiple of 16. M may be ragged.
#define GM_BM 128
#define GM_BN 128
#define GM_BK 16
#define GM_TM 8
#define GM_TN 8
#define GM_PAD 4

template <bool GATHER>
__global__ __launch_bounds__(256, 2)
void sgemm_kernel(const float* __restrict__ A, const float* __restrict__ Bm,
                  const float* __restrict__ bias, float* __restrict__ C,
                  int M, int N, int K, const int* __restrict__ gidx) {
    __shared__ float As[GM_BK][GM_BM + GM_PAD];
    __shared__ float Bs[GM_BK][GM_BN];
    const int tid = threadIdx.x;
    const int row0 = blockIdx.y * GM_BM;
    const int col0 = blockIdx.x * GM_BN;
    const int tr = tid >> 4;   // 0..15
    const int tc = tid & 15;   // 0..15

    float acc[GM_TM][GM_TN];
#pragma unroll
    for (int i = 0; i < GM_TM; i++)
#pragma unroll
        for (int j = 0; j < GM_TN; j++) acc[i][j] = 0.0f;

    for (int k0 = 0; k0 < K; k0 += GM_BK) {
        // load A tile (BM x BK), stored transposed As[k][m]
        for (int i = tid; i < GM_BM * GM_BK; i += 256) {
            int r = i >> 4;
            int c = i & 15;
            int gr = row0 + r;
            float v = 0.0f;
            if (gr < M) {
                long ar = GATHER ? (long)gidx[gr] : (long)gr;
                v = A[ar * (long)K + (k0 + c)];
            }
            As[c][r] = v;
        }
        // load B tile (BK x BN)
        for (int i = tid; i < GM_BK * GM_BN; i += 256) {
            int r = i >> 7;
            int c = i & 127;
            Bs[r][c] = Bm[(long)(k0 + r) * N + (col0 + c)];
        }
        __syncthreads();
#pragma unroll
        for (int k = 0; k < GM_BK; k++) {
            float4 a0 = *(const float4*)&As[k][tr * GM_TM];
            float4 a1 = *(const float4*)&As[k][tr * GM_TM + 4];
            float4 b0 = *(const float4*)&Bs[k][tc * GM_TN];
            float4 b1 = *(const float4*)&Bs[k][tc * GM_TN + 4];
            float ra[8] = {a0.x, a0.y, a0.z, a0.w, a1.x, a1.y, a1.z, a1.w};
            float rb[8] = {b0.x, b0.y, b0.z, b0.w, b1.x, b1.y, b1.z, b1.w};
#pragma unroll
            for (int i = 0; i < 8; i++)
#pragma unroll
                for (int j = 0; j < 8; j++) acc[i][j] += ra[i] * rb[j];
        }
        __syncthreads();
    }
#pragma unroll
    for (int i = 0; i < GM_TM; i++) {
        int r = row0 + tr * GM_TM + i;
        if (r >= M) continue;
        float* Cr = C + (long)r * N + col0 + tc * GM_TN;
        const float* br = bias + col0 + tc * GM_TN;
#pragma unroll
        for (int j = 0; j < GM_TN; j++) Cr[j] = acc[i][j] + br[j];
    }
}

// ---------------- small-M (M=32) split-K GEMM into partials ---------------------
// Cp[split][32][N] = A[32, k0:k0+kslice] @ B[k0:k0+kslice, N]
// grid: (N/64, SPLITK); 256 threads; thread = (b = tid&31, ngroup = tid>>5)
__global__ void gemm_m32_kernel(const float* __restrict__ A, const float* __restrict__ Bm,
                                float* __restrict__ Cp, int N, int K) {
    extern __shared__ float sh[];   // [32][kslice+1]
    const int kslice = K / SPLITK;
    const int pitch = kslice + 1;
    const int tid = threadIdx.x;
    const int k0 = blockIdx.y * kslice;
    const int col0 = blockIdx.x * 64;

    for (int i = tid; i < 32 * kslice; i += 256) {
        int b = i / kslice;
        int k = i - b * kslice;
        sh[b * pitch + k] = A[b * K + k0 + k];
    }
    __syncthreads();

    const int b = tid & 31;
    const int ng = tid >> 5;
    const float* Bp = Bm + (long)k0 * N + col0 + ng * 8;
    const float* hp = sh + b * pitch;
    float a0 = 0, a1 = 0, a2 = 0, a3 = 0, a4 = 0, a5 = 0, a6 = 0, a7 = 0;
#pragma unroll 4
    for (int k = 0; k < kslice; k++) {
        float a = hp[k];
        float4 w0 = *(const float4*)(Bp + (long)k * N);
        float4 w1 = *(const float4*)(Bp + (long)k * N + 4);
        a0 += a * w0.x; a1 += a * w0.y; a2 += a * w0.z; a3 += a * w0.w;
        a4 += a * w1.x; a5 += a * w1.y; a6 += a * w1.z; a7 += a * w1.w;
    }
    float* outp = Cp + ((long)blockIdx.y * 32 + b) * N + col0 + ng * 8;
    outp[0] = a0; outp[1] = a1; outp[2] = a2; outp[3] = a3;
    outp[4] = a4; outp[5] = a5; outp[6] = a6; outp[7] = a7;
}

// out[i] = sum_p part[p][i] + bias[i % biasN]
__global__ void reduce8_bias_kernel(const float* __restrict__ part,
                                    const float* __restrict__ bias,
                                    float* __restrict__ out, int n, int biasN) {
    int i = blockIdx.x * 256 + threadIdx.x;
    if (i >= n) return;
    float s = bias[i % biasN];
#pragma unroll
    for (int p = 0; p < SPLITK; p++) s += part[(long)p * n + i];
    out[i] = s;
}

// ---------------- fused GRU gates -----------------------------------------------
__global__ void gates_kernel(const float* __restrict__ gi, const float* __restrict__ ghp,
                             const float* __restrict__ bhh, float* __restrict__ h,
                             float* __restrict__ combined, int t) {
    int i = blockIdx.x * 256 + threadIdx.x;   // 0 .. 32*1024-1
    int b = i >> 10;
    int n = i & 1023;
    float hr = bhh[n], hz = bhh[HH + n], hn = bhh[2 * HH + n];
#pragma unroll
    for (int p = 0; p < SPLITK; p++) {
        const float* g = ghp + ((long)p * 32 + b) * H3;
        hr += g[n]; hz += g[HH + n]; hn += g[2 * HH + n];
    }
    const float* gir = gi + ((long)b * TT + t) * H3;
    float r = sigmf(gir[n] + hr);
    float z = sigmf(gir[HH + n] + hz);
    float nn = tanhx(gir[2 * HH + n] + r * hn);
    float hv = (1.0f - z) * nn + z * h[i];
    h[i] = hv;
    combined[((long)b * TT + t) * H2 + n] = hv;
}

// ---------------- attention scores: block per (b,s) -----------------------------
__global__ void scores_kernel(const float* __restrict__ qw, const float* __restrict__ vw,
                              const float* __restrict__ wc, const float* __restrict__ bc,
                              const int* __restrict__ mask, float* __restrict__ scores) {
    __shared__ float red[256];
    const int bs = blockIdx.x;
    const int b = bs >> 7;
    const float* v = vw + (long)bs * HH;
    const float* q = qw + (long)b * HH;
    float a = 0.0f;
    for (int hh = threadIdx.x; hh < HH; hh += 256)
        a += wc[hh] * tanhx(q[hh] + v[hh]);
    red[threadIdx.x] = a;
    __syncthreads();
#pragma unroll
    for (int off = 128; off > 0; off >>= 1) {
        if (threadIdx.x < off) red[threadIdx.x] += red[threadIdx.x + off];
        __syncthreads();
    }
    if (threadIdx.x == 0)
        scores[bs] = red[0] + bc[0] + (mask[bs] == 0 ? -1e30f : 0.0f);
}

// ---------------- softmax (redundant per block) + context -----------------------
// grid (BB, HH/128); 128 threads; each thread one h element.
__global__ void ctx_kernel(const float* __restrict__ scores, const float* __restrict__ values,
                           float* __restrict__ combined, int t) {
    __shared__ float w[SS];
    __shared__ float red[SS];
    const int b = blockIdx.x;
    const int tid = threadIdx.x;
    float sc = scores[b * SS + tid];
    red[tid] = sc;
    __syncthreads();
#pragma unroll
    for (int off = 64; off > 0; off >>= 1) {
        if (tid < off) red[tid] = fmaxf(red[tid], red[tid + off]);
        __syncthreads();
    }
    float mx = red[0];
    __syncthreads();
    float e = ex2f((sc - mx) * 1.4426950408889634f);
    red[tid] = e;
    __syncthreads();
#pragma unroll
    for (int off = 64; off > 0; off >>= 1) {
        if (tid < off) red[tid] += red[tid + off];
        __syncthreads();
    }
    w[tid] = e * rcpf(red[0]);
    __syncthreads();

    const int h = blockIdx.y * 128 + tid;
    const float* vb = values + (long)b * SS * HH + h;
    float acc = 0.0f;
#pragma unroll
    for (int s = 0; s < SS; s++) acc += w[s] * vb[(long)s * HH];
    combined[((long)b * TT + t) * H2 + HH + h] = acc;
}

__global__ void copyh_kernel(const float* __restrict__ h, float* __restrict__ out) {
    int i = blockIdx.x * 256 + threadIdx.x;
    if (i < BB * HH) out[i] = h[i];
}

// ---------------- launch --------------------------------------------------------
extern "C" void kernel_launch(void* const* d_in, const int* in_sizes, int n_in,
                              void* d_out, int out_size) {
    const float* enc_out = (const float*)d_in[0];   // [B,S,2H]
    const float* enc_hid = (const float*)d_in[1];   // [B,2H]
    const int*   mask    = (const int*)d_in[2];     // [B,S]
    const int*   tgt     = (const int*)d_in[3];     // [B,T]
    const float* emb     = (const float*)d_in[4];   // [V,H]
    const float* Wq   = (const float*)d_in[5];
    const float* bq   = (const float*)d_in[6];
    const float* Wv   = (const float*)d_in[7];
    const float* bv   = (const float*)d_in[8];
    const float* wc   = (const float*)d_in[9];
    const float* bc   = (const float*)d_in[10];
    const float* Wih  = (const float*)d_in[11];
    const float* bih  = (const float*)d_in[12];
    const float* Whh  = (const float*)d_in[13];
    const float* bhh  = (const float*)d_in[14];
    const float* Wproj = (const float*)d_in[15];
    const float* bproj = (const float*)d_in[16];
    const float* Wout  = (const float*)d_in[17];
    const float* bout  = (const float*)d_in[18];
    float* out = (float*)d_out;

    float *values, *vw, *gi, *ghp, *qwp, *qw, *h, *scores, *combined;
    cudaGetSymbolAddress((void**)&values, g_values);
    cudaGetSymbolAddress((void**)&vw, g_vw);
    cudaGetSymbolAddress((void**)&gi, g_gi);
    cudaGetSymbolAddress((void**)&ghp, g_ghp);
    cudaGetSymbolAddress((void**)&qwp, g_qwp);
    cudaGetSymbolAddress((void**)&qw, g_qw);
    cudaGetSymbolAddress((void**)&h, g_h);
    cudaGetSymbolAddress((void**)&scores, g_scores);
    cudaGetSymbolAddress((void**)&combined, g_combined);

    // ---- Phase A: step-invariant precompute ----
    // values = enc_out @ Wproj + bproj   [4096,2048]@[2048,1024]
    sgemm_kernel<false><<<dim3(HH / 128, (BB * SS) / 128), 256>>>(
        enc_out, Wproj, bproj, values, BB * SS, HH, H2, nullptr);
    // vw = values @ Wv + bv              [4096,1024]@[1024,1024]
    sgemm_kernel<false><<<dim3(HH / 128, (BB * SS) / 128), 256>>>(
        values, Wv, bv, vw, BB * SS, HH, HH, nullptr);
    // gi = embedding[tgt] @ Wih + bih    [3072,1024]@[1024,3072]
    sgemm_kernel<true><<<dim3(H3 / 128, (BB * TT) / 128), 256>>>(
        emb, Wih, bih, gi, BB * TT, H3, HH, tgt);
    // h0 = enc_hid @ Wproj + bproj (M=32, split-K)
    {
        int ks = H2 / SPLITK;
        size_t sm = 32 * (ks + 1) * sizeof(float);
        gemm_m32_kernel<<<dim3(HH / 64, SPLITK), 256, sm>>>(enc_hid, Wproj, qwp, HH, H2);
        reduce8_bias_kernel<<<(BB * HH + 255) / 256, 256>>>(qwp, bproj, h, BB * HH, HH);
    }

    // ---- Phase B: sequential recurrence ----
    for (int t = 0; t < TT; t++) {
        {   // gh partials = h @ Whh
            int ks = HH / SPLITK;
            size_t sm = 32 * (ks + 1) * sizeof(float);
            gemm_m32_kernel<<<dim3(H3 / 64, SPLITK), 256, sm>>>(h, Whh, ghp, H3, HH);
        }
        gates_kernel<<<(BB * HH) / 256, 256>>>(gi, ghp, bhh, h, combined, t);
        {   // qw partials = h_new @ Wq
            int ks = HH / SPLITK;
            size_t sm = 32 * (ks + 1) * sizeof(float);
            gemm_m32_kernel<<<dim3(HH / 64, SPLITK), 256, sm>>>(h, Wq, qwp, HH, HH);
        }
        reduce8_bias_kernel<<<(BB * HH + 255) / 256, 256>>>(qwp, bq, qw, BB * HH, HH);
        scores_kernel<<<BB * SS, 256>>>(qw, vw, wc, bc, mask, scores);
        ctx_kernel<<<dim3(BB, HH / 128), 128>>>(scores, values, combined, t);
    }

    // ---- Phase C: logits = combined @ Wout + bout  [3072,2048]@[2048,32000] ----
    sgemm_kernel<false><<<dim3(VV / 128, (BB * TT) / 128), 256>>>(
        combined, Wout, bout, out, BB * TT, VV, H2, nullptr);

    // decoder_hidden output appended after logits
    long btv = (long)BB * TT * VV;
    if ((long)out_size >= btv + BB * HH)
        copyh_kernel<<<(BB * HH + 255) / 256, 256>>>(h, out + btv);
}

// round 9
// speedup vs baseline: 2.1693x; 2.1693x over previous
#include <cuda_runtime.h>
#include <cuda_bf16.h>
#include <cstdint>

#define BB 32
#define SS 128
#define TT 96
#define HH 1024
#define VV 32000
#define H3 3072
#define H2 2048
#define KSPLIT 8

// ---------------- scratch (static device globals; no allocation) ----------------
__device__ float g_values[BB * SS * HH];
__device__ float g_vw[BB * SS * HH];
__device__ float g_gi[BB * TT * H3];
__device__ float g_ghp[KSPLIT * BB * H3];
__device__ float g_qwp[KSPLIT * BB * HH];
__device__ float g_qw[BB * HH];
__device__ float g_h[BB * HH];
__device__ float g_scores[BB * SS];
__device__ float g_combined[BB * TT * H2];
// bf16 hi/lo staging
__device__ __nv_bfloat16 g_ahi[4096 * 2048];
__device__ __nv_bfloat16 g_alo[4096 * 2048];
__device__ __nv_bfloat16 g_whi[32000u * 2048u];
__device__ __nv_bfloat16 g_wlo[32000u * 2048u];

// ---------------- fast transcendentals ------------------------------------------
__device__ __forceinline__ float ex2f(float x) {
    float y; asm("ex2.approx.f32 %0, %1;" : "=f"(y) : "f"(x)); return y;
}
__device__ __forceinline__ float rcpf(float x) {
    float y; asm("rcp.approx.f32 %0, %1;" : "=f"(y) : "f"(x)); return y;
}
__device__ __forceinline__ float sigmf(float x) {
    return rcpf(1.0f + ex2f(-1.4426950408889634f * x));
}
__device__ __forceinline__ float tanhx(float x) {
    float e = ex2f(2.8853900817779268f * x);
    return 1.0f - 2.0f * rcpf(e + 1.0f);
}

__device__ __forceinline__ uint32_t smem_to_u32(const void* p) {
    uint32_t a;
    asm("{ .reg .u64 t; cvta.to.shared.u64 t, %1; cvt.u32.u64 %0, t; }" : "=r"(a) : "l"(p));
    return a;
}

// ---------------- mma.sync primitives (sm_80 ISA — valid on compute_103) ---------
__device__ __forceinline__ void ldsm_x4(uint32_t* r, uint32_t addr) {
    asm volatile("ldmatrix.sync.aligned.m8n8.x4.shared.b16 {%0,%1,%2,%3}, [%4];"
        : "=r"(r[0]), "=r"(r[1]), "=r"(r[2]), "=r"(r[3]) : "r"(addr));
}
__device__ __forceinline__ void mma16816(float* d, const uint32_t* a, uint32_t b0, uint32_t b1) {
    asm volatile("mma.sync.aligned.m16n8k16.row.col.f32.bf16.bf16.f32 "
        "{%0,%1,%2,%3}, {%4,%5,%6,%7}, {%8,%9}, {%0,%1,%2,%3};"
        : "+f"(d[0]), "+f"(d[1]), "+f"(d[2]), "+f"(d[3])
        : "r"(a[0]), "r"(a[1]), "r"(a[2]), "r"(a[3]), "r"(b0), "r"(b1));
}
__device__ __forceinline__ void cp16(uint32_t dst, const void* src) {
    asm volatile("cp.async.cg.shared.global [%0], [%1], 16;" :: "r"(dst), "l"(src));
}

// ---------------- hi/lo conversion kernels ---------------------------------------
// W [K,N] fp32 -> whi/wlo [N,K] bf16 (transpose + split). grid (N/32, K/32), block (32,8)
__global__ void wconv_kernel(const float* __restrict__ W, __nv_bfloat16* __restrict__ whi,
                             __nv_bfloat16* __restrict__ wlo, int K, int N) {
    __shared__ float t[32][33];
    int n0 = blockIdx.x * 32, k0 = blockIdx.y * 32;
    int tx = threadIdx.x, ty = threadIdx.y;
#pragma unroll
    for (int j = 0; j < 4; j++)
        t[ty + 8 * j][tx] = W[(long)(k0 + ty + 8 * j) * N + n0 + tx];
    __syncthreads();
#pragma unroll
    for (int j = 0; j < 4; j++) {
        int n = n0 + ty + 8 * j;
        float x = t[tx][ty + 8 * j];
        __nv_bfloat16 h = __float2bfloat16(x);
        float r = x - __bfloat162float(h);
        long o = (long)n * K + k0 + tx;
        whi[o] = h;
        wlo[o] = __float2bfloat16(r);
    }
}

__global__ void aconv_kernel(const float* __restrict__ A, __nv_bfloat16* __restrict__ ahi,
                             __nv_bfloat16* __restrict__ alo, int n) {
    int i = blockIdx.x * 256 + threadIdx.x;
    if (i >= n) return;
    float x = A[i];
    __nv_bfloat16 h = __float2bfloat16(x);
    ahi[i] = h;
    alo[i] = __float2bfloat16(x - __bfloat162float(h));
}

__global__ void aconv_gather_kernel(const float* __restrict__ emb, const int* __restrict__ idx,
                                    __nv_bfloat16* __restrict__ ahi, __nv_bfloat16* __restrict__ alo,
                                    int n) {
    int i = blockIdx.x * 256 + threadIdx.x;
    if (i >= n) return;
    int r = i >> 10, k = i & 1023;
    float x = emb[(long)idx[r] * HH + k];
    __nv_bfloat16 h = __float2bfloat16(x);
    ahi[i] = h;
    alo[i] = __float2bfloat16(x - __bfloat162float(h));
}

// ---------------- HMMA GEMM: C[M,N] = (Ahi+Alo) @ (Bhi+Blo)^T + bias --------------
// Ahi/Alo [M,K] bf16 K-major; Bhi/Blo [N,K] bf16 K-major. C fp32 [M,N].
// grid (M/128, N/128), 256 thr = 8 warps (4M x 2N), warp tile 32x64, BK=32,
// double-buffered cp.async. 3 products: hi*hi + lo*hi + hi*lo.
#define MM_PITCH 40                        // bf16/row in smem (80B: conflict-free ldmatrix)
#define MM_MAT (128 * MM_PITCH * 2)        // 10240 B per matrix tile
#define MM_STAGE (4 * MM_MAT)              // 40960 B
#define MM_SMEM (2 * MM_STAGE)             // 81920 B

__global__ __launch_bounds__(256, 2)
void mma_gemm_kernel(const __nv_bfloat16* __restrict__ Ahi, const __nv_bfloat16* __restrict__ Alo,
                     const __nv_bfloat16* __restrict__ Bhi, const __nv_bfloat16* __restrict__ Blo,
                     const float* __restrict__ bias, float* __restrict__ C, int K, int N) {
    extern __shared__ __align__(16) char smem[];
    const uint32_t sb = smem_to_u32(smem);
    const int tid = threadIdx.x;
    const int wid = tid >> 5, lane = tid & 31;
    const int m0 = blockIdx.x * 128, n0 = blockIdx.y * 128;
    const int wm = (wid >> 1) * 32;    // warp row offset (4 warps in M)
    const int wn = (wid & 1) * 64;     // warp col offset (2 warps in N)
    const int NC = K >> 5;             // K chunks of 32

    const __nv_bfloat16* gp0 = Ahi + (long)m0 * K;
    const __nv_bfloat16* gp1 = Alo + (long)m0 * K;
    const __nv_bfloat16* gp2 = Bhi + (long)n0 * K;
    const __nv_bfloat16* gp3 = Blo + (long)n0 * K;

    float acc[2][8][4];
#pragma unroll
    for (int a = 0; a < 2; a++)
#pragma unroll
        for (int b = 0; b < 8; b++)
#pragma unroll
            for (int c = 0; c < 4; c++) acc[a][b][c] = 0.0f;

    // per-lane ldmatrix coordinates
    const int arow = lane & 15;                           // + wm + tm*16
    const int acol = (lane >> 4) << 3;                    // + ks*16
    const int brow = ((lane >> 4) << 3) + (lane & 7);     // + wn + gn*16
    const int bcol = ((lane >> 3) & 1) << 3;              // + ks*16

    auto issue = [&](int c, int buf) {
        const uint32_t base = sb + buf * MM_STAGE;
        const long k0 = (long)c << 5;
        for (int i = tid; i < 2048; i += 256) {
            int mat = i >> 9, r = (i >> 2) & 127, s = i & 3;
            const __nv_bfloat16* g = (mat == 0) ? gp0 : (mat == 1) ? gp1 : (mat == 2) ? gp2 : gp3;
            cp16(base + mat * MM_MAT + r * (MM_PITCH * 2) + s * 16,
                 (const char*)(g + (long)r * K + k0) + s * 16);
        }
        asm volatile("cp.async.commit_group;" ::: "memory");
    };

    issue(0, 0);

    for (int c = 0; c < NC; c++) {
        const int buf = c & 1;
        if (c + 1 < NC) {
            issue(c + 1, buf ^ 1);
            asm volatile("cp.async.wait_group 1;" ::: "memory");
        } else {
            asm volatile("cp.async.wait_group 0;" ::: "memory");
        }
        __syncthreads();

        const uint32_t base = sb + buf * MM_STAGE;
#pragma unroll
        for (int ks = 0; ks < 2; ks++) {
            const int kc = ks * 16;
            uint32_t ah[2][4], al[2][4], bb[4][4];
#pragma unroll
            for (int tm = 0; tm < 2; tm++) {
                uint32_t ad = base + (uint32_t)(((wm + tm * 16 + arow) * MM_PITCH + kc + acol) * 2);
                ldsm_x4(ah[tm], ad);
                ldsm_x4(al[tm], ad + MM_MAT);
            }
#pragma unroll
            for (int gn = 0; gn < 4; gn++) {
                uint32_t bd = base + 2 * MM_MAT +
                    (uint32_t)(((wn + gn * 16 + brow) * MM_PITCH + kc + bcol) * 2);
                ldsm_x4(bb[gn], bd);
            }
            // hi*hi + lo*hi (share B regs)
#pragma unroll
            for (int tm = 0; tm < 2; tm++)
#pragma unroll
                for (int j = 0; j < 8; j++) {
                    uint32_t b0 = bb[j >> 1][(j & 1) * 2];
                    uint32_t b1 = bb[j >> 1][(j & 1) * 2 + 1];
                    mma16816(acc[tm][j], ah[tm], b0, b1);
                    mma16816(acc[tm][j], al[tm], b0, b1);
                }
            // hi*lo
#pragma unroll
            for (int gn = 0; gn < 4; gn++) {
                uint32_t bd = base + 3 * MM_MAT +
                    (uint32_t)(((wn + gn * 16 + brow) * MM_PITCH + kc + bcol) * 2);
                ldsm_x4(bb[gn], bd);
            }
#pragma unroll
            for (int tm = 0; tm < 2; tm++)
#pragma unroll
                for (int j = 0; j < 8; j++)
                    mma16816(acc[tm][j], ah[tm],
                             bb[j >> 1][(j & 1) * 2], bb[j >> 1][(j & 1) * 2 + 1]);
        }
        __syncthreads();
    }

    // epilogue: frag (tm,j): lane holds C[row + l/4][col + (l%4)*2 + {0,1}], rows +8 for c2/c3
#pragma unroll
    for (int tm = 0; tm < 2; tm++) {
        const int r0 = m0 + wm + tm * 16 + (lane >> 2);
#pragma unroll
        for (int j = 0; j < 8; j++) {
            const int col = n0 + wn + j * 8 + (lane & 3) * 2;
            float b0 = bias[col], b1 = bias[col + 1];
            float* p0 = C + (long)r0 * N + col;
            p0[0] = acc[tm][j][0] + b0;
            p0[1] = acc[tm][j][1] + b1;
            float* p1 = p0 + 8 * (long)N;
            p1[0] = acc[tm][j][2] + b0;
            p1[1] = acc[tm][j][3] + b1;
        }
    }
}

// ---------------- small-M (M=32) split-K GEMM -> partials ------------------------
// grid (N/32, ksplit), 256 thr (8 warps x 4 cols), lane=batch. B loads warp-uniform.
__global__ void gemm_m32_kernel(const float* __restrict__ A, const float* __restrict__ Bm,
                                float* __restrict__ Cp, int N, int K, int ksplit) {
    extern __shared__ float sh[];       // [kslice][33]
    const int kslice = K / ksplit;
    const int tid = threadIdx.x;
    const int k0 = blockIdx.y * kslice;

    for (int i = tid; i < 32 * kslice; i += 256) {
        int b = i / kslice;
        int k = i - b * kslice;
        sh[k * 33 + b] = A[b * K + k0 + k];
    }
    __syncthreads();

    const int w = tid >> 5, lane = tid & 31;
    const int n0 = blockIdx.x * 32 + w * 4;
    const float* Bp = Bm + (long)k0 * N + n0;
    float a0 = 0.f, a1 = 0.f, a2 = 0.f, a3 = 0.f;
#pragma unroll 8
    for (int k = 0; k < kslice; k++) {
        float4 wv = *(const float4*)(Bp + (long)k * N);
        float a = sh[k * 33 + lane];
        a0 += a * wv.x; a1 += a * wv.y; a2 += a * wv.z; a3 += a * wv.w;
    }
    float4* o = (float4*)(Cp + ((long)blockIdx.y * 32 + lane) * N + n0);
    *o = make_float4(a0, a1, a2, a3);
}

__global__ void reduce8_bias_kernel(const float* __restrict__ part, const float* __restrict__ bias,
                                    float* __restrict__ out, int n, int biasN) {
    int i = blockIdx.x * 256 + threadIdx.x;
    if (i >= n) return;
    float s = bias[i % biasN];
#pragma unroll
    for (int p = 0; p < KSPLIT; p++) s += part[(long)p * n + i];
    out[i] = s;
}

// ---------------- fused GRU gates -------------------------------------------------
__global__ void gates_kernel(const float* __restrict__ gi, const float* __restrict__ ghp,
                             const float* __restrict__ bhh, float* __restrict__ h,
                             float* __restrict__ combined, int t) {
    int i = blockIdx.x * 256 + threadIdx.x;
    int b = i >> 10;
    int n = i & 1023;
    float hr = bhh[n], hz = bhh[HH + n], hn = bhh[2 * HH + n];
#pragma unroll
    for (int p = 0; p < KSPLIT; p++) {
        const float* g = ghp + ((long)p * 32 + b) * H3;
        hr += g[n]; hz += g[HH + n]; hn += g[2 * HH + n];
    }
    const float* gir = gi + ((long)b * TT + t) * H3;
    float r = sigmf(gir[n] + hr);
    float z = sigmf(gir[HH + n] + hz);
    float nn = tanhx(gir[2 * HH + n] + r * hn);
    float hv = (1.0f - z) * nn + z * h[i];
    h[i] = hv;
    combined[((long)b * TT + t) * H2 + n] = hv;
}

// ---------------- attention scores ------------------------------------------------
__global__ void scores_kernel(const float* __restrict__ qw, const float* __restrict__ vw,
                              const float* __restrict__ wc, const float* __restrict__ bc,
                              const int* __restrict__ mask, float* __restrict__ scores) {
    __shared__ float red[256];
    const int bs = blockIdx.x;
    const int b = bs >> 7;
    const float* v = vw + (long)bs * HH;
    const float* q = qw + (long)b * HH;
    float a = 0.0f;
    for (int hh = threadIdx.x; hh < HH; hh += 256)
        a += wc[hh] * tanhx(q[hh] + v[hh]);
    red[threadIdx.x] = a;
    __syncthreads();
#pragma unroll
    for (int off = 128; off > 0; off >>= 1) {
        if (threadIdx.x < off) red[threadIdx.x] += red[threadIdx.x + off];
        __syncthreads();
    }
    if (threadIdx.x == 0)
        scores[bs] = red[0] + bc[0] + (mask[bs] == 0 ? -1e30f : 0.0f);
}

// ---------------- softmax + context ----------------------------------------------
__global__ void ctx_kernel(const float* __restrict__ scores, const float* __restrict__ values,
                           float* __restrict__ combined, int t) {
    __shared__ float w[SS];
    __shared__ float red[SS];
    const int b = blockIdx.x;
    const int tid = threadIdx.x;
    float sc = scores[b * SS + tid];
    red[tid] = sc;
    __syncthreads();
#pragma unroll
    for (int off = 64; off > 0; off >>= 1) {
        if (tid < off) red[tid] = fmaxf(red[tid], red[tid + off]);
        __syncthreads();
    }
    float mx = red[0];
    __syncthreads();
    float e = ex2f((sc - mx) * 1.4426950408889634f);
    red[tid] = e;
    __syncthreads();
#pragma unroll
    for (int off = 64; off > 0; off >>= 1) {
        if (tid < off) red[tid] += red[tid + off];
        __syncthreads();
    }
    w[tid] = e * rcpf(red[0]);
    __syncthreads();

    const int hidx = blockIdx.y * 128 + tid;
    const float* vb = values + (long)b * SS * HH + hidx;
    float acc = 0.0f;
#pragma unroll
    for (int s = 0; s < SS; s++) acc += w[s] * vb[(long)s * HH];
    combined[((long)b * TT + t) * H2 + HH + hidx] = acc;
}

__global__ void copyh_kernel(const float* __restrict__ h, float* __restrict__ out) {
    int i = blockIdx.x * 256 + threadIdx.x;
    if (i < BB * HH) out[i] = h[i];
}

// ---------------- launch ----------------------------------------------------------
extern "C" void kernel_launch(void* const* d_in, const int* in_sizes, int n_in,
                              void* d_out, int out_size) {
    const float* enc_out = (const float*)d_in[0];
    const float* enc_hid = (const float*)d_in[1];
    const int*   mask    = (const int*)d_in[2];
    const int*   tgt     = (const int*)d_in[3];
    const float* emb     = (const float*)d_in[4];
    const float* Wq   = (const float*)d_in[5];
    const float* bq   = (const float*)d_in[6];
    const float* Wv   = (const float*)d_in[7];
    const float* bv   = (const float*)d_in[8];
    const float* wc   = (const float*)d_in[9];
    const float* bc   = (const float*)d_in[10];
    const float* Wih  = (const float*)d_in[11];
    const float* bih  = (const float*)d_in[12];
    const float* Whh  = (const float*)d_in[13];
    const float* bhh  = (const float*)d_in[14];
    const float* Wproj = (const float*)d_in[15];
    const float* bproj = (const float*)d_in[16];
    const float* Wout  = (const float*)d_in[17];
    const float* bout  = (const float*)d_in[18];
    float* out = (float*)d_out;

    float *values, *vw, *gi, *ghp, *qwp, *qw, *h, *scores, *combined;
    __nv_bfloat16 *ahi, *alo, *whi, *wlo;
    cudaGetSymbolAddress((void**)&values, g_values);
    cudaGetSymbolAddress((void**)&vw, g_vw);
    cudaGetSymbolAddress((void**)&gi, g_gi);
    cudaGetSymbolAddress((void**)&ghp, g_ghp);
    cudaGetSymbolAddress((void**)&qwp, g_qwp);
    cudaGetSymbolAddress((void**)&qw, g_qw);
    cudaGetSymbolAddress((void**)&h, g_h);
    cudaGetSymbolAddress((void**)&scores, g_scores);
    cudaGetSymbolAddress((void**)&combined, g_combined);
    cudaGetSymbolAddress((void**)&ahi, g_ahi);
    cudaGetSymbolAddress((void**)&alo, g_alo);
    cudaGetSymbolAddress((void**)&whi, g_whi);
    cudaGetSymbolAddress((void**)&wlo, g_wlo);

    cudaFuncSetAttribute(mma_gemm_kernel, cudaFuncAttributeMaxDynamicSharedMemorySize, MM_SMEM);

    // ---- Phase A (HMMA tensor path) ----
    // values = enc_out @ Wproj + bproj     [4096,2048] @ [2048,1024]
    wconv_kernel<<<dim3(HH / 32, H2 / 32), dim3(32, 8)>>>(Wproj, whi, wlo, H2, HH);
    aconv_kernel<<<(4096 * 2048) / 256, 256>>>(enc_out, ahi, alo, 4096 * 2048);
    mma_gemm_kernel<<<dim3(4096 / 128, HH / 128), 256, MM_SMEM>>>(ahi, alo, whi, wlo, bproj, values, H2, HH);
    // vw = values @ Wv + bv                [4096,1024] @ [1024,1024]
    wconv_kernel<<<dim3(HH / 32, HH / 32), dim3(32, 8)>>>(Wv, whi, wlo, HH, HH);
    aconv_kernel<<<(4096 * 1024) / 256, 256>>>(values, ahi, alo, 4096 * 1024);
    mma_gemm_kernel<<<dim3(4096 / 128, HH / 128), 256, MM_SMEM>>>(ahi, alo, whi, wlo, bv, vw, HH, HH);
    // gi = embedding[tgt] @ Wih + bih      [3072,1024] @ [1024,3072]
    wconv_kernel<<<dim3(H3 / 32, HH / 32), dim3(32, 8)>>>(Wih, whi, wlo, HH, H3);
    aconv_gather_kernel<<<(BB * TT * HH) / 256, 256>>>(emb, tgt, ahi, alo, BB * TT * HH);
    mma_gemm_kernel<<<dim3((BB * TT) / 128, H3 / 128), 256, MM_SMEM>>>(ahi, alo, whi, wlo, bih, gi, HH, H3);
    // h0 = enc_hid @ Wproj + bproj (M=32 split-K)
    gemm_m32_kernel<<<dim3(HH / 32, KSPLIT), 256, (H2 / KSPLIT) * 33 * 4>>>(enc_hid, Wproj, qwp, HH, H2, KSPLIT);
    reduce8_bias_kernel<<<(BB * HH + 255) / 256, 256>>>(qwp, bproj, h, BB * HH, HH);

    // ---- Phase B: recurrence ----
    for (int t = 0; t < TT; t++) {
        gemm_m32_kernel<<<dim3(H3 / 32, KSPLIT), 256, (HH / KSPLIT) * 33 * 4>>>(h, Whh, ghp, H3, HH, KSPLIT);
        gates_kernel<<<(BB * HH) / 256, 256>>>(gi, ghp, bhh, h, combined, t);
        gemm_m32_kernel<<<dim3(HH / 32, KSPLIT), 256, (HH / KSPLIT) * 33 * 4>>>(h, Wq, qwp, HH, HH, KSPLIT);
        reduce8_bias_kernel<<<(BB * HH + 255) / 256, 256>>>(qwp, bq, qw, BB * HH, HH);
        scores_kernel<<<BB * SS, 256>>>(qw, vw, wc, bc, mask, scores);
        ctx_kernel<<<dim3(BB, HH / 128), 128>>>(scores, values, combined, t);
    }

    // ---- Phase C: logits = combined @ Wout + bout  [3072,2048] @ [2048,32000] ----
    wconv_kernel<<<dim3(VV / 32, H2 / 32), dim3(32, 8)>>>(Wout, whi, wlo, H2, VV);
    aconv_kernel<<<(BB * TT * H2) / 256, 256>>>(combined, ahi, alo, BB * TT * H2);
    mma_gemm_kernel<<<dim3((BB * TT) / 128, VV / 128), 256, MM_SMEM>>>(ahi, alo, whi, wlo, bout, out, H2, VV);

    long btv = (long)BB * TT * VV;
    if ((long)out_size >= btv + BB * HH)
        copyh_kernel<<<(BB * HH + 255) / 256, 256>>>(h, out + btv);
}

// round 10
// speedup vs baseline: 2.3839x; 1.0989x over previous
#include <cuda_runtime.h>
#include <cuda_bf16.h>
#include <cstdint>

#define BB 32
#define SS 128
#define TT 96
#define HH 1024
#define VV 32000
#define H3 3072
#define H2 2048
#define H4 4096
#define KSPLIT 8

// ---------------- scratch (static device globals; no allocation) ----------------
__device__ float g_values[BB * SS * HH];
__device__ float g_vw[BB * SS * HH];
__device__ float g_gi[BB * TT * H3];
__device__ float g_fp[KSPLIT * BB * H4];      // fused qw|gh partials (4 MB)
__device__ float g_qwp[KSPLIT * BB * HH];     // h0 partials
__device__ float g_h[BB * HH];
__device__ float g_scores[BB * SS];
__device__ float g_combined[BB * TT * H2];
__device__ float g_wcat[HH * H4];             // [Wq | Whh]  16.8 MB
// bf16 hi/lo staging
__device__ __nv_bfloat16 g_ahi[4096 * 2048];
__device__ __nv_bfloat16 g_alo[4096 * 2048];
__device__ __nv_bfloat16 g_whi[32000u * 2048u];
__device__ __nv_bfloat16 g_wlo[32000u * 2048u];

// ---------------- fast transcendentals ------------------------------------------
__device__ __forceinline__ float ex2f(float x) {
    float y; asm("ex2.approx.f32 %0, %1;" : "=f"(y) : "f"(x)); return y;
}
__device__ __forceinline__ float rcpf(float x) {
    float y; asm("rcp.approx.f32 %0, %1;" : "=f"(y) : "f"(x)); return y;
}
__device__ __forceinline__ float sigmf(float x) {
    return rcpf(1.0f + ex2f(-1.4426950408889634f * x));
}
__device__ __forceinline__ float tanhx(float x) {
    float e = ex2f(2.8853900817779268f * x);
    return 1.0f - 2.0f * rcpf(e + 1.0f);
}

__device__ __forceinline__ uint32_t smem_to_u32(const void* p) {
    uint32_t a;
    asm("{ .reg .u64 t; cvta.to.shared.u64 t, %1; cvt.u32.u64 %0, t; }" : "=r"(a) : "l"(p));
    return a;
}

// ---------------- mma.sync primitives (sm_80 ISA — valid on compute_103) ---------
__device__ __forceinline__ void ldsm_x4(uint32_t* r, uint32_t addr) {
    asm volatile("ldmatrix.sync.aligned.m8n8.x4.shared.b16 {%0,%1,%2,%3}, [%4];"
        : "=r"(r[0]), "=r"(r[1]), "=r"(r[2]), "=r"(r[3]) : "r"(addr));
}
__device__ __forceinline__ void mma16816(float* d, const uint32_t* a, uint32_t b0, uint32_t b1) {
    asm volatile("mma.sync.aligned.m16n8k16.row.col.f32.bf16.bf16.f32 "
        "{%0,%1,%2,%3}, {%4,%5,%6,%7}, {%8,%9}, {%0,%1,%2,%3};"
        : "+f"(d[0]), "+f"(d[1]), "+f"(d[2]), "+f"(d[3])
        : "r"(a[0]), "r"(a[1]), "r"(a[2]), "r"(a[3]), "r"(b0), "r"(b1));
}
__device__ __forceinline__ void cp16(uint32_t dst, const void* src) {
    asm volatile("cp.async.cg.shared.global [%0], [%1], 16;" :: "r"(dst), "l"(src));
}

// ---------------- hi/lo conversion kernels ---------------------------------------
__global__ void wconv_kernel(const float* __restrict__ W, __nv_bfloat16* __restrict__ whi,
                             __nv_bfloat16* __restrict__ wlo, int K, int N) {
    __shared__ float t[32][33];
    int n0 = blockIdx.x * 32, k0 = blockIdx.y * 32;
    int tx = threadIdx.x, ty = threadIdx.y;
#pragma unroll
    for (int j = 0; j < 4; j++)
        t[ty + 8 * j][tx] = W[(long)(k0 + ty + 8 * j) * N + n0 + tx];
    __syncthreads();
#pragma unroll
    for (int j = 0; j < 4; j++) {
        int n = n0 + ty + 8 * j;
        float x = t[tx][ty + 8 * j];
        __nv_bfloat16 h = __float2bfloat16(x);
        float r = x - __bfloat162float(h);
        long o = (long)n * K + k0 + tx;
        whi[o] = h;
        wlo[o] = __float2bfloat16(r);
    }
}

__global__ void aconv_kernel(const float* __restrict__ A, __nv_bfloat16* __restrict__ ahi,
                             __nv_bfloat16* __restrict__ alo, int n) {
    int i = blockIdx.x * 256 + threadIdx.x;
    if (i >= n) return;
    float x = A[i];
    __nv_bfloat16 h = __float2bfloat16(x);
    ahi[i] = h;
    alo[i] = __float2bfloat16(x - __bfloat162float(h));
}

__global__ void aconv_gather_kernel(const float* __restrict__ emb, const int* __restrict__ idx,
                                    __nv_bfloat16* __restrict__ ahi, __nv_bfloat16* __restrict__ alo,
                                    int n) {
    int i = blockIdx.x * 256 + threadIdx.x;
    if (i >= n) return;
    int r = i >> 10, k = i & 1023;
    float x = emb[(long)idx[r] * HH + k];
    __nv_bfloat16 h = __float2bfloat16(x);
    ahi[i] = h;
    alo[i] = __float2bfloat16(x - __bfloat162float(h));
}

// wcat[k][j] = (j<1024) ? Wq[k][j] : Whh[k][j-1024]
__global__ void wcat_kernel(const float* __restrict__ Wq, const float* __restrict__ Whh,
                            float* __restrict__ wcat) {
    int i = blockIdx.x * 256 + threadIdx.x;   // over 1024*4096
    int k = i >> 12, j = i & 4095;
    wcat[i] = (j < HH) ? Wq[k * HH + j] : Whh[k * H3 + (j - HH)];
}

// ---------------- HMMA GEMM: C[M,N] = (Ahi+Alo) @ (Bhi+Blo)^T + bias --------------
#define MM_PITCH 40
#define MM_MAT (128 * MM_PITCH * 2)
#define MM_STAGE (4 * MM_MAT)
#define MM_SMEM (2 * MM_STAGE)

__global__ __launch_bounds__(256, 2)
void mma_gemm_kernel(const __nv_bfloat16* __restrict__ Ahi, const __nv_bfloat16* __restrict__ Alo,
                     const __nv_bfloat16* __restrict__ Bhi, const __nv_bfloat16* __restrict__ Blo,
                     const float* __restrict__ bias, float* __restrict__ C, int K, int N) {
    extern __shared__ __align__(16) char smem[];
    const uint32_t sb = smem_to_u32(smem);
    const int tid = threadIdx.x;
    const int wid = tid >> 5, lane = tid & 31;
    const int m0 = blockIdx.x * 128, n0 = blockIdx.y * 128;
    const int wm = (wid >> 1) * 32;
    const int wn = (wid & 1) * 64;
    const int NC = K >> 5;

    const __nv_bfloat16* gp0 = Ahi + (long)m0 * K;
    const __nv_bfloat16* gp1 = Alo + (long)m0 * K;
    const __nv_bfloat16* gp2 = Bhi + (long)n0 * K;
    const __nv_bfloat16* gp3 = Blo + (long)n0 * K;

    float acc[2][8][4];
#pragma unroll
    for (int a = 0; a < 2; a++)
#pragma unroll
        for (int b = 0; b < 8; b++)
#pragma unroll
            for (int c = 0; c < 4; c++) acc[a][b][c] = 0.0f;

    const int arow = lane & 15;
    const int acol = (lane >> 4) << 3;
    const int brow = ((lane >> 4) << 3) + (lane & 7);
    const int bcol = ((lane >> 3) & 1) << 3;

    auto issue = [&](int c, int buf) {
        const uint32_t base = sb + buf * MM_STAGE;
        const long k0 = (long)c << 5;
        for (int i = tid; i < 2048; i += 256) {
            int mat = i >> 9, r = (i >> 2) & 127, s = i & 3;
            const __nv_bfloat16* g = (mat == 0) ? gp0 : (mat == 1) ? gp1 : (mat == 2) ? gp2 : gp3;
            cp16(base + mat * MM_MAT + r * (MM_PITCH * 2) + s * 16,
                 (const char*)(g + (long)r * K + k0) + s * 16);
        }
        asm volatile("cp.async.commit_group;" ::: "memory");
    };

    issue(0, 0);

    for (int c = 0; c < NC; c++) {
        const int buf = c & 1;
        if (c + 1 < NC) {
            issue(c + 1, buf ^ 1);
            asm volatile("cp.async.wait_group 1;" ::: "memory");
        } else {
            asm volatile("cp.async.wait_group 0;" ::: "memory");
        }
        __syncthreads();

        const uint32_t base = sb + buf * MM_STAGE;
#pragma unroll
        for (int ks = 0; ks < 2; ks++) {
            const int kc = ks * 16;
            uint32_t ah[2][4], al[2][4], bb[4][4];
#pragma unroll
            for (int tm = 0; tm < 2; tm++) {
                uint32_t ad = base + (uint32_t)(((wm + tm * 16 + arow) * MM_PITCH + kc + acol) * 2);
                ldsm_x4(ah[tm], ad);
                ldsm_x4(al[tm], ad + MM_MAT);
            }
#pragma unroll
            for (int gn = 0; gn < 4; gn++) {
                uint32_t bd = base + 2 * MM_MAT +
                    (uint32_t)(((wn + gn * 16 + brow) * MM_PITCH + kc + bcol) * 2);
                ldsm_x4(bb[gn], bd);
            }
#pragma unroll
            for (int tm = 0; tm < 2; tm++)
#pragma unroll
                for (int j = 0; j < 8; j++) {
                    uint32_t b0 = bb[j >> 1][(j & 1) * 2];
                    uint32_t b1 = bb[j >> 1][(j & 1) * 2 + 1];
                    mma16816(acc[tm][j], ah[tm], b0, b1);
                    mma16816(acc[tm][j], al[tm], b0, b1);
                }
#pragma unroll
            for (int gn = 0; gn < 4; gn++) {
                uint32_t bd = base + 3 * MM_MAT +
                    (uint32_t)(((wn + gn * 16 + brow) * MM_PITCH + kc + bcol) * 2);
                ldsm_x4(bb[gn], bd);
            }
#pragma unroll
            for (int tm = 0; tm < 2; tm++)
#pragma unroll
                for (int j = 0; j < 8; j++)
                    mma16816(acc[tm][j], ah[tm],
                             bb[j >> 1][(j & 1) * 2], bb[j >> 1][(j & 1) * 2 + 1]);
        }
        __syncthreads();
    }

#pragma unroll
    for (int tm = 0; tm < 2; tm++) {
        const int r0 = m0 + wm + tm * 16 + (lane >> 2);
#pragma unroll
        for (int j = 0; j < 8; j++) {
            const int col = n0 + wn + j * 8 + (lane & 3) * 2;
            float b0 = bias[col], b1 = bias[col + 1];
            float* p0 = C + (long)r0 * N + col;
            p0[0] = acc[tm][j][0] + b0;
            p0[1] = acc[tm][j][1] + b1;
            float* p1 = p0 + 8 * (long)N;
            p1[0] = acc[tm][j][2] + b0;
            p1[1] = acc[tm][j][3] + b1;
        }
    }
}

// ---------------- small-M (M=32) split-K GEMM -> partials ------------------------
__global__ void gemm_m32_kernel(const float* __restrict__ A, const float* __restrict__ Bm,
                                float* __restrict__ Cp, int N, int K, int ksplit) {
    extern __shared__ float sh[];       // [kslice][33]
    const int kslice = K / ksplit;
    const int tid = threadIdx.x;
    const int k0 = blockIdx.y * kslice;

    for (int i = tid; i < 32 * kslice; i += 256) {
        int b = i / kslice;
        int k = i - b * kslice;
        sh[k * 33 + b] = A[b * K + k0 + k];
    }
    __syncthreads();

    const int w = tid >> 5, lane = tid & 31;
    const int n0 = blockIdx.x * 32 + w * 4;
    const float* Bp = Bm + (long)k0 * N + n0;
    float a0 = 0.f, a1 = 0.f, a2 = 0.f, a3 = 0.f;
#pragma unroll 8
    for (int k = 0; k < kslice; k++) {
        float4 wv = *(const float4*)(Bp + (long)k * N);
        float a = sh[k * 33 + lane];
        a0 += a * wv.x; a1 += a * wv.y; a2 += a * wv.z; a3 += a * wv.w;
    }
    float4* o = (float4*)(Cp + ((long)blockIdx.y * 32 + lane) * N + n0);
    *o = make_float4(a0, a1, a2, a3);
}

__global__ void reduce8_bias_kernel(const float* __restrict__ part, const float* __restrict__ bias,
                                    float* __restrict__ out, int n, int biasN) {
    int i = blockIdx.x * 256 + threadIdx.x;
    if (i >= n) return;
    float s = bias[i % biasN];
#pragma unroll
    for (int p = 0; p < KSPLIT; p++) s += part[(long)p * n + i];
    out[i] = s;
}

// ---------------- fused GRU gates (reads gh section of fused partials) -----------
__global__ void gates_kernel(const float* __restrict__ gi, const float* __restrict__ fp,
                             const float* __restrict__ bhh, float* __restrict__ h,
                             float* __restrict__ combined, int t) {
    int i = blockIdx.x * 256 + threadIdx.x;
    int b = i >> 10;
    int n = i & 1023;
    float hr = bhh[n], hz = bhh[HH + n], hn = bhh[2 * HH + n];
#pragma unroll
    for (int p = 0; p < KSPLIT; p++) {
        const float* g = fp + ((long)(p * 32 + b) << 12);   // pitch 4096
        hr += g[HH + n]; hz += g[2 * HH + n]; hn += g[3 * HH + n];
    }
    const float* gir = gi + ((long)b * TT + t) * H3;
    float r = sigmf(gir[n] + hr);
    float z = sigmf(gir[HH + n] + hz);
    float nn = tanhx(gir[2 * HH + n] + r * hn);
    float hv = (1.0f - z) * nn + z * h[i];
    h[i] = hv;
    combined[((long)b * TT + t) * H2 + n] = hv;
}

// ---------------- scores with inline qw reduction --------------------------------
// grid = BB*8 (b, s-group of 16); 256 thr = 8 warps x 2 s each.
__global__ void scores2_kernel(const float* __restrict__ fp, const float* __restrict__ bq,
                               const float* __restrict__ wc_g, const float* __restrict__ bc,
                               const int* __restrict__ mask, const float* __restrict__ vw,
                               float* __restrict__ scores) {
    __shared__ float q[HH];
    __shared__ float wcs[HH];
    const int b = blockIdx.x >> 3;
    const int g = blockIdx.x & 7;
    const int tid = threadIdx.x;
    for (int i = tid; i < HH; i += 256) {
        float s = bq[i];
#pragma unroll
        for (int p = 0; p < KSPLIT; p++) s += fp[((long)(p * 32 + b) << 12) + i];
        q[i] = s;
        wcs[i] = wc_g[i];
    }
    __syncthreads();
    const int w = tid >> 5, lane = tid & 31;
#pragma unroll
    for (int si = 0; si < 2; si++) {
        const int s = g * 16 + w * 2 + si;
        const float* v = vw + (long)(b * SS + s) * HH;
        float a = 0.0f;
        for (int hh = lane; hh < HH; hh += 32)
            a += wcs[hh] * tanhx(q[hh] + v[hh]);
#pragma unroll
        for (int off = 16; off > 0; off >>= 1) a += __shfl_xor_sync(0xffffffffu, a, off);
        if (lane == 0)
            scores[b * SS + s] = a + bc[0] + (mask[b * SS + s] == 0 ? -1e30f : 0.0f);
    }
}

// ---------------- softmax + context ----------------------------------------------
__global__ void ctx_kernel(const float* __restrict__ scores, const float* __restrict__ values,
                           float* __restrict__ combined, int t) {
    __shared__ float w[SS];
    __shared__ float red[SS];
    const int b = blockIdx.x;
    const int tid = threadIdx.x;
    float sc = scores[b * SS + tid];
    red[tid] = sc;
    __syncthreads();
#pragma unroll
    for (int off = 64; off > 0; off >>= 1) {
        if (tid < off) red[tid] = fmaxf(red[tid], red[tid + off]);
        __syncthreads();
    }
    float mx = red[0];
    __syncthreads();
    float e = ex2f((sc - mx) * 1.4426950408889634f);
    red[tid] = e;
    __syncthreads();
#pragma unroll
    for (int off = 64; off > 0; off >>= 1) {
        if (tid < off) red[tid] += red[tid + off];
        __syncthreads();
    }
    w[tid] = e * rcpf(red[0]);
    __syncthreads();

    const int hidx = blockIdx.y * 128 + tid;
    const float* vb = values + (long)b * SS * HH + hidx;
    float acc = 0.0f;
#pragma unroll
    for (int s = 0; s < SS; s++) acc += w[s] * vb[(long)s * HH];
    combined[((long)b * TT + t) * H2 + HH + hidx] = acc;
}

__global__ void copyh_kernel(const float* __restrict__ h, float* __restrict__ out) {
    int i = blockIdx.x * 256 + threadIdx.x;
    if (i < BB * HH) out[i] = h[i];
}

// ---------------- launch ----------------------------------------------------------
extern "C" void kernel_launch(void* const* d_in, const int* in_sizes, int n_in,
                              void* d_out, int out_size) {
    const float* enc_out = (const float*)d_in[0];
    const float* enc_hid = (const float*)d_in[1];
    const int*   mask    = (const int*)d_in[2];
    const int*   tgt     = (const int*)d_in[3];
    const float* emb     = (const float*)d_in[4];
    const float* Wq   = (const float*)d_in[5];
    const float* bq   = (const float*)d_in[6];
    const float* Wv   = (const float*)d_in[7];
    const float* bv   = (const float*)d_in[8];
    const float* wc   = (const float*)d_in[9];
    const float* bc   = (const float*)d_in[10];
    const float* Wih  = (const float*)d_in[11];
    const float* bih  = (const float*)d_in[12];
    const float* Whh  = (const float*)d_in[13];
    const float* bhh  = (const float*)d_in[14];
    const float* Wproj = (const float*)d_in[15];
    const float* bproj = (const float*)d_in[16];
    const float* Wout  = (const float*)d_in[17];
    const float* bout  = (const float*)d_in[18];
    float* out = (float*)d_out;

    float *values, *vw, *gi, *fp, *qwp, *h, *scores, *combined, *wcat;
    __nv_bfloat16 *ahi, *alo, *whi, *wlo;
    cudaGetSymbolAddress((void**)&values, g_values);
    cudaGetSymbolAddress((void**)&vw, g_vw);
    cudaGetSymbolAddress((void**)&gi, g_gi);
    cudaGetSymbolAddress((void**)&fp, g_fp);
    cudaGetSymbolAddress((void**)&qwp, g_qwp);
    cudaGetSymbolAddress((void**)&h, g_h);
    cudaGetSymbolAddress((void**)&scores, g_scores);
    cudaGetSymbolAddress((void**)&combined, g_combined);
    cudaGetSymbolAddress((void**)&wcat, g_wcat);
    cudaGetSymbolAddress((void**)&ahi, g_ahi);
    cudaGetSymbolAddress((void**)&alo, g_alo);
    cudaGetSymbolAddress((void**)&whi, g_whi);
    cudaGetSymbolAddress((void**)&wlo, g_wlo);

    cudaFuncSetAttribute(mma_gemm_kernel, cudaFuncAttributeMaxDynamicSharedMemorySize, MM_SMEM);

    // ---- one-time weight prep ----
    wcat_kernel<<<(HH * H4) / 256, 256>>>(Wq, Whh, wcat);

    // ---- Phase A (HMMA tensor path) ----
    wconv_kernel<<<dim3(HH / 32, H2 / 32), dim3(32, 8)>>>(Wproj, whi, wlo, H2, HH);
    aconv_kernel<<<(4096 * 2048) / 256, 256>>>(enc_out, ahi, alo, 4096 * 2048);
    mma_gemm_kernel<<<dim3(4096 / 128, HH / 128), 256, MM_SMEM>>>(ahi, alo, whi, wlo, bproj, values, H2, HH);
    wconv_kernel<<<dim3(HH / 32, HH / 32), dim3(32, 8)>>>(Wv, whi, wlo, HH, HH);
    aconv_kernel<<<(4096 * 1024) / 256, 256>>>(values, ahi, alo, 4096 * 1024);
    mma_gemm_kernel<<<dim3(4096 / 128, HH / 128), 256, MM_SMEM>>>(ahi, alo, whi, wlo, bv, vw, HH, HH);
    wconv_kernel<<<dim3(H3 / 32, HH / 32), dim3(32, 8)>>>(Wih, whi, wlo, HH, H3);
    aconv_gather_kernel<<<(BB * TT * HH) / 256, 256>>>(emb, tgt, ahi, alo, BB * TT * HH);
    mma_gemm_kernel<<<dim3((BB * TT) / 128, H3 / 128), 256, MM_SMEM>>>(ahi, alo, whi, wlo, bih, gi, HH, H3);
    // h0 = enc_hid @ Wproj + bproj (M=32 split-K)
    gemm_m32_kernel<<<dim3(HH / 32, KSPLIT), 256, (H2 / KSPLIT) * 33 * 4>>>(enc_hid, Wproj, qwp, HH, H2, KSPLIT);
    reduce8_bias_kernel<<<(BB * HH + 255) / 256, 256>>>(qwp, bproj, h, BB * HH, HH);

    // prime fused partials with h0 @ [Wq|Whh] (gh section used by step 0)
    gemm_m32_kernel<<<dim3(H4 / 32, KSPLIT), 256, (HH / KSPLIT) * 33 * 4>>>(h, wcat, fp, H4, HH, KSPLIT);

    // ---- Phase B: recurrence (4 kernels/step) ----
    for (int t = 0; t < TT; t++) {
        gates_kernel<<<(BB * HH) / 256, 256>>>(gi, fp, bhh, h, combined, t);
        gemm_m32_kernel<<<dim3(H4 / 32, KSPLIT), 256, (HH / KSPLIT) * 33 * 4>>>(h, wcat, fp, H4, HH, KSPLIT);
        scores2_kernel<<<BB * 8, 256>>>(fp, bq, wc, bc, mask, vw, scores);
        ctx_kernel<<<dim3(BB, HH / 128), 128>>>(scores, values, combined, t);
    }

    // ---- Phase C: logits = combined @ Wout + bout ----
    wconv_kernel<<<dim3(VV / 32, H2 / 32), dim3(32, 8)>>>(Wout, whi, wlo, H2, VV);
    aconv_kernel<<<(BB * TT * H2) / 256, 256>>>(combined, ahi, alo, BB * TT * H2);
    mma_gemm_kernel<<<dim3((BB * TT) / 128, VV / 128), 256, MM_SMEM>>>(ahi, alo, whi, wlo, bout, out, H2, VV);

    long btv = (long)BB * TT * VV;
    if ((long)out_size >= btv + BB * HH)
        copyh_kernel<<<(BB * HH + 255) / 256, 256>>>(h, out + btv);
}

// round 12
// speedup vs baseline: 3.0114x; 1.2632x over previous
#include <cuda_runtime.h>
#include <cuda_bf16.h>
#include <cstdint>

#define BB 32
#define SS 128
#define TT 96
#define HH 1024
#define VV 32000
#define H3 3072
#define H2 2048
#define H4 4096
#define KSPLIT 8

// ---------------- scratch (static device globals; no allocation) ----------------
__device__ float g_values[BB * SS * HH];
__device__ float g_vw[BB * SS * HH];
__device__ float g_gi[BB * TT * H3];
__device__ float g_qwp[KSPLIT * BB * HH];     // h0 partials (fp32 path, once)
__device__ float g_h[BB * HH];
__device__ float g_qgh[BB * H4];              // fused qw|gh (single, no split)
__device__ float g_scores[BB * SS];
// bf16 staging
__device__ __nv_bfloat16 g_hhi[BB * HH];
__device__ __nv_bfloat16 g_hlo[BB * HH];
__device__ __nv_bfloat16 g_ahi[4096 * 2048];
__device__ __nv_bfloat16 g_alo[4096 * 2048];
__device__ __nv_bfloat16 g_a2hi[4096 * 1024];
__device__ __nv_bfloat16 g_a2lo[4096 * 1024];
__device__ __nv_bfloat16 g_whi[32000u * 2048u];
__device__ __nv_bfloat16 g_wlo[32000u * 2048u];
__device__ __nv_bfloat16 g_wcathi[H4 * HH];   // [Wq|Whh]^T hi, [4096,1024] K-major
__device__ __nv_bfloat16 g_wcatlo[H4 * HH];

// ---------------- fast transcendentals ------------------------------------------
__device__ __forceinline__ float ex2f(float x) {
    float y; asm("ex2.approx.f32 %0, %1;" : "=f"(y) : "f"(x)); return y;
}
__device__ __forceinline__ float rcpf(float x) {
    float y; asm("rcp.approx.f32 %0, %1;" : "=f"(y) : "f"(x)); return y;
}
__device__ __forceinline__ float sigmf(float x) {
    return rcpf(1.0f + ex2f(-1.4426950408889634f * x));
}
__device__ __forceinline__ float tanhx(float x) {
    float e = ex2f(2.8853900817779268f * x);
    return 1.0f - 2.0f * rcpf(e + 1.0f);
}

__device__ __forceinline__ uint32_t smem_to_u32(const void* p) {
    uint32_t a;
    asm("{ .reg .u64 t; cvta.to.shared.u64 t, %1; cvt.u32.u64 %0, t; }" : "=r"(a) : "l"(p));
    return a;
}

// ---------------- mma.sync primitives (sm_80 ISA — valid on compute_103) ---------
__device__ __forceinline__ void ldsm_x4(uint32_t* r, uint32_t addr) {
    asm volatile("ldmatrix.sync.aligned.m8n8.x4.shared.b16 {%0,%1,%2,%3}, [%4];"
        : "=r"(r[0]), "=r"(r[1]), "=r"(r[2]), "=r"(r[3]) : "r"(addr));
}
__device__ __forceinline__ void mma16816(float* d, const uint32_t* a, uint32_t b0, uint32_t b1) {
    asm volatile("mma.sync.aligned.m16n8k16.row.col.f32.bf16.bf16.f32 "
        "{%0,%1,%2,%3}, {%4,%5,%6,%7}, {%8,%9}, {%0,%1,%2,%3};"
        : "+f"(d[0]), "+f"(d[1]), "+f"(d[2]), "+f"(d[3])
        : "r"(a[0]), "r"(a[1]), "r"(a[2]), "r"(a[3]), "r"(b0), "r"(b1));
}
__device__ __forceinline__ void cp16(uint32_t dst, const void* src) {
    asm volatile("cp.async.cg.shared.global [%0], [%1], 16;" :: "r"(dst), "l"(src));
}

// ---------------- hi/lo conversion kernels ---------------------------------------
// W [K,N] fp32 -> whi/wlo [N,K] bf16 (transpose + split). grid (N/32, K/32), block (32,8)
__global__ void wconv_kernel(const float* __restrict__ W, __nv_bfloat16* __restrict__ whi,
                             __nv_bfloat16* __restrict__ wlo, int K, int N) {
    __shared__ float t[32][33];
    int n0 = blockIdx.x * 32, k0 = blockIdx.y * 32;
    int tx = threadIdx.x, ty = threadIdx.y;
#pragma unroll
    for (int j = 0; j < 4; j++)
        t[ty + 8 * j][tx] = W[(long)(k0 + ty + 8 * j) * N + n0 + tx];
    __syncthreads();
#pragma unroll
    for (int j = 0; j < 4; j++) {
        int n = n0 + ty + 8 * j;
        float x = t[tx][ty + 8 * j];
        __nv_bfloat16 h = __float2bfloat16(x);
        float r = x - __bfloat162float(h);
        long o = (long)n * K + k0 + tx;
        whi[o] = h;
        wlo[o] = __float2bfloat16(r);
    }
}

__global__ void aconv_kernel(const float* __restrict__ A, __nv_bfloat16* __restrict__ ahi,
                             __nv_bfloat16* __restrict__ alo, int n) {
    int i = blockIdx.x * 256 + threadIdx.x;
    if (i >= n) return;
    float x = A[i];
    __nv_bfloat16 h = __float2bfloat16(x);
    ahi[i] = h;
    alo[i] = __float2bfloat16(x - __bfloat162float(h));
}

__global__ void aconv_gather_kernel(const float* __restrict__ emb, const int* __restrict__ idx,
                                    __nv_bfloat16* __restrict__ ahi, __nv_bfloat16* __restrict__ alo,
                                    int n) {
    int i = blockIdx.x * 256 + threadIdx.x;
    if (i >= n) return;
    int r = i >> 10, k = i & 1023;
    float x = emb[(long)idx[r] * HH + k];
    __nv_bfloat16 h = __float2bfloat16(x);
    ahi[i] = h;
    alo[i] = __float2bfloat16(x - __bfloat162float(h));
}

// ---------------- HMMA GEMM: C[M,N] = (Ahi+Alo) @ (Bhi+Blo)^T + bias --------------
// Optional Chi/Clo epilogue output (bf16 hi/lo of C, pitch N) for GEMM chaining.
#define MM_PITCH 40
#define MM_MAT (128 * MM_PITCH * 2)
#define MM_STAGE (4 * MM_MAT)
#define MM_SMEM (2 * MM_STAGE)

__global__ __launch_bounds__(256, 2)
void mma_gemm_kernel(const __nv_bfloat16* __restrict__ Ahi, const __nv_bfloat16* __restrict__ Alo,
                     const __nv_bfloat16* __restrict__ Bhi, const __nv_bfloat16* __restrict__ Blo,
                     const float* __restrict__ bias, float* __restrict__ C, int K, int N,
                     __nv_bfloat16* __restrict__ Chi, __nv_bfloat16* __restrict__ Clo) {
    extern __shared__ __align__(16) char smem[];
    const uint32_t sb = smem_to_u32(smem);
    const int tid = threadIdx.x;
    const int wid = tid >> 5, lane = tid & 31;
    const int m0 = blockIdx.x * 128, n0 = blockIdx.y * 128;
    const int wm = (wid >> 1) * 32;
    const int wn = (wid & 1) * 64;
    const int NC = K >> 5;

    const __nv_bfloat16* gp0 = Ahi + (long)m0 * K;
    const __nv_bfloat16* gp1 = Alo + (long)m0 * K;
    const __nv_bfloat16* gp2 = Bhi + (long)n0 * K;
    const __nv_bfloat16* gp3 = Blo + (long)n0 * K;

    // hoisted per-thread cp.async assignments (8 fixed (ptr, smem-off) pairs)
    const __nv_bfloat16* gptr[8];
    uint32_t soff[8];
#pragma unroll
    for (int j = 0; j < 8; j++) {
        int i = tid + j * 256;
        int mat = i >> 9, r = (i >> 2) & 127, s = i & 3;
        const __nv_bfloat16* g = (mat == 0) ? gp0 : (mat == 1) ? gp1 : (mat == 2) ? gp2 : gp3;
        gptr[j] = g + (long)r * K + s * 8;
        soff[j] = (uint32_t)(mat * MM_MAT + r * (MM_PITCH * 2) + s * 16);
    }

    float acc[2][8][4];
#pragma unroll
    for (int a = 0; a < 2; a++)
#pragma unroll
        for (int b = 0; b < 8; b++)
#pragma unroll
            for (int c = 0; c < 4; c++) acc[a][b][c] = 0.0f;

    const int arow = lane & 15;
    const int acol = (lane >> 4) << 3;
    const int brow = ((lane >> 4) << 3) + (lane & 7);
    const int bcol = ((lane >> 3) & 1) << 3;

    auto issue = [&](int c, int buf) {
        const uint32_t b0 = sb + buf * MM_STAGE;
#pragma unroll
        for (int j = 0; j < 8; j++) cp16(b0 + soff[j], gptr[j] + c * 32);
        asm volatile("cp.async.commit_group;" ::: "memory");
    };

    issue(0, 0);

    for (int c = 0; c < NC; c++) {
        const int buf = c & 1;
        if (c + 1 < NC) {
            issue(c + 1, buf ^ 1);
            asm volatile("cp.async.wait_group 1;" ::: "memory");
        } else {
            asm volatile("cp.async.wait_group 0;" ::: "memory");
        }
        __syncthreads();

        const uint32_t base = sb + buf * MM_STAGE;
#pragma unroll
        for (int ks = 0; ks < 2; ks++) {
            const int kc = ks * 16;
            uint32_t ah[2][4], al[2][4], bb[4][4];
#pragma unroll
            for (int tm = 0; tm < 2; tm++) {
                uint32_t ad = base + (uint32_t)(((wm + tm * 16 + arow) * MM_PITCH + kc + acol) * 2);
                ldsm_x4(ah[tm], ad);
                ldsm_x4(al[tm], ad + MM_MAT);
            }
#pragma unroll
            for (int gn = 0; gn < 4; gn++) {
                uint32_t bd = base + 2 * MM_MAT +
                    (uint32_t)(((wn + gn * 16 + brow) * MM_PITCH + kc + bcol) * 2);
                ldsm_x4(bb[gn], bd);
            }
#pragma unroll
            for (int tm = 0; tm < 2; tm++)
#pragma unroll
                for (int j = 0; j < 8; j++) {
                    uint32_t b0 = bb[j >> 1][(j & 1) * 2];
                    uint32_t b1 = bb[j >> 1][(j & 1) * 2 + 1];
                    mma16816(acc[tm][j], ah[tm], b0, b1);
                    mma16816(acc[tm][j], al[tm], b0, b1);
                }
#pragma unroll
            for (int gn = 0; gn < 4; gn++) {
                uint32_t bd = base + 3 * MM_MAT +
                    (uint32_t)(((wn + gn * 16 + brow) * MM_PITCH + kc + bcol) * 2);
                ldsm_x4(bb[gn], bd);
            }
#pragma unroll
            for (int tm = 0; tm < 2; tm++)
#pragma unroll
                for (int j = 0; j < 8; j++)
                    mma16816(acc[tm][j], ah[tm],
                             bb[j >> 1][(j & 1) * 2], bb[j >> 1][(j & 1) * 2 + 1]);
        }
        __syncthreads();
    }

#pragma unroll
    for (int tm = 0; tm < 2; tm++) {
        const int r0 = m0 + wm + tm * 16 + (lane >> 2);
#pragma unroll
        for (int j = 0; j < 8; j++) {
            const int col = n0 + wn + j * 8 + (lane & 3) * 2;
            float b0 = bias[col], b1 = bias[col + 1];
            float v0 = acc[tm][j][0] + b0, v1 = acc[tm][j][1] + b1;
            float v2 = acc[tm][j][2] + b0, v3 = acc[tm][j][3] + b1;
            long o0 = (long)r0 * N + col;
            long o1 = o0 + 8 * (long)N;
            C[o0] = v0; C[o0 + 1] = v1;
            C[o1] = v2; C[o1 + 1] = v3;
            if (Chi) {
                __nv_bfloat16 t0 = __float2bfloat16(v0), t1 = __float2bfloat16(v1);
                __nv_bfloat16 t2 = __float2bfloat16(v2), t3 = __float2bfloat16(v3);
                Chi[o0] = t0; Chi[o0 + 1] = t1; Chi[o1] = t2; Chi[o1 + 1] = t3;
                Clo[o0] = __float2bfloat16(v0 - __bfloat162float(t0));
                Clo[o0 + 1] = __float2bfloat16(v1 - __bfloat162float(t1));
                Clo[o1] = __float2bfloat16(v2 - __bfloat162float(t2));
                Clo[o1 + 1] = __float2bfloat16(v3 - __bfloat162float(t3));
            }
        }
    }
}

// ---------------- recurrence HMMA GEMM: qgh[32,4096] = h @ [Wq|Whh] ---------------
// A = hhi/hlo [32,1024], B = wcat hi/lo [4096,1024] K-major. grid 64 (N=64/block),
// 256 thr = 8 warps (2m16 x 4n16), BK=64, double-buffered cp.async. No bias.
#define RN_PITCH 72
#define RN_AMAT (32 * RN_PITCH * 2)                 // 4608
#define RN_BMAT (64 * RN_PITCH * 2)                 // 9216
#define RN_STAGE (2 * RN_AMAT + 2 * RN_BMAT)        // 27648
#define RN_SMEM (2 * RN_STAGE)                      // 55296

__global__ __launch_bounds__(256, 2)
void rnn_gemm_kernel(const __nv_bfloat16* __restrict__ hhi, const __nv_bfloat16* __restrict__ hlo,
                     const __nv_bfloat16* __restrict__ bhi, const __nv_bfloat16* __restrict__ blo,
                     float* __restrict__ qgh) {
    extern __shared__ __align__(16) char smem[];
    const uint32_t sb = smem_to_u32(smem);
    const int tid = threadIdx.x;
    const int wid = tid >> 5, lane = tid & 31;
    const int n0 = blockIdx.x * 64;
    const int wm2 = wid >> 2;          // 0..1 (m16 tile)
    const int wn2 = wid & 3;           // 0..3 (n16 tile)

    // hoisted cp.async assignments: 1536 cp16 / 256 thr = 6 per thread
    const __nv_bfloat16* gptr[6];
    uint32_t soff[6];
#pragma unroll
    for (int j = 0; j < 6; j++) {
        int i = tid + j * 256;
        if (i < 512) {                             // A hi/lo: 32 rows x 8 segs
            int ii = i & 255;
            int r = ii >> 3, s = ii & 7;
            const __nv_bfloat16* g = (i < 256) ? hhi : hlo;
            gptr[j] = g + r * HH + s * 8;
            soff[j] = (uint32_t)((i < 256 ? 0 : RN_AMAT) + r * (RN_PITCH * 2) + s * 16);
        } else {                                   // B hi/lo: 64 rows x 8 segs
            int ii = (i - 512) & 511;
            int r = ii >> 3, s = ii & 7;
            const __nv_bfloat16* g = (i < 1024) ? bhi : blo;
            gptr[j] = g + (long)(n0 + r) * HH + s * 8;
            soff[j] = (uint32_t)(2 * RN_AMAT + (i < 1024 ? 0 : RN_BMAT) + r * (RN_PITCH * 2) + s * 16);
        }
    }

    float acc[2][4];
#pragma unroll
    for (int j = 0; j < 2; j++)
#pragma unroll
        for (int c = 0; c < 4; c++) acc[j][c] = 0.0f;

    const int arow = lane & 15;
    const int acol = (lane >> 4) << 3;
    const int brow = ((lane >> 4) << 3) + (lane & 7);
    const int bcol = ((lane >> 3) & 1) << 3;

    auto issue = [&](int c, int buf) {
        const uint32_t b0 = sb + buf * RN_STAGE;
#pragma unroll
        for (int j = 0; j < 6; j++) cp16(b0 + soff[j], gptr[j] + c * 64);
        asm volatile("cp.async.commit_group;" ::: "memory");
    };

    issue(0, 0);
    const int NC = HH / 64;   // 16 chunks
    for (int c = 0; c < NC; c++) {
        const int buf = c & 1;
        if (c + 1 < NC) {
            issue(c + 1, buf ^ 1);
            asm volatile("cp.async.wait_group 1;" ::: "memory");
        } else {
            asm volatile("cp.async.wait_group 0;" ::: "memory");
        }
        __syncthreads();

        const uint32_t base = sb + buf * RN_STAGE;
#pragma unroll
        for (int ks = 0; ks < 4; ks++) {
            const int kc = ks * 16;
            uint32_t ah[4], al[4], bh[4], bl[4];
            uint32_t ad = base + (uint32_t)(((wm2 * 16 + arow) * RN_PITCH + kc + acol) * 2);
            ldsm_x4(ah, ad);
            ldsm_x4(al, ad + RN_AMAT);
            uint32_t bd = base + 2 * RN_AMAT +
                (uint32_t)(((wn2 * 16 + brow) * RN_PITCH + kc + bcol) * 2);
            ldsm_x4(bh, bd);
            ldsm_x4(bl, bd + RN_BMAT);
#pragma unroll
            for (int j = 0; j < 2; j++) {
                mma16816(acc[j], ah, bh[j * 2], bh[j * 2 + 1]);
                mma16816(acc[j], al, bh[j * 2], bh[j * 2 + 1]);
                mma16816(acc[j], ah, bl[j * 2], bl[j * 2 + 1]);
            }
        }
        __syncthreads();
    }

    const int row = wm2 * 16 + (lane >> 2);
#pragma unroll
    for (int j = 0; j < 2; j++) {
        const int col = n0 + wn2 * 16 + j * 8 + (lane & 3) * 2;
        qgh[row * H4 + col] = acc[j][0];
        qgh[row * H4 + col + 1] = acc[j][1];
        qgh[(row + 8) * H4 + col] = acc[j][2];
        qgh[(row + 8) * H4 + col + 1] = acc[j][3];
    }
}

// ---------------- small-M fp32 split-K GEMM (h0 only, once) ----------------------
__global__ void gemm_m32_kernel(const float* __restrict__ A, const float* __restrict__ Bm,
                                float* __restrict__ Cp, int N, int K, int ksplit) {
    extern __shared__ float sh[];
    const int kslice = K / ksplit;
    const int tid = threadIdx.x;
    const int k0 = blockIdx.y * kslice;

    for (int i = tid; i < 32 * kslice; i += 256) {
        int b = i / kslice;
        int k = i - b * kslice;
        sh[k * 33 + b] = A[b * K + k0 + k];
    }
    __syncthreads();

    const int w = tid >> 5, lane = tid & 31;
    const int n0 = blockIdx.x * 32 + w * 4;
    const float* Bp = Bm + (long)k0 * N + n0;
    float a0 = 0.f, a1 = 0.f, a2 = 0.f, a3 = 0.f;
#pragma unroll 8
    for (int k = 0; k < kslice; k++) {
        float4 wv = *(const float4*)(Bp + (long)k * N);
        float a = sh[k * 33 + lane];
        a0 += a * wv.x; a1 += a * wv.y; a2 += a * wv.z; a3 += a * wv.w;
    }
    float4* o = (float4*)(Cp + ((long)blockIdx.y * 32 + lane) * N + n0);
    *o = make_float4(a0, a1, a2, a3);
}

__global__ void reduce8_bias_kernel(const float* __restrict__ part, const float* __restrict__ bias,
                                    float* __restrict__ out, int n, int biasN) {
    int i = blockIdx.x * 256 + threadIdx.x;
    if (i >= n) return;
    float s = bias[i % biasN];
#pragma unroll
    for (int p = 0; p < KSPLIT; p++) s += part[(long)p * n + i];
    out[i] = s;
}

__global__ void hconv_kernel(const float* __restrict__ h, __nv_bfloat16* __restrict__ hhi,
                             __nv_bfloat16* __restrict__ hlo) {
    int i = blockIdx.x * 256 + threadIdx.x;
    if (i >= BB * HH) return;
    float x = h[i];
    __nv_bfloat16 t = __float2bfloat16(x);
    hhi[i] = t;
    hlo[i] = __float2bfloat16(x - __bfloat162float(t));
}

// ---------------- fused GRU gates (single gh buffer; writes h + hi/lo + combined) -
__global__ void gates_kernel(const float* __restrict__ gi, const float* __restrict__ qgh,
                             const float* __restrict__ bhh, float* __restrict__ h,
                             __nv_bfloat16* __restrict__ hhi, __nv_bfloat16* __restrict__ hlo,
                             __nv_bfloat16* __restrict__ ahi, __nv_bfloat16* __restrict__ alo,
                             int t) {
    int i = blockIdx.x * 256 + threadIdx.x;
    int b = i >> 10;
    int n = i & 1023;
    const float* g = qgh + (long)b * H4;
    float hr = bhh[n] + g[HH + n];
    float hz = bhh[HH + n] + g[2 * HH + n];
    float hn = bhh[2 * HH + n] + g[3 * HH + n];
    const float* gir = gi + ((long)b * TT + t) * H3;
    float r = sigmf(gir[n] + hr);
    float z = sigmf(gir[HH + n] + hz);
    float nn = tanhx(gir[2 * HH + n] + r * hn);
    float hv = (1.0f - z) * nn + z * h[i];
    h[i] = hv;
    __nv_bfloat16 th = __float2bfloat16(hv);
    __nv_bfloat16 tl = __float2bfloat16(hv - __bfloat162float(th));
    hhi[i] = th;
    hlo[i] = tl;
    long co = ((long)b * TT + t) * H2 + n;
    ahi[co] = th;
    alo[co] = tl;
}

// ---------------- scores with inline q pickup ------------------------------------
__global__ void scores2_kernel(const float* __restrict__ qgh, const float* __restrict__ bq,
                               const float* __restrict__ wc_g, const float* __restrict__ bc,
                               const int* __restrict__ mask, const float* __restrict__ vw,
                               float* __restrict__ scores) {
    __shared__ float q[HH];
    __shared__ float wcs[HH];
    const int b = blockIdx.x >> 3;
    const int g = blockIdx.x & 7;
    const int tid = threadIdx.x;
    for (int i = tid; i < HH; i += 256) {
        q[i] = qgh[(long)b * H4 + i] + bq[i];
        wcs[i] = wc_g[i];
    }
    __syncthreads();
    const int w = tid >> 5, lane = tid & 31;
#pragma unroll
    for (int si = 0; si < 2; si++) {
        const int s = g * 16 + w * 2 + si;
        const float* v = vw + (long)(b * SS + s) * HH;
        float a = 0.0f;
        for (int hh = lane; hh < HH; hh += 32)
            a += wcs[hh] * tanhx(q[hh] + v[hh]);
#pragma unroll
        for (int off = 16; off > 0; off >>= 1) a += __shfl_xor_sync(0xffffffffu, a, off);
        if (lane == 0)
            scores[b * SS + s] = a + bc[0] + (mask[b * SS + s] == 0 ? -1e30f : 0.0f);
    }
}

// ---------------- softmax + context (writes combined ctx half as hi/lo) ----------
__global__ void ctx_kernel(const float* __restrict__ scores, const float* __restrict__ values,
                           __nv_bfloat16* __restrict__ ahi, __nv_bfloat16* __restrict__ alo,
                           int t) {
    __shared__ float w[SS];
    __shared__ float red[SS];
    const int b = blockIdx.x;
    const int tid = threadIdx.x;
    float sc = scores[b * SS + tid];
    red[tid] = sc;
    __syncthreads();
#pragma unroll
    for (int off = 64; off > 0; off >>= 1) {
        if (tid < off) red[tid] = fmaxf(red[tid], red[tid + off]);
        __syncthreads();
    }
    float mx = red[0];
    __syncthreads();
    float e = ex2f((sc - mx) * 1.4426950408889634f);
    red[tid] = e;
    __syncthreads();
#pragma unroll
    for (int off = 64; off > 0; off >>= 1) {
        if (tid < off) red[tid] += red[tid + off];
        __syncthreads();
    }
    w[tid] = e * rcpf(red[0]);
    __syncthreads();

    const int hidx = blockIdx.y * 128 + tid;
    const float* vb = values + (long)b * SS * HH + hidx;
    float acc = 0.0f;
#pragma unroll
    for (int s = 0; s < SS; s++) acc += w[s] * vb[(long)s * HH];
    long co = ((long)b * TT + t) * H2 + HH + hidx;
    __nv_bfloat16 th = __float2bfloat16(acc);
    ahi[co] = th;
    alo[co] = __float2bfloat16(acc - __bfloat162float(th));
}

__global__ void copyh_kernel(const float* __restrict__ h, float* __restrict__ out) {
    int i = blockIdx.x * 256 + threadIdx.x;
    if (i < BB * HH) out[i] = h[i];
}

// ---------------- launch ----------------------------------------------------------
extern "C" void kernel_launch(void* const* d_in, const int* in_sizes, int n_in,
                              void* d_out, int out_size) {
    const float* enc_out = (const float*)d_in[0];
    const float* enc_hid = (const float*)d_in[1];
    const int*   mask    = (const int*)d_in[2];
    const int*   tgt     = (const int*)d_in[3];
    const float* emb     = (const float*)d_in[4];
    const float* Wq   = (const float*)d_in[5];
    const float* bq   = (const float*)d_in[6];
    const float* Wv   = (const float*)d_in[7];
    const float* bv   = (const float*)d_in[8];
    const float* wc   = (const float*)d_in[9];
    const float* bc   = (const float*)d_in[10];
    const float* Wih  = (const float*)d_in[11];
    const float* bih  = (const float*)d_in[12];
    const float* Whh  = (const float*)d_in[13];
    const float* bhh  = (const float*)d_in[14];
    const float* Wproj = (const float*)d_in[15];
    const float* bproj = (const float*)d_in[16];
    const float* Wout  = (const float*)d_in[17];
    const float* bout  = (const float*)d_in[18];
    float* out = (float*)d_out;

    float *values, *vw, *gi, *qwp, *h, *qgh, *scores;
    __nv_bfloat16 *hhi, *hlo, *ahi, *alo, *a2hi, *a2lo, *whi, *wlo, *wcathi, *wcatlo;
    cudaGetSymbolAddress((void**)&values, g_values);
    cudaGetSymbolAddress((void**)&vw, g_vw);
    cudaGetSymbolAddress((void**)&gi, g_gi);
    cudaGetSymbolAddress((void**)&qwp, g_qwp);
    cudaGetSymbolAddress((void**)&h, g_h);
    cudaGetSymbolAddress((void**)&qgh, g_qgh);
    cudaGetSymbolAddress((void**)&scores, g_scores);
    cudaGetSymbolAddress((void**)&hhi, g_hhi);
    cudaGetSymbolAddress((void**)&hlo, g_hlo);
    cudaGetSymbolAddress((void**)&ahi, g_ahi);
    cudaGetSymbolAddress((void**)&alo, g_alo);
    cudaGetSymbolAddress((void**)&a2hi, g_a2hi);
    cudaGetSymbolAddress((void**)&a2lo, g_a2lo);
    cudaGetSymbolAddress((void**)&whi, g_whi);
    cudaGetSymbolAddress((void**)&wlo, g_wlo);
    cudaGetSymbolAddress((void**)&wcathi, g_wcathi);
    cudaGetSymbolAddress((void**)&wcatlo, g_wcatlo);

    cudaFuncSetAttribute(mma_gemm_kernel, cudaFuncAttributeMaxDynamicSharedMemorySize, MM_SMEM);
    cudaFuncSetAttribute(rnn_gemm_kernel, cudaFuncAttributeMaxDynamicSharedMemorySize, RN_SMEM);

    // ---- one-time weight prep: [Wq|Whh]^T hi/lo (rows 0-1023 = Wq, 1024-4095 = Whh)
    wconv_kernel<<<dim3(HH / 32, HH / 32), dim3(32, 8)>>>(Wq, wcathi, wcatlo, HH, HH);
    wconv_kernel<<<dim3(H3 / 32, HH / 32), dim3(32, 8)>>>(Whh, wcathi + HH * HH, wcatlo + HH * HH, HH, H3);

    // ---- Phase A (HMMA tensor path) ----
    wconv_kernel<<<dim3(HH / 32, H2 / 32), dim3(32, 8)>>>(Wproj, whi, wlo, H2, HH);
    aconv_kernel<<<(4096 * 2048) / 256, 256>>>(enc_out, ahi, alo, 4096 * 2048);
    mma_gemm_kernel<<<dim3(4096 / 128, HH / 128), 256, MM_SMEM>>>(
        ahi, alo, whi, wlo, bproj, values, H2, HH, a2hi, a2lo);
    wconv_kernel<<<dim3(HH / 32, HH / 32), dim3(32, 8)>>>(Wv, whi, wlo, HH, HH);
    mma_gemm_kernel<<<dim3(4096 / 128, HH / 128), 256, MM_SMEM>>>(
        a2hi, a2lo, whi, wlo, bv, vw, HH, HH, nullptr, nullptr);
    wconv_kernel<<<dim3(H3 / 32, HH / 32), dim3(32, 8)>>>(Wih, whi, wlo, HH, H3);
    aconv_gather_kernel<<<(BB * TT * HH) / 256, 256>>>(emb, tgt, ahi, alo, BB * TT * HH);
    mma_gemm_kernel<<<dim3((BB * TT) / 128, H3 / 128), 256, MM_SMEM>>>(
        ahi, alo, whi, wlo, bih, gi, HH, H3, nullptr, nullptr);
    // h0 = enc_hid @ Wproj + bproj (fp32 split-K, once)
    gemm_m32_kernel<<<dim3(HH / 32, KSPLIT), 256, (H2 / KSPLIT) * 33 * 4>>>(enc_hid, Wproj, qwp, HH, H2, KSPLIT);
    reduce8_bias_kernel<<<(BB * HH + 255) / 256, 256>>>(qwp, bproj, h, BB * HH, HH);
    hconv_kernel<<<(BB * HH + 255) / 256, 256>>>(h, hhi, hlo);
    rnn_gemm_kernel<<<H4 / 64, 256, RN_SMEM>>>(hhi, hlo, wcathi, wcatlo, qgh);

    // ---- Phase B: recurrence (4 kernels/step) ----
    for (int t = 0; t < TT; t++) {
        gates_kernel<<<(BB * HH) / 256, 256>>>(gi, qgh, bhh, h, hhi, hlo, ahi, alo, t);
        rnn_gemm_kernel<<<H4 / 64, 256, RN_SMEM>>>(hhi, hlo, wcathi, wcatlo, qgh);
        scores2_kernel<<<BB * 8, 256>>>(qgh, bq, wc, bc, mask, vw, scores);
        ctx_kernel<<<dim3(BB, HH / 128), 128>>>(scores, values, ahi, alo, t);
    }

    // ---- Phase C: logits = combined @ Wout + bout (combined already hi/lo) ----
    wconv_kernel<<<dim3(VV / 32, H2 / 32), dim3(32, 8)>>>(Wout, whi, wlo, H2, VV);
    mma_gemm_kernel<<<dim3((BB * TT) / 128, VV / 128), 256, MM_SMEM>>>(
        ahi, alo, whi, wlo, bout, out, H2, VV, nullptr, nullptr);

    long btv = (long)BB * TT * VV;
    if ((long)out_size >= btv + BB * HH)
        copyh_kernel<<<(BB * HH + 255) / 256, 256>>>(h, out + btv);
}

// round 13
// speedup vs baseline: 4.1743x; 1.3862x over previous
#include <cuda_runtime.h>
#include <cuda_bf16.h>
#include <cuda_fp16.h>
#include <cstdint>

#define BB 32
#define SS 128
#define TT 96
#define HH 1024
#define VV 32000
#define H3 3072
#define H2 2048
#define KSPLIT 8

// ---------------- scratch (static device globals; no allocation) ----------------
__device__ float g_values[BB * SS * HH];
__device__ float g_vw[BB * SS * HH];
__device__ float g_gi[BB * TT * H3];
__device__ float g_qwp[KSPLIT * BB * HH];
__device__ float g_h[BB * HH];
__device__ float g_gh[BB * H3];
__device__ float g_qw_all[BB * TT * HH];      // 12.6 MB
__device__ float g_wsm[BB * TT * SS];         // softmax weights 1.6 MB
__device__ __nv_bfloat16 g_hhi[BB * HH];
__device__ __nv_bfloat16 g_hlo[BB * HH];
__device__ __nv_bfloat16 g_ahi[4096 * 2048];
__device__ __nv_bfloat16 g_alo[4096 * 2048];
__device__ __nv_bfloat16 g_a2hi[4096 * 1024];
__device__ __nv_bfloat16 g_a2lo[4096 * 1024];
__device__ __nv_bfloat16 g_whi[3072 * 2048];
__device__ __nv_bfloat16 g_wlo[3072 * 2048];
__device__ __nv_bfloat16 g_whhThi[H3 * HH];
__device__ __nv_bfloat16 g_whhTlo[H3 * HH];
__device__ __half g_c16hi[BB * TT * H2];      // combined fp16 hi/lo
__device__ __half g_c16lo[BB * TT * H2];
__device__ __half g_w16[32000u * 2048u];      // fp16 weights (Wq then Wout)

// ---------------- fast transcendentals ------------------------------------------
__device__ __forceinline__ float ex2f(float x) {
    float y; asm("ex2.approx.f32 %0, %1;" : "=f"(y) : "f"(x)); return y;
}
__device__ __forceinline__ float rcpf(float x) {
    float y; asm("rcp.approx.f32 %0, %1;" : "=f"(y) : "f"(x)); return y;
}
__device__ __forceinline__ float sigmf(float x) {
    return rcpf(1.0f + ex2f(-1.4426950408889634f * x));
}
__device__ __forceinline__ float tanhx(float x) {
    float e = ex2f(2.8853900817779268f * x);
    return 1.0f - 2.0f * rcpf(e + 1.0f);
}

__device__ __forceinline__ uint32_t smem_to_u32(const void* p) {
    uint32_t a;
    asm("{ .reg .u64 t; cvta.to.shared.u64 t, %1; cvt.u32.u64 %0, t; }" : "=r"(a) : "l"(p));
    return a;
}

// ---------------- mma.sync primitives --------------------------------------------
__device__ __forceinline__ void ldsm_x4(uint32_t* r, uint32_t addr) {
    asm volatile("ldmatrix.sync.aligned.m8n8.x4.shared.b16 {%0,%1,%2,%3}, [%4];"
        : "=r"(r[0]), "=r"(r[1]), "=r"(r[2]), "=r"(r[3]) : "r"(addr));
}
__device__ __forceinline__ void mma16816(float* d, const uint32_t* a, uint32_t b0, uint32_t b1) {
    asm volatile("mma.sync.aligned.m16n8k16.row.col.f32.bf16.bf16.f32 "
        "{%0,%1,%2,%3}, {%4,%5,%6,%7}, {%8,%9}, {%0,%1,%2,%3};"
        : "+f"(d[0]), "+f"(d[1]), "+f"(d[2]), "+f"(d[3])
        : "r"(a[0]), "r"(a[1]), "r"(a[2]), "r"(a[3]), "r"(b0), "r"(b1));
}
__device__ __forceinline__ void mma16816h(float* d, const uint32_t* a, uint32_t b0, uint32_t b1) {
    asm volatile("mma.sync.aligned.m16n8k16.row.col.f32.f16.f16.f32 "
        "{%0,%1,%2,%3}, {%4,%5,%6,%7}, {%8,%9}, {%0,%1,%2,%3};"
        : "+f"(d[0]), "+f"(d[1]), "+f"(d[2]), "+f"(d[3])
        : "r"(a[0]), "r"(a[1]), "r"(a[2]), "r"(a[3]), "r"(b0), "r"(b1));
}
__device__ __forceinline__ void cp16(uint32_t dst, const void* src) {
    asm volatile("cp.async.cg.shared.global [%0], [%1], 16;" :: "r"(dst), "l"(src));
}

// ---------------- conversion kernels ---------------------------------------------
// W [K,N] fp32 -> whi/wlo [N,K] bf16 (transpose + split). grid (N/32, K/32), block (32,8)
__global__ void wconv_kernel(const float* __restrict__ W, __nv_bfloat16* __restrict__ whi,
                             __nv_bfloat16* __restrict__ wlo, int K, int N) {
    __shared__ float t[32][33];
    int n0 = blockIdx.x * 32, k0 = blockIdx.y * 32;
    int tx = threadIdx.x, ty = threadIdx.y;
#pragma unroll
    for (int j = 0; j < 4; j++)
        t[ty + 8 * j][tx] = W[(long)(k0 + ty + 8 * j) * N + n0 + tx];
    __syncthreads();
#pragma unroll
    for (int j = 0; j < 4; j++) {
        int n = n0 + ty + 8 * j;
        float x = t[tx][ty + 8 * j];
        __nv_bfloat16 h = __float2bfloat16(x);
        float r = x - __bfloat162float(h);
        long o = (long)n * K + k0 + tx;
        whi[o] = h;
        wlo[o] = __float2bfloat16(r);
    }
}

// W [K,N] fp32 -> w16 [N,K] fp16 (transpose, single precision level)
__global__ void wconv16_kernel(const float* __restrict__ W, __half* __restrict__ w16,
                               int K, int N) {
    __shared__ float t[32][33];
    int n0 = blockIdx.x * 32, k0 = blockIdx.y * 32;
    int tx = threadIdx.x, ty = threadIdx.y;
#pragma unroll
    for (int j = 0; j < 4; j++)
        t[ty + 8 * j][tx] = W[(long)(k0 + ty + 8 * j) * N + n0 + tx];
    __syncthreads();
#pragma unroll
    for (int j = 0; j < 4; j++) {
        int n = n0 + ty + 8 * j;
        w16[(long)n * K + k0 + tx] = __float2half_rn(t[tx][ty + 8 * j]);
    }
}

__global__ void aconv_kernel(const float* __restrict__ A, __nv_bfloat16* __restrict__ ahi,
                             __nv_bfloat16* __restrict__ alo, int n) {
    int i = blockIdx.x * 256 + threadIdx.x;
    if (i >= n) return;
    float x = A[i];
    __nv_bfloat16 h = __float2bfloat16(x);
    ahi[i] = h;
    alo[i] = __float2bfloat16(x - __bfloat162float(h));
}

__global__ void aconv_gather_kernel(const float* __restrict__ emb, const int* __restrict__ idx,
                                    __nv_bfloat16* __restrict__ ahi, __nv_bfloat16* __restrict__ alo,
                                    int n) {
    int i = blockIdx.x * 256 + threadIdx.x;
    if (i >= n) return;
    int r = i >> 10, k = i & 1023;
    float x = emb[(long)idx[r] * HH + k];
    __nv_bfloat16 h = __float2bfloat16(x);
    ahi[i] = h;
    alo[i] = __float2bfloat16(x - __bfloat162float(h));
}

// ---------------- bf16 3-product HMMA GEMM (Phase A) ------------------------------
#define MM_PITCH 40
#define MM_MAT (128 * MM_PITCH * 2)
#define MM_STAGE (4 * MM_MAT)
#define MM_SMEM (2 * MM_STAGE)

__global__ __launch_bounds__(256, 2)
void mma_gemm_kernel(const __nv_bfloat16* __restrict__ Ahi, const __nv_bfloat16* __restrict__ Alo,
                     const __nv_bfloat16* __restrict__ Bhi, const __nv_bfloat16* __restrict__ Blo,
                     const float* __restrict__ bias, float* __restrict__ C, int K, int N,
                     __nv_bfloat16* __restrict__ Chi, __nv_bfloat16* __restrict__ Clo) {
    extern __shared__ __align__(16) char smem[];
    const uint32_t sb = smem_to_u32(smem);
    const int tid = threadIdx.x;
    const int wid = tid >> 5, lane = tid & 31;
    const int m0 = blockIdx.x * 128, n0 = blockIdx.y * 128;
    const int wm = (wid >> 1) * 32;
    const int wn = (wid & 1) * 64;
    const int NC = K >> 5;

    const __nv_bfloat16* gp0 = Ahi + (long)m0 * K;
    const __nv_bfloat16* gp1 = Alo + (long)m0 * K;
    const __nv_bfloat16* gp2 = Bhi + (long)n0 * K;
    const __nv_bfloat16* gp3 = Blo + (long)n0 * K;

    const __nv_bfloat16* gptr[8];
    uint32_t soff[8];
#pragma unroll
    for (int j = 0; j < 8; j++) {
        int i = tid + j * 256;
        int mat = i >> 9, r = (i >> 2) & 127, s = i & 3;
        const __nv_bfloat16* g = (mat == 0) ? gp0 : (mat == 1) ? gp1 : (mat == 2) ? gp2 : gp3;
        gptr[j] = g + (long)r * K + s * 8;
        soff[j] = (uint32_t)(mat * MM_MAT + r * (MM_PITCH * 2) + s * 16);
    }

    float acc[2][8][4];
#pragma unroll
    for (int a = 0; a < 2; a++)
#pragma unroll
        for (int b = 0; b < 8; b++)
#pragma unroll
            for (int c = 0; c < 4; c++) acc[a][b][c] = 0.0f;

    const int arow = lane & 15;
    const int acol = (lane >> 4) << 3;
    const int brow = ((lane >> 4) << 3) + (lane & 7);
    const int bcol = ((lane >> 3) & 1) << 3;

    auto issue = [&](int c, int buf) {
        const uint32_t b0 = sb + buf * MM_STAGE;
#pragma unroll
        for (int j = 0; j < 8; j++) cp16(b0 + soff[j], gptr[j] + c * 32);
        asm volatile("cp.async.commit_group;" ::: "memory");
    };

    issue(0, 0);

    for (int c = 0; c < NC; c++) {
        const int buf = c & 1;
        if (c + 1 < NC) {
            issue(c + 1, buf ^ 1);
            asm volatile("cp.async.wait_group 1;" ::: "memory");
        } else {
            asm volatile("cp.async.wait_group 0;" ::: "memory");
        }
        __syncthreads();

        const uint32_t base = sb + buf * MM_STAGE;
#pragma unroll
        for (int ks = 0; ks < 2; ks++) {
            const int kc = ks * 16;
            uint32_t ah[2][4], al[2][4], bb[4][4];
#pragma unroll
            for (int tm = 0; tm < 2; tm++) {
                uint32_t ad = base + (uint32_t)(((wm + tm * 16 + arow) * MM_PITCH + kc + acol) * 2);
                ldsm_x4(ah[tm], ad);
                ldsm_x4(al[tm], ad + MM_MAT);
            }
#pragma unroll
            for (int gn = 0; gn < 4; gn++) {
                uint32_t bd = base + 2 * MM_MAT +
                    (uint32_t)(((wn + gn * 16 + brow) * MM_PITCH + kc + bcol) * 2);
                ldsm_x4(bb[gn], bd);
            }
#pragma unroll
            for (int tm = 0; tm < 2; tm++)
#pragma unroll
                for (int j = 0; j < 8; j++) {
                    uint32_t b0 = bb[j >> 1][(j & 1) * 2];
                    uint32_t b1 = bb[j >> 1][(j & 1) * 2 + 1];
                    mma16816(acc[tm][j], ah[tm], b0, b1);
                    mma16816(acc[tm][j], al[tm], b0, b1);
                }
#pragma unroll
            for (int gn = 0; gn < 4; gn++) {
                uint32_t bd = base + 3 * MM_MAT +
                    (uint32_t)(((wn + gn * 16 + brow) * MM_PITCH + kc + bcol) * 2);
                ldsm_x4(bb[gn], bd);
            }
#pragma unroll
            for (int tm = 0; tm < 2; tm++)
#pragma unroll
                for (int j = 0; j < 8; j++)
                    mma16816(acc[tm][j], ah[tm],
                             bb[j >> 1][(j & 1) * 2], bb[j >> 1][(j & 1) * 2 + 1]);
        }
        __syncthreads();
    }

#pragma unroll
    for (int tm = 0; tm < 2; tm++) {
        const int r0 = m0 + wm + tm * 16 + (lane >> 2);
#pragma unroll
        for (int j = 0; j < 8; j++) {
            const int col = n0 + wn + j * 8 + (lane & 3) * 2;
            float b0 = bias[col], b1 = bias[col + 1];
            float v0 = acc[tm][j][0] + b0, v1 = acc[tm][j][1] + b1;
            float v2 = acc[tm][j][2] + b0, v3 = acc[tm][j][3] + b1;
            long o0 = (long)r0 * N + col;
            long o1 = o0 + 8 * (long)N;
            C[o0] = v0; C[o0 + 1] = v1;
            C[o1] = v2; C[o1 + 1] = v3;
            if (Chi) {
                __nv_bfloat16 t0 = __float2bfloat16(v0), t1 = __float2bfloat16(v1);
                __nv_bfloat16 t2 = __float2bfloat16(v2), t3 = __float2bfloat16(v3);
                Chi[o0] = t0; Chi[o0 + 1] = t1; Chi[o1] = t2; Chi[o1 + 1] = t3;
                Clo[o0] = __float2bfloat16(v0 - __bfloat162float(t0));
                Clo[o0 + 1] = __float2bfloat16(v1 - __bfloat162float(t1));
                Clo[o1] = __float2bfloat16(v2 - __bfloat162float(t2));
                Clo[o1 + 1] = __float2bfloat16(v3 - __bfloat162float(t3));
            }
        }
    }
}

// ---------------- fp16 2-product HMMA GEMM (qw + Phase C) -------------------------
// C[M,N] = (Ahi+Alo) @ B^T + bias; Ahi/Alo fp16 [M, lda] (first K cols used),
// B fp16 [N,K] K-major.
#define F6_MAT (128 * MM_PITCH * 2)
#define F6_STAGE (3 * F6_MAT)
#define F6_SMEM (2 * F6_STAGE)

__global__ __launch_bounds__(256, 2)
void mma_f16_kernel(const __half* __restrict__ Ahi, const __half* __restrict__ Alo,
                    const __half* __restrict__ Bf, const float* __restrict__ bias,
                    float* __restrict__ C, int K, int N, int lda) {
    extern __shared__ __align__(16) char smem[];
    const uint32_t sb = smem_to_u32(smem);
    const int tid = threadIdx.x;
    const int wid = tid >> 5, lane = tid & 31;
    const int m0 = blockIdx.x * 128, n0 = blockIdx.y * 128;
    const int wm = (wid >> 1) * 32;
    const int wn = (wid & 1) * 64;
    const int NC = K >> 5;

    const __half* gp0 = Ahi + (long)m0 * lda;
    const __half* gp1 = Alo + (long)m0 * lda;
    const __half* gp2 = Bf + (long)n0 * K;

    const __half* gptr[6];
    uint32_t soff[6];
#pragma unroll
    for (int j = 0; j < 6; j++) {
        int i = tid + j * 256;
        int mat = i >> 9, r = (i >> 2) & 127, s = i & 3;
        const __half* g = (mat == 0) ? (gp0 + (long)r * lda) :
                          (mat == 1) ? (gp1 + (long)r * lda) : (gp2 + (long)r * K);
        gptr[j] = g + s * 8;
        soff[j] = (uint32_t)(mat * F6_MAT + r * (MM_PITCH * 2) + s * 16);
    }

    float acc[2][8][4];
#pragma unroll
    for (int a = 0; a < 2; a++)
#pragma unroll
        for (int b = 0; b < 8; b++)
#pragma unroll
            for (int c = 0; c < 4; c++) acc[a][b][c] = 0.0f;

    const int arow = lane & 15;
    const int acol = (lane >> 4) << 3;
    const int brow = ((lane >> 4) << 3) + (lane & 7);
    const int bcol = ((lane >> 3) & 1) << 3;

    auto issue = [&](int c, int buf) {
        const uint32_t b0 = sb + buf * F6_STAGE;
#pragma unroll
        for (int j = 0; j < 6; j++) cp16(b0 + soff[j], gptr[j] + c * 32);
        asm volatile("cp.async.commit_group;" ::: "memory");
    };

    issue(0, 0);

    for (int c = 0; c < NC; c++) {
        const int buf = c & 1;
        if (c + 1 < NC) {
            issue(c + 1, buf ^ 1);
            asm volatile("cp.async.wait_group 1;" ::: "memory");
        } else {
            asm volatile("cp.async.wait_group 0;" ::: "memory");
        }
        __syncthreads();

        const uint32_t base = sb + buf * F6_STAGE;
#pragma unroll
        for (int ks = 0; ks < 2; ks++) {
            const int kc = ks * 16;
            uint32_t ah[2][4], al[2][4], bb[4][4];
#pragma unroll
            for (int tm = 0; tm < 2; tm++) {
                uint32_t ad = base + (uint32_t)(((wm + tm * 16 + arow) * MM_PITCH + kc + acol) * 2);
                ldsm_x4(ah[tm], ad);
                ldsm_x4(al[tm], ad + F6_MAT);
            }
#pragma unroll
            for (int gn = 0; gn < 4; gn++) {
                uint32_t bd = base + 2 * F6_MAT +
                    (uint32_t)(((wn + gn * 16 + brow) * MM_PITCH + kc + bcol) * 2);
                ldsm_x4(bb[gn], bd);
            }
#pragma unroll
            for (int tm = 0; tm < 2; tm++)
#pragma unroll
                for (int j = 0; j < 8; j++) {
                    uint32_t b0 = bb[j >> 1][(j & 1) * 2];
                    uint32_t b1 = bb[j >> 1][(j & 1) * 2 + 1];
                    mma16816h(acc[tm][j], ah[tm], b0, b1);
                    mma16816h(acc[tm][j], al[tm], b0, b1);
                }
        }
        __syncthreads();
    }

#pragma unroll
    for (int tm = 0; tm < 2; tm++) {
        const int r0 = m0 + wm + tm * 16 + (lane >> 2);
#pragma unroll
        for (int j = 0; j < 8; j++) {
            const int col = n0 + wn + j * 8 + (lane & 3) * 2;
            float b0 = bias[col], b1 = bias[col + 1];
            long o0 = (long)r0 * N + col;
            long o1 = o0 + 8 * (long)N;
            C[o0] = acc[tm][j][0] + b0;
            C[o0 + 1] = acc[tm][j][1] + b1;
            C[o1] = acc[tm][j][2] + b0;
            C[o1 + 1] = acc[tm][j][3] + b1;
        }
    }
}

// ---------------- recurrence HMMA GEMM: gh[32,3072] = h @ Whh^T -------------------
#define RN_PITCH 72
#define RN_AMAT (32 * RN_PITCH * 2)
#define RN_BMAT (64 * RN_PITCH * 2)
#define RN_STAGE (2 * RN_AMAT + 2 * RN_BMAT)
#define RN_SMEM (2 * RN_STAGE)

__global__ __launch_bounds__(256, 2)
void rnn_gemm_kernel(const __nv_bfloat16* __restrict__ hhi, const __nv_bfloat16* __restrict__ hlo,
                     const __nv_bfloat16* __restrict__ bhi, const __nv_bfloat16* __restrict__ blo,
                     float* __restrict__ gh) {
    extern __shared__ __align__(16) char smem[];
    const uint32_t sb = smem_to_u32(smem);
    const int tid = threadIdx.x;
    const int wid = tid >> 5, lane = tid & 31;
    const int n0 = blockIdx.x * 64;
    const int wm2 = wid >> 2;
    const int wn2 = wid & 3;

    const __nv_bfloat16* gptr[6];
    uint32_t soff[6];
#pragma unroll
    for (int j = 0; j < 6; j++) {
        int i = tid + j * 256;
        if (i < 512) {
            int ii = i & 255;
            int r = ii >> 3, s = ii & 7;
            const __nv_bfloat16* g = (i < 256) ? hhi : hlo;
            gptr[j] = g + r * HH + s * 8;
            soff[j] = (uint32_t)((i < 256 ? 0 : RN_AMAT) + r * (RN_PITCH * 2) + s * 16);
        } else {
            int ii = (i - 512) & 511;
            int r = ii >> 3, s = ii & 7;
            const __nv_bfloat16* g = (i < 1024) ? bhi : blo;
            gptr[j] = g + (long)(n0 + r) * HH + s * 8;
            soff[j] = (uint32_t)(2 * RN_AMAT + (i < 1024 ? 0 : RN_BMAT) + r * (RN_PITCH * 2) + s * 16);
        }
    }

    float acc[2][4];
#pragma unroll
    for (int j = 0; j < 2; j++)
#pragma unroll
        for (int c = 0; c < 4; c++) acc[j][c] = 0.0f;

    const int arow = lane & 15;
    const int acol = (lane >> 4) << 3;
    const int brow = ((lane >> 4) << 3) + (lane & 7);
    const int bcol = ((lane >> 3) & 1) << 3;

    auto issue = [&](int c, int buf) {
        const uint32_t b0 = sb + buf * RN_STAGE;
#pragma unroll
        for (int j = 0; j < 6; j++) cp16(b0 + soff[j], gptr[j] + c * 64);
        asm volatile("cp.async.commit_group;" ::: "memory");
    };

    issue(0, 0);
    const int NC = HH / 64;
    for (int c = 0; c < NC; c++) {
        const int buf = c & 1;
        if (c + 1 < NC) {
            issue(c + 1, buf ^ 1);
            asm volatile("cp.async.wait_group 1;" ::: "memory");
        } else {
            asm volatile("cp.async.wait_group 0;" ::: "memory");
        }
        __syncthreads();

        const uint32_t base = sb + buf * RN_STAGE;
#pragma unroll
        for (int ks = 0; ks < 4; ks++) {
            const int kc = ks * 16;
            uint32_t ah[4], al[4], bh[4], bl[4];
            uint32_t ad = base + (uint32_t)(((wm2 * 16 + arow) * RN_PITCH + kc + acol) * 2);
            ldsm_x4(ah, ad);
            ldsm_x4(al, ad + RN_AMAT);
            uint32_t bd = base + 2 * RN_AMAT +
                (uint32_t)(((wn2 * 16 + brow) * RN_PITCH + kc + bcol) * 2);
            ldsm_x4(bh, bd);
            ldsm_x4(bl, bd + RN_BMAT);
#pragma unroll
            for (int j = 0; j < 2; j++) {
                mma16816(acc[j], ah, bh[j * 2], bh[j * 2 + 1]);
                mma16816(acc[j], al, bh[j * 2], bh[j * 2 + 1]);
                mma16816(acc[j], ah, bl[j * 2], bl[j * 2 + 1]);
            }
        }
        __syncthreads();
    }

    const int row = wm2 * 16 + (lane >> 2);
#pragma unroll
    for (int j = 0; j < 2; j++) {
        const int col = n0 + wn2 * 16 + j * 8 + (lane & 3) * 2;
        gh[row * H3 + col] = acc[j][0];
        gh[row * H3 + col + 1] = acc[j][1];
        gh[(row + 8) * H3 + col] = acc[j][2];
        gh[(row + 8) * H3 + col + 1] = acc[j][3];
    }
}

// ---------------- small-M fp32 split-K GEMM (h0 only) ----------------------------
__global__ void gemm_m32_kernel(const float* __restrict__ A, const float* __restrict__ Bm,
                                float* __restrict__ Cp, int N, int K, int ksplit) {
    extern __shared__ float sh[];
    const int kslice = K / ksplit;
    const int tid = threadIdx.x;
    const int k0 = blockIdx.y * kslice;

    for (int i = tid; i < 32 * kslice; i += 256) {
        int b = i / kslice;
        int k = i - b * kslice;
        sh[k * 33 + b] = A[b * K + k0 + k];
    }
    __syncthreads();

    const int w = tid >> 5, lane = tid & 31;
    const int n0 = blockIdx.x * 32 + w * 4;
    const float* Bp = Bm + (long)k0 * N + n0;
    float a0 = 0.f, a1 = 0.f, a2 = 0.f, a3 = 0.f;
#pragma unroll 8
    for (int k = 0; k < kslice; k++) {
        float4 wv = *(const float4*)(Bp + (long)k * N);
        float a = sh[k * 33 + lane];
        a0 += a * wv.x; a1 += a * wv.y; a2 += a * wv.z; a3 += a * wv.w;
    }
    float4* o = (float4*)(Cp + ((long)blockIdx.y * 32 + lane) * N + n0);
    *o = make_float4(a0, a1, a2, a3);
}

__global__ void reduce8_bias_kernel(const float* __restrict__ part, const float* __restrict__ bias,
                                    float* __restrict__ out, int n, int biasN) {
    int i = blockIdx.x * 256 + threadIdx.x;
    if (i >= n) return;
    float s = bias[i % biasN];
#pragma unroll
    for (int p = 0; p < KSPLIT; p++) s += part[(long)p * n + i];
    out[i] = s;
}

__global__ void hconv_kernel(const float* __restrict__ h, __nv_bfloat16* __restrict__ hhi,
                             __nv_bfloat16* __restrict__ hlo) {
    int i = blockIdx.x * 256 + threadIdx.x;
    if (i >= BB * HH) return;
    float x = h[i];
    __nv_bfloat16 t = __float2bfloat16(x);
    hhi[i] = t;
    hlo[i] = __float2bfloat16(x - __bfloat162float(t));
}

// ---------------- fused GRU gates ------------------------------------------------
__global__ void gates_kernel(const float* __restrict__ gi, const float* __restrict__ gh,
                             const float* __restrict__ bhh, float* __restrict__ h,
                             __nv_bfloat16* __restrict__ hhi, __nv_bfloat16* __restrict__ hlo,
                             __half* __restrict__ c16hi, __half* __restrict__ c16lo, int t) {
    int i = blockIdx.x * 256 + threadIdx.x;
    int b = i >> 10;
    int n = i & 1023;
    const float* g = gh + (long)b * H3;
    float hr = bhh[n] + g[n];
    float hz = bhh[HH + n] + g[HH + n];
    float hn = bhh[2 * HH + n] + g[2 * HH + n];
    const float* gir = gi + ((long)b * TT + t) * H3;
    float r = sigmf(gir[n] + hr);
    float z = sigmf(gir[HH + n] + hz);
    float nn = tanhx(gir[2 * HH + n] + r * hn);
    float hv = (1.0f - z) * nn + z * h[i];
    h[i] = hv;
    __nv_bfloat16 th = __float2bfloat16(hv);
    hhi[i] = th;
    hlo[i] = __float2bfloat16(hv - __bfloat162float(th));
    long co = ((long)b * TT + t) * H2 + n;
    __half f = __float2half_rn(hv);
    c16hi[co] = f;
    c16lo[co] = __float2half_rn(hv - __half2float(f));
}

// ---------------- batched scores + softmax (one block per (b,t)) -----------------
__global__ __launch_bounds__(256)
void scores_batch_kernel(const float* __restrict__ qw_all, const float* __restrict__ wc_g,
                         const float* __restrict__ bc, const int* __restrict__ mask,
                         const float* __restrict__ vw, float* __restrict__ wsm) {
    __shared__ float q[HH];
    __shared__ float wcs[HH];
    __shared__ float sc[SS];
    __shared__ float red[SS];
    const int blk = blockIdx.x;          // = b*TT + t
    const int b = blk / TT;
    const int tid = threadIdx.x;
    for (int i = tid; i < HH; i += 256) {
        q[i] = qw_all[(long)blk * HH + i];
        wcs[i] = wc_g[i];
    }
    __syncthreads();
    const int w = tid >> 5, lane = tid & 31;
#pragma unroll
    for (int si = 0; si < 16; si++) {
        const int s = w * 16 + si;
        const float* v = vw + (long)(b * SS + s) * HH;
        float a = 0.0f;
        for (int hh = lane; hh < HH; hh += 32)
            a += wcs[hh] * tanhx(q[hh] + v[hh]);
#pragma unroll
        for (int off = 16; off > 0; off >>= 1) a += __shfl_xor_sync(0xffffffffu, a, off);
        if (lane == 0)
            sc[s] = a + bc[0] + (mask[b * SS + s] == 0 ? -1e30f : 0.0f);
    }
    __syncthreads();
    // softmax over sc[0..127]
    if (tid < 128) red[tid] = sc[tid];
    __syncthreads();
#pragma unroll
    for (int off = 64; off > 0; off >>= 1) {
        if (tid < off) red[tid] = fmaxf(red[tid], red[tid + off]);
        __syncthreads();
    }
    float mx = red[0];
    __syncthreads();
    float e = 0.0f;
    if (tid < 128) { e = ex2f((sc[tid] - mx) * 1.4426950408889634f); red[tid] = e; }
    __syncthreads();
#pragma unroll
    for (int off = 64; off > 0; off >>= 1) {
        if (tid < off) red[tid] += red[tid + off];
        __syncthreads();
    }
    if (tid < 128) wsm[(long)blk * SS + tid] = e * rcpf(red[0]);
}

// ---------------- batched context (values staged in smem) ------------------------
#define CTX_SMEM ((SS * 128 + SS) * 4)
__global__ __launch_bounds__(128)
void ctx_batch_kernel(const float* __restrict__ wsm, const float* __restrict__ values,
                      __half* __restrict__ c16hi, __half* __restrict__ c16lo) {
    extern __shared__ float csm[];
    float* val = csm;               // [SS][128]
    float* wv = csm + SS * 128;     // [SS]
    const int b = blockIdx.x;
    const int h0 = blockIdx.y * 128;
    const int tid = threadIdx.x;
    for (int s = 0; s < SS; s++)
        val[s * 128 + tid] = values[(long)(b * SS + s) * HH + h0 + tid];
    __syncthreads();
    for (int t = 0; t < TT; t++) {
        wv[tid] = wsm[((long)b * TT + t) * SS + tid];
        __syncthreads();
        float acc = 0.0f;
#pragma unroll 16
        for (int s = 0; s < SS; s++) acc += wv[s] * val[s * 128 + tid];
        long co = ((long)b * TT + t) * H2 + HH + h0 + tid;
        __half f = __float2half_rn(acc);
        c16hi[co] = f;
        c16lo[co] = __float2half_rn(acc - __half2float(f));
        __syncthreads();
    }
}

__global__ void copyh_kernel(const float* __restrict__ h, float* __restrict__ out) {
    int i = blockIdx.x * 256 + threadIdx.x;
    if (i < BB * HH) out[i] = h[i];
}

// ---------------- launch ----------------------------------------------------------
extern "C" void kernel_launch(void* const* d_in, const int* in_sizes, int n_in,
                              void* d_out, int out_size) {
    const float* enc_out = (const float*)d_in[0];
    const float* enc_hid = (const float*)d_in[1];
    const int*   mask    = (const int*)d_in[2];
    const int*   tgt     = (const int*)d_in[3];
    const float* emb     = (const float*)d_in[4];
    const float* Wq   = (const float*)d_in[5];
    const float* bq   = (const float*)d_in[6];
    const float* Wv   = (const float*)d_in[7];
    const float* bv   = (const float*)d_in[8];
    const float* wc   = (const float*)d_in[9];
    const float* bc   = (const float*)d_in[10];
    const float* Wih  = (const float*)d_in[11];
    const float* bih  = (const float*)d_in[12];
    const float* Whh  = (const float*)d_in[13];
    const float* bhh  = (const float*)d_in[14];
    const float* Wproj = (const float*)d_in[15];
    const float* bproj = (const float*)d_in[16];
    const float* Wout  = (const float*)d_in[17];
    const float* bout  = (const float*)d_in[18];
    float* out = (float*)d_out;

    float *values, *vw, *gi, *qwp, *h, *gh, *qw_all, *wsm;
    __nv_bfloat16 *hhi, *hlo, *ahi, *alo, *a2hi, *a2lo, *whi, *wlo, *whhThi, *whhTlo;
    __half *c16hi, *c16lo, *w16;
    cudaGetSymbolAddress((void**)&values, g_values);
    cudaGetSymbolAddress((void**)&vw, g_vw);
    cudaGetSymbolAddress((void**)&gi, g_gi);
    cudaGetSymbolAddress((void**)&qwp, g_qwp);
    cudaGetSymbolAddress((void**)&h, g_h);
    cudaGetSymbolAddress((void**)&gh, g_gh);
    cudaGetSymbolAddress((void**)&qw_all, g_qw_all);
    cudaGetSymbolAddress((void**)&wsm, g_wsm);
    cudaGetSymbolAddress((void**)&hhi, g_hhi);
    cudaGetSymbolAddress((void**)&hlo, g_hlo);
    cudaGetSymbolAddress((void**)&ahi, g_ahi);
    cudaGetSymbolAddress((void**)&alo, g_alo);
    cudaGetSymbolAddress((void**)&a2hi, g_a2hi);
    cudaGetSymbolAddress((void**)&a2lo, g_a2lo);
    cudaGetSymbolAddress((void**)&whi, g_whi);
    cudaGetSymbolAddress((void**)&wlo, g_wlo);
    cudaGetSymbolAddress((void**)&whhThi, g_whhThi);
    cudaGetSymbolAddress((void**)&whhTlo, g_whhTlo);
    cudaGetSymbolAddress((void**)&c16hi, g_c16hi);
    cudaGetSymbolAddress((void**)&c16lo, g_c16lo);
    cudaGetSymbolAddress((void**)&w16, g_w16);

    cudaFuncSetAttribute(mma_gemm_kernel, cudaFuncAttributeMaxDynamicSharedMemorySize, MM_SMEM);
    cudaFuncSetAttribute(mma_f16_kernel, cudaFuncAttributeMaxDynamicSharedMemorySize, F6_SMEM);
    cudaFuncSetAttribute(rnn_gemm_kernel, cudaFuncAttributeMaxDynamicSharedMemorySize, RN_SMEM);
    cudaFuncSetAttribute(ctx_batch_kernel, cudaFuncAttributeMaxDynamicSharedMemorySize, CTX_SMEM);

    // ---- weight prep ----
    wconv_kernel<<<dim3(H3 / 32, HH / 32), dim3(32, 8)>>>(Whh, whhThi, whhTlo, HH, H3);
    wconv16_kernel<<<dim3(HH / 32, HH / 32), dim3(32, 8)>>>(Wq, w16, HH, HH);

    // ---- Phase A (bf16 3-product HMMA) ----
    wconv_kernel<<<dim3(HH / 32, H2 / 32), dim3(32, 8)>>>(Wproj, whi, wlo, H2, HH);
    aconv_kernel<<<(4096 * 2048) / 256, 256>>>(enc_out, ahi, alo, 4096 * 2048);
    mma_gemm_kernel<<<dim3(4096 / 128, HH / 128), 256, MM_SMEM>>>(
        ahi, alo, whi, wlo, bproj, values, H2, HH, a2hi, a2lo);
    wconv_kernel<<<dim3(HH / 32, HH / 32), dim3(32, 8)>>>(Wv, whi, wlo, HH, HH);
    mma_gemm_kernel<<<dim3(4096 / 128, HH / 128), 256, MM_SMEM>>>(
        a2hi, a2lo, whi, wlo, bv, vw, HH, HH, nullptr, nullptr);
    wconv_kernel<<<dim3(H3 / 32, HH / 32), dim3(32, 8)>>>(Wih, whi, wlo, HH, H3);
    aconv_gather_kernel<<<(BB * TT * HH) / 256, 256>>>(emb, tgt, ahi, alo, BB * TT * HH);
    mma_gemm_kernel<<<dim3((BB * TT) / 128, H3 / 128), 256, MM_SMEM>>>(
        ahi, alo, whi, wlo, bih, gi, HH, H3, nullptr, nullptr);
    // h0
    gemm_m32_kernel<<<dim3(HH / 32, KSPLIT), 256, (H2 / KSPLIT) * 33 * 4>>>(enc_hid, Wproj, qwp, HH, H2, KSPLIT);
    reduce8_bias_kernel<<<(BB * HH + 255) / 256, 256>>>(qwp, bproj, h, BB * HH, HH);
    hconv_kernel<<<(BB * HH + 255) / 256, 256>>>(h, hhi, hlo);
    rnn_gemm_kernel<<<H3 / 64, 256, RN_SMEM>>>(hhi, hlo, whhThi, whhTlo, gh);

    // ---- Phase B: minimal serial recurrence (2 kernels/step) ----
    for (int t = 0; t < TT; t++) {
        gates_kernel<<<(BB * HH) / 256, 256>>>(gi, gh, bhh, h, hhi, hlo, c16hi, c16lo, t);
        if (t + 1 < TT)
            rnn_gemm_kernel<<<H3 / 64, 256, RN_SMEM>>>(hhi, hlo, whhThi, whhTlo, gh);
    }

    // ---- batched attention (post-recurrence) ----
    mma_f16_kernel<<<dim3((BB * TT) / 128, HH / 128), 256, F6_SMEM>>>(
        c16hi, c16lo, w16, bq, qw_all, HH, HH, H2);
    scores_batch_kernel<<<BB * TT, 256>>>(qw_all, wc, bc, mask, vw, wsm);
    ctx_batch_kernel<<<dim3(BB, HH / 128), 128, CTX_SMEM>>>(wsm, values, c16hi, c16lo);

    // ---- Phase C: logits (fp16 2-product) ----
    wconv16_kernel<<<dim3(VV / 32, H2 / 32), dim3(32, 8)>>>(Wout, w16, H2, VV);
    mma_f16_kernel<<<dim3((BB * TT) / 128, VV / 128), 256, F6_SMEM>>>(
        c16hi, c16lo, w16, bout, out, H2, VV, H2);

    long btv = (long)BB * TT * VV;
    if ((long)out_size >= btv + BB * HH)
        copyh_kernel<<<(BB * HH + 255) / 256, 256>>>(h, out + btv);
}

// round 14
// speedup vs baseline: 5.2013x; 1.2460x over previous
#include <cuda_runtime.h>
#include <cuda_bf16.h>
#include <cuda_fp16.h>
#include <cstdint>

#define BB 32
#define SS 128
#define TT 96
#define HH 1024
#define VV 32000
#define H3 3072
#define H2 2048
#define KSPLIT 8

// ---------------- scratch (static device globals; no allocation) ----------------
__device__ float g_values[BB * SS * HH];
__device__ float g_vw[BB * SS * HH];
__device__ float g_gi[BB * TT * H3];
__device__ float g_qwp[KSPLIT * BB * HH];
__device__ float g_h[BB * HH];
__device__ float g_gh[BB * H3];
__device__ float g_qw_all[BB * TT * HH];
__device__ float g_wsm[BB * TT * SS];
__device__ __nv_bfloat16 g_hhi[BB * HH];
__device__ __nv_bfloat16 g_hlo[BB * HH];
__device__ __nv_bfloat16 g_ahi[4096 * 2048];
__device__ __nv_bfloat16 g_alo[4096 * 2048];
__device__ __nv_bfloat16 g_a2hi[4096 * 1024];
__device__ __nv_bfloat16 g_a2lo[4096 * 1024];
__device__ __nv_bfloat16 g_whi[3072 * 2048];
__device__ __nv_bfloat16 g_wlo[3072 * 2048];
__device__ __nv_bfloat16 g_whhThi[H3 * HH];
__device__ __nv_bfloat16 g_whhTlo[H3 * HH];
__device__ __half g_c16hi[BB * TT * H2];      // combined fp16 hi/lo
__device__ __half g_c16lo[BB * TT * H2];
__device__ __half g_w16[32000u * 2048u];      // fp16 weights (Wq then Wout)

// ---------------- fast transcendentals ------------------------------------------
__device__ __forceinline__ float ex2f(float x) {
    float y; asm("ex2.approx.f32 %0, %1;" : "=f"(y) : "f"(x)); return y;
}
__device__ __forceinline__ float rcpf(float x) {
    float y; asm("rcp.approx.f32 %0, %1;" : "=f"(y) : "f"(x)); return y;
}
__device__ __forceinline__ float sigmf(float x) {
    return rcpf(1.0f + ex2f(-1.4426950408889634f * x));
}
__device__ __forceinline__ float tanhx(float x) {
    float e = ex2f(2.8853900817779268f * x);
    return 1.0f - 2.0f * rcpf(e + 1.0f);
}

__device__ __forceinline__ uint32_t smem_to_u32(const void* p) {
    uint32_t a;
    asm("{ .reg .u64 t; cvta.to.shared.u64 t, %1; cvt.u32.u64 %0, t; }" : "=r"(a) : "l"(p));
    return a;
}

// ---------------- mma.sync primitives --------------------------------------------
__device__ __forceinline__ void ldsm_x4(uint32_t* r, uint32_t addr) {
    asm volatile("ldmatrix.sync.aligned.m8n8.x4.shared.b16 {%0,%1,%2,%3}, [%4];"
        : "=r"(r[0]), "=r"(r[1]), "=r"(r[2]), "=r"(r[3]) : "r"(addr));
}
__device__ __forceinline__ void mma16816(float* d, const uint32_t* a, uint32_t b0, uint32_t b1) {
    asm volatile("mma.sync.aligned.m16n8k16.row.col.f32.bf16.bf16.f32 "
        "{%0,%1,%2,%3}, {%4,%5,%6,%7}, {%8,%9}, {%0,%1,%2,%3};"
        : "+f"(d[0]), "+f"(d[1]), "+f"(d[2]), "+f"(d[3])
        : "r"(a[0]), "r"(a[1]), "r"(a[2]), "r"(a[3]), "r"(b0), "r"(b1));
}
__device__ __forceinline__ void mma16816h(float* d, const uint32_t* a, uint32_t b0, uint32_t b1) {
    asm volatile("mma.sync.aligned.m16n8k16.row.col.f32.f16.f16.f32 "
        "{%0,%1,%2,%3}, {%4,%5,%6,%7}, {%8,%9}, {%0,%1,%2,%3};"
        : "+f"(d[0]), "+f"(d[1]), "+f"(d[2]), "+f"(d[3])
        : "r"(a[0]), "r"(a[1]), "r"(a[2]), "r"(a[3]), "r"(b0), "r"(b1));
}
__device__ __forceinline__ void cp16(uint32_t dst, const void* src) {
    asm volatile("cp.async.cg.shared.global [%0], [%1], 16;" :: "r"(dst), "l"(src));
}

// ---------------- conversion kernels ---------------------------------------------
// W [K,N] fp32 -> whi/wlo [N,K] bf16 (transpose + split). grid (N/32, K/32), block (32,8)
__global__ void wconv_kernel(const float* __restrict__ W, __nv_bfloat16* __restrict__ whi,
                             __nv_bfloat16* __restrict__ wlo, int K, int N) {
    __shared__ float t[32][33];
    int n0 = blockIdx.x * 32, k0 = blockIdx.y * 32;
    int tx = threadIdx.x, ty = threadIdx.y;
#pragma unroll
    for (int j = 0; j < 4; j++)
        t[ty + 8 * j][tx] = W[(long)(k0 + ty + 8 * j) * N + n0 + tx];
    __syncthreads();
#pragma unroll
    for (int j = 0; j < 4; j++) {
        int n = n0 + ty + 8 * j;
        float x = t[tx][ty + 8 * j];
        __nv_bfloat16 h = __float2bfloat16(x);
        float r = x - __bfloat162float(h);
        long o = (long)n * K + k0 + tx;
        whi[o] = h;
        wlo[o] = __float2bfloat16(r);
    }
}

// W [K,N] fp32 -> w16 [N,K] fp16 (transpose)
__global__ void wconv16_kernel(const float* __restrict__ W, __half* __restrict__ w16,
                               int K, int N) {
    __shared__ float t[32][33];
    int n0 = blockIdx.x * 32, k0 = blockIdx.y * 32;
    int tx = threadIdx.x, ty = threadIdx.y;
#pragma unroll
    for (int j = 0; j < 4; j++)
        t[ty + 8 * j][tx] = W[(long)(k0 + ty + 8 * j) * N + n0 + tx];
    __syncthreads();
#pragma unroll
    for (int j = 0; j < 4; j++) {
        int n = n0 + ty + 8 * j;
        w16[(long)n * K + k0 + tx] = __float2half_rn(t[tx][ty + 8 * j]);
    }
}

__global__ void aconv_kernel(const float* __restrict__ A, __nv_bfloat16* __restrict__ ahi,
                             __nv_bfloat16* __restrict__ alo, int n) {
    int i = blockIdx.x * 256 + threadIdx.x;
    if (i >= n) return;
    float x = A[i];
    __nv_bfloat16 h = __float2bfloat16(x);
    ahi[i] = h;
    alo[i] = __float2bfloat16(x - __bfloat162float(h));
}

__global__ void aconv_gather_kernel(const float* __restrict__ emb, const int* __restrict__ idx,
                                    __nv_bfloat16* __restrict__ ahi, __nv_bfloat16* __restrict__ alo,
                                    int n) {
    int i = blockIdx.x * 256 + threadIdx.x;
    if (i >= n) return;
    int r = i >> 10, k = i & 1023;
    float x = emb[(long)idx[r] * HH + k];
    __nv_bfloat16 h = __float2bfloat16(x);
    ahi[i] = h;
    alo[i] = __float2bfloat16(x - __bfloat162float(h));
}

// ---------------- bf16 3-product HMMA GEMM (Phase A) ------------------------------
#define MM_PITCH 40
#define MM_MAT (128 * MM_PITCH * 2)
#define MM_STAGE (4 * MM_MAT)
#define MM_SMEM (2 * MM_STAGE)

__global__ __launch_bounds__(256, 2)
void mma_gemm_kernel(const __nv_bfloat16* __restrict__ Ahi, const __nv_bfloat16* __restrict__ Alo,
                     const __nv_bfloat16* __restrict__ Bhi, const __nv_bfloat16* __restrict__ Blo,
                     const float* __restrict__ bias, float* __restrict__ C, int K, int N,
                     __nv_bfloat16* __restrict__ Chi, __nv_bfloat16* __restrict__ Clo) {
    extern __shared__ __align__(16) char smem[];
    const uint32_t sb = smem_to_u32(smem);
    const int tid = threadIdx.x;
    const int wid = tid >> 5, lane = tid & 31;
    const int m0 = blockIdx.x * 128, n0 = blockIdx.y * 128;
    const int wm = (wid >> 1) * 32;
    const int wn = (wid & 1) * 64;
    const int NC = K >> 5;

    const __nv_bfloat16* gp0 = Ahi + (long)m0 * K;
    const __nv_bfloat16* gp1 = Alo + (long)m0 * K;
    const __nv_bfloat16* gp2 = Bhi + (long)n0 * K;
    const __nv_bfloat16* gp3 = Blo + (long)n0 * K;

    const __nv_bfloat16* gptr[8];
    uint32_t soff[8];
#pragma unroll
    for (int j = 0; j < 8; j++) {
        int i = tid + j * 256;
        int mat = i >> 9, r = (i >> 2) & 127, s = i & 3;
        const __nv_bfloat16* g = (mat == 0) ? gp0 : (mat == 1) ? gp1 : (mat == 2) ? gp2 : gp3;
        gptr[j] = g + (long)r * K + s * 8;
        soff[j] = (uint32_t)(mat * MM_MAT + r * (MM_PITCH * 2) + s * 16);
    }

    float acc[2][8][4];
#pragma unroll
    for (int a = 0; a < 2; a++)
#pragma unroll
        for (int b = 0; b < 8; b++)
#pragma unroll
            for (int c = 0; c < 4; c++) acc[a][b][c] = 0.0f;

    const int arow = lane & 15;
    const int acol = (lane >> 4) << 3;
    const int brow = ((lane >> 4) << 3) + (lane & 7);
    const int bcol = ((lane >> 3) & 1) << 3;

    auto issue = [&](int c, int buf) {
        const uint32_t b0 = sb + buf * MM_STAGE;
#pragma unroll
        for (int j = 0; j < 8; j++) cp16(b0 + soff[j], gptr[j] + c * 32);
        asm volatile("cp.async.commit_group;" ::: "memory");
    };

    issue(0, 0);

    for (int c = 0; c < NC; c++) {
        const int buf = c & 1;
        if (c + 1 < NC) {
            issue(c + 1, buf ^ 1);
            asm volatile("cp.async.wait_group 1;" ::: "memory");
        } else {
            asm volatile("cp.async.wait_group 0;" ::: "memory");
        }
        __syncthreads();

        const uint32_t base = sb + buf * MM_STAGE;
#pragma unroll
        for (int ks = 0; ks < 2; ks++) {
            const int kc = ks * 16;
            uint32_t ah[2][4], al[2][4], bb[4][4];
#pragma unroll
            for (int tm = 0; tm < 2; tm++) {
                uint32_t ad = base + (uint32_t)(((wm + tm * 16 + arow) * MM_PITCH + kc + acol) * 2);
                ldsm_x4(ah[tm], ad);
                ldsm_x4(al[tm], ad + MM_MAT);
            }
#pragma unroll
            for (int gn = 0; gn < 4; gn++) {
                uint32_t bd = base + 2 * MM_MAT +
                    (uint32_t)(((wn + gn * 16 + brow) * MM_PITCH + kc + bcol) * 2);
                ldsm_x4(bb[gn], bd);
            }
#pragma unroll
            for (int tm = 0; tm < 2; tm++)
#pragma unroll
                for (int j = 0; j < 8; j++) {
                    uint32_t b0 = bb[j >> 1][(j & 1) * 2];
                    uint32_t b1 = bb[j >> 1][(j & 1) * 2 + 1];
                    mma16816(acc[tm][j], ah[tm], b0, b1);
                    mma16816(acc[tm][j], al[tm], b0, b1);
                }
#pragma unroll
            for (int gn = 0; gn < 4; gn++) {
                uint32_t bd = base + 3 * MM_MAT +
                    (uint32_t)(((wn + gn * 16 + brow) * MM_PITCH + kc + bcol) * 2);
                ldsm_x4(bb[gn], bd);
            }
#pragma unroll
            for (int tm = 0; tm < 2; tm++)
#pragma unroll
                for (int j = 0; j < 8; j++)
                    mma16816(acc[tm][j], ah[tm],
                             bb[j >> 1][(j & 1) * 2], bb[j >> 1][(j & 1) * 2 + 1]);
        }
        __syncthreads();
    }

#pragma unroll
    for (int tm = 0; tm < 2; tm++) {
        const int r0 = m0 + wm + tm * 16 + (lane >> 2);
#pragma unroll
        for (int j = 0; j < 8; j++) {
            const int col = n0 + wn + j * 8 + (lane & 3) * 2;
            float b0 = bias[col], b1 = bias[col + 1];
            float v0 = acc[tm][j][0] + b0, v1 = acc[tm][j][1] + b1;
            float v2 = acc[tm][j][2] + b0, v3 = acc[tm][j][3] + b1;
            long o0 = (long)r0 * N + col;
            long o1 = o0 + 8 * (long)N;
            C[o0] = v0; C[o0 + 1] = v1;
            C[o1] = v2; C[o1 + 1] = v3;
            if (Chi) {
                __nv_bfloat16 t0 = __float2bfloat16(v0), t1 = __float2bfloat16(v1);
                __nv_bfloat16 t2 = __float2bfloat16(v2), t3 = __float2bfloat16(v3);
                Chi[o0] = t0; Chi[o0 + 1] = t1; Chi[o1] = t2; Chi[o1 + 1] = t3;
                Clo[o0] = __float2bfloat16(v0 - __bfloat162float(t0));
                Clo[o0 + 1] = __float2bfloat16(v1 - __bfloat162float(t1));
                Clo[o1] = __float2bfloat16(v2 - __bfloat162float(t2));
                Clo[o1 + 1] = __float2bfloat16(v3 - __bfloat162float(t3));
            }
        }
    }
}

// ---------------- fp16 HMMA GEMM (TWO: A hi+lo products; else single) -------------
// C[M,N] = A @ B^T + bias; Ahi/Alo fp16 [M, lda] (first K cols), B fp16 [N,K] K-major.
#define F6_MAT (128 * MM_PITCH * 2)
#define F6_SMEM_MAX (2 * 3 * F6_MAT)

template <bool TWO>
__global__ __launch_bounds__(256, 2)
void mma_f16_kernel(const __half* __restrict__ Ahi, const __half* __restrict__ Alo,
                    const __half* __restrict__ Bf, const float* __restrict__ bias,
                    float* __restrict__ C, int K, int N, int lda) {
    constexpr int MATS = TWO ? 3 : 2;
    constexpr int STAGE = MATS * F6_MAT;
    constexpr int NCP = MATS * 2;            // cp16 per thread per stage
    extern __shared__ __align__(16) char smem[];
    const uint32_t sb = smem_to_u32(smem);
    const int tid = threadIdx.x;
    const int wid = tid >> 5, lane = tid & 31;
    const int m0 = blockIdx.x * 128, n0 = blockIdx.y * 128;
    const int wm = (wid >> 1) * 32;
    const int wn = (wid & 1) * 64;
    const int NC = K >> 5;
    const int bmat = (MATS - 1) * F6_MAT;    // B tile smem offset

    const __half* gp0 = Ahi + (long)m0 * lda;
    const __half* gp1 = TWO ? (Alo + (long)m0 * lda) : nullptr;
    const __half* gp2 = Bf + (long)n0 * K;

    const __half* gptr[NCP];
    uint32_t soff[NCP];
#pragma unroll
    for (int j = 0; j < NCP; j++) {
        int i = tid + j * 256;
        int mat = i >> 9, r = (i >> 2) & 127, s = i & 3;
        const __half* g;
        if (mat == 0) g = gp0 + (long)r * lda;
        else if (TWO && mat == 1) g = gp1 + (long)r * lda;
        else g = gp2 + (long)r * K;
        gptr[j] = g + s * 8;
        soff[j] = (uint32_t)(mat * F6_MAT + r * (MM_PITCH * 2) + s * 16);
    }

    float acc[2][8][4];
#pragma unroll
    for (int a = 0; a < 2; a++)
#pragma unroll
        for (int b = 0; b < 8; b++)
#pragma unroll
            for (int c = 0; c < 4; c++) acc[a][b][c] = 0.0f;

    const int arow = lane & 15;
    const int acol = (lane >> 4) << 3;
    const int brow = ((lane >> 4) << 3) + (lane & 7);
    const int bcol = ((lane >> 3) & 1) << 3;

    auto issue = [&](int c, int buf) {
        const uint32_t b0 = sb + buf * STAGE;
#pragma unroll
        for (int j = 0; j < NCP; j++) cp16(b0 + soff[j], gptr[j] + c * 32);
        asm volatile("cp.async.commit_group;" ::: "memory");
    };

    issue(0, 0);

    for (int c = 0; c < NC; c++) {
        const int buf = c & 1;
        if (c + 1 < NC) {
            issue(c + 1, buf ^ 1);
            asm volatile("cp.async.wait_group 1;" ::: "memory");
        } else {
            asm volatile("cp.async.wait_group 0;" ::: "memory");
        }
        __syncthreads();

        const uint32_t base = sb + buf * STAGE;
#pragma unroll
        for (int ks = 0; ks < 2; ks++) {
            const int kc = ks * 16;
            uint32_t ah[2][4], al[2][4], bb[4][4];
#pragma unroll
            for (int tm = 0; tm < 2; tm++) {
                uint32_t ad = base + (uint32_t)(((wm + tm * 16 + arow) * MM_PITCH + kc + acol) * 2);
                ldsm_x4(ah[tm], ad);
                if (TWO) ldsm_x4(al[tm], ad + F6_MAT);
            }
#pragma unroll
            for (int gn = 0; gn < 4; gn++) {
                uint32_t bd = base + bmat +
                    (uint32_t)(((wn + gn * 16 + brow) * MM_PITCH + kc + bcol) * 2);
                ldsm_x4(bb[gn], bd);
            }
#pragma unroll
            for (int tm = 0; tm < 2; tm++)
#pragma unroll
                for (int j = 0; j < 8; j++) {
                    uint32_t b0 = bb[j >> 1][(j & 1) * 2];
                    uint32_t b1 = bb[j >> 1][(j & 1) * 2 + 1];
                    mma16816h(acc[tm][j], ah[tm], b0, b1);
                    if (TWO) mma16816h(acc[tm][j], al[tm], b0, b1);
                }
        }
        __syncthreads();
    }

#pragma unroll
    for (int tm = 0; tm < 2; tm++) {
        const int r0 = m0 + wm + tm * 16 + (lane >> 2);
#pragma unroll
        for (int j = 0; j < 8; j++) {
            const int col = n0 + wn + j * 8 + (lane & 3) * 2;
            float b0 = bias[col], b1 = bias[col + 1];
            long o0 = (long)r0 * N + col;
            long o1 = o0 + 8 * (long)N;
            C[o0] = acc[tm][j][0] + b0;
            C[o0 + 1] = acc[tm][j][1] + b1;
            C[o1] = acc[tm][j][2] + b0;
            C[o1 + 1] = acc[tm][j][3] + b1;
        }
    }
}

// ---------------- recurrence HMMA GEMM: gh[32,3072] = h @ Whh^T -------------------
#define RN_PITCH 72
#define RN_AMAT (32 * RN_PITCH * 2)
#define RN_BMAT (64 * RN_PITCH * 2)
#define RN_STAGE (2 * RN_AMAT + 2 * RN_BMAT)
#define RN_SMEM (2 * RN_STAGE)

__global__ __launch_bounds__(256, 2)
void rnn_gemm_kernel(const __nv_bfloat16* __restrict__ hhi, const __nv_bfloat16* __restrict__ hlo,
                     const __nv_bfloat16* __restrict__ bhi, const __nv_bfloat16* __restrict__ blo,
                     float* __restrict__ gh) {
    extern __shared__ __align__(16) char smem[];
    const uint32_t sb = smem_to_u32(smem);
    const int tid = threadIdx.x;
    const int wid = tid >> 5, lane = tid & 31;
    const int n0 = blockIdx.x * 64;
    const int wm2 = wid >> 2;
    const int wn2 = wid & 3;

    const __nv_bfloat16* gptr[6];
    uint32_t soff[6];
#pragma unroll
    for (int j = 0; j < 6; j++) {
        int i = tid + j * 256;
        if (i < 512) {
            int ii = i & 255;
            int r = ii >> 3, s = ii & 7;
            const __nv_bfloat16* g = (i < 256) ? hhi : hlo;
            gptr[j] = g + r * HH + s * 8;
            soff[j] = (uint32_t)((i < 256 ? 0 : RN_AMAT) + r * (RN_PITCH * 2) + s * 16);
        } else {
            int ii = (i - 512) & 511;
            int r = ii >> 3, s = ii & 7;
            const __nv_bfloat16* g = (i < 1024) ? bhi : blo;
            gptr[j] = g + (long)(n0 + r) * HH + s * 8;
            soff[j] = (uint32_t)(2 * RN_AMAT + (i < 1024 ? 0 : RN_BMAT) + r * (RN_PITCH * 2) + s * 16);
        }
    }

    float acc[2][4];
#pragma unroll
    for (int j = 0; j < 2; j++)
#pragma unroll
        for (int c = 0; c < 4; c++) acc[j][c] = 0.0f;

    const int arow = lane & 15;
    const int acol = (lane >> 4) << 3;
    const int brow = ((lane >> 4) << 3) + (lane & 7);
    const int bcol = ((lane >> 3) & 1) << 3;

    auto issue = [&](int c, int buf) {
        const uint32_t b0 = sb + buf * RN_STAGE;
#pragma unroll
        for (int j = 0; j < 6; j++) cp16(b0 + soff[j], gptr[j] + c * 64);
        asm volatile("cp.async.commit_group;" ::: "memory");
    };

    issue(0, 0);
    const int NC = HH / 64;
    for (int c = 0; c < NC; c++) {
        const int buf = c & 1;
        if (c + 1 < NC) {
            issue(c + 1, buf ^ 1);
            asm volatile("cp.async.wait_group 1;" ::: "memory");
        } else {
            asm volatile("cp.async.wait_group 0;" ::: "memory");
        }
        __syncthreads();

        const uint32_t base = sb + buf * RN_STAGE;
#pragma unroll
        for (int ks = 0; ks < 4; ks++) {
            const int kc = ks * 16;
            uint32_t ah[4], al[4], bh[4], bl[4];
            uint32_t ad = base + (uint32_t)(((wm2 * 16 + arow) * RN_PITCH + kc + acol) * 2);
            ldsm_x4(ah, ad);
            ldsm_x4(al, ad + RN_AMAT);
            uint32_t bd = base + 2 * RN_AMAT +
                (uint32_t)(((wn2 * 16 + brow) * RN_PITCH + kc + bcol) * 2);
            ldsm_x4(bh, bd);
            ldsm_x4(bl, bd + RN_BMAT);
#pragma unroll
            for (int j = 0; j < 2; j++) {
                mma16816(acc[j], ah, bh[j * 2], bh[j * 2 + 1]);
                mma16816(acc[j], al, bh[j * 2], bh[j * 2 + 1]);
                mma16816(acc[j], ah, bl[j * 2], bl[j * 2 + 1]);
            }
        }
        __syncthreads();
    }

    const int row = wm2 * 16 + (lane >> 2);
#pragma unroll
    for (int j = 0; j < 2; j++) {
        const int col = n0 + wn2 * 16 + j * 8 + (lane & 3) * 2;
        gh[row * H3 + col] = acc[j][0];
        gh[row * H3 + col + 1] = acc[j][1];
        gh[(row + 8) * H3 + col] = acc[j][2];
        gh[(row + 8) * H3 + col + 1] = acc[j][3];
    }
}

// ---------------- small-M fp32 split-K GEMM (h0 only) ----------------------------
__global__ void gemm_m32_kernel(const float* __restrict__ A, const float* __restrict__ Bm,
                                float* __restrict__ Cp, int N, int K, int ksplit) {
    extern __shared__ float sh[];
    const int kslice = K / ksplit;
    const int tid = threadIdx.x;
    const int k0 = blockIdx.y * kslice;

    for (int i = tid; i < 32 * kslice; i += 256) {
        int b = i / kslice;
        int k = i - b * kslice;
        sh[k * 33 + b] = A[b * K + k0 + k];
    }
    __syncthreads();

    const int w = tid >> 5, lane = tid & 31;
    const int n0 = blockIdx.x * 32 + w * 4;
    const float* Bp = Bm + (long)k0 * N + n0;
    float a0 = 0.f, a1 = 0.f, a2 = 0.f, a3 = 0.f;
#pragma unroll 8
    for (int k = 0; k < kslice; k++) {
        float4 wv = *(const float4*)(Bp + (long)k * N);
        float a = sh[k * 33 + lane];
        a0 += a * wv.x; a1 += a * wv.y; a2 += a * wv.z; a3 += a * wv.w;
    }
    float4* o = (float4*)(Cp + ((long)blockIdx.y * 32 + lane) * N + n0);
    *o = make_float4(a0, a1, a2, a3);
}

__global__ void reduce8_bias_kernel(const float* __restrict__ part, const float* __restrict__ bias,
                                    float* __restrict__ out, int n, int biasN) {
    int i = blockIdx.x * 256 + threadIdx.x;
    if (i >= n) return;
    float s = bias[i % biasN];
#pragma unroll
    for (int p = 0; p < KSPLIT; p++) s += part[(long)p * n + i];
    out[i] = s;
}

__global__ void hconv_kernel(const float* __restrict__ h, __nv_bfloat16* __restrict__ hhi,
                             __nv_bfloat16* __restrict__ hlo) {
    int i = blockIdx.x * 256 + threadIdx.x;
    if (i >= BB * HH) return;
    float x = h[i];
    __nv_bfloat16 t = __float2bfloat16(x);
    hhi[i] = t;
    hlo[i] = __float2bfloat16(x - __bfloat162float(t));
}

// ---------------- fused GRU gates ------------------------------------------------
__global__ void gates_kernel(const float* __restrict__ gi, const float* __restrict__ gh,
                             const float* __restrict__ bhh, float* __restrict__ h,
                             __nv_bfloat16* __restrict__ hhi, __nv_bfloat16* __restrict__ hlo,
                             __half* __restrict__ c16hi, __half* __restrict__ c16lo, int t) {
    int i = blockIdx.x * 256 + threadIdx.x;
    int b = i >> 10;
    int n = i & 1023;
    const float* g = gh + (long)b * H3;
    float hr = bhh[n] + g[n];
    float hz = bhh[HH + n] + g[HH + n];
    float hn = bhh[2 * HH + n] + g[2 * HH + n];
    const float* gir = gi + ((long)b * TT + t) * H3;
    float r = sigmf(gir[n] + hr);
    float z = sigmf(gir[HH + n] + hz);
    float nn = tanhx(gir[2 * HH + n] + r * hn);
    float hv = (1.0f - z) * nn + z * h[i];
    h[i] = hv;
    __nv_bfloat16 th = __float2bfloat16(hv);
    hhi[i] = th;
    hlo[i] = __float2bfloat16(hv - __bfloat162float(th));
    long co = ((long)b * TT + t) * H2 + n;
    __half f = __float2half_rn(hv);
    c16hi[co] = f;
    c16lo[co] = __float2half_rn(hv - __half2float(f));
}

// ---------------- batched scores + softmax (one block per (b,t)) -----------------
__global__ __launch_bounds__(256)
void scores_batch_kernel(const float* __restrict__ qw_all, const float* __restrict__ wc_g,
                         const float* __restrict__ bc, const int* __restrict__ mask,
                         const float* __restrict__ vw, float* __restrict__ wsm) {
    __shared__ float q[HH];
    __shared__ float wcs[HH];
    __shared__ float sc[SS];
    __shared__ float red[SS];
    const int blk = blockIdx.x;          // = b*TT + t
    const int b = blk / TT;
    const int tid = threadIdx.x;
    for (int i = tid; i < HH; i += 256) {
        q[i] = qw_all[(long)blk * HH + i];
        wcs[i] = wc_g[i];
    }
    __syncthreads();
    const int w = tid >> 5, lane = tid & 31;
#pragma unroll
    for (int si = 0; si < 16; si++) {
        const int s = w * 16 + si;
        const float* v = vw + (long)(b * SS + s) * HH;
        float a = 0.0f;
        for (int hh = lane; hh < HH; hh += 32)
            a += wcs[hh] * tanhx(q[hh] + v[hh]);
#pragma unroll
        for (int off = 16; off > 0; off >>= 1) a += __shfl_xor_sync(0xffffffffu, a, off);
        if (lane == 0)
            sc[s] = a + bc[0] + (mask[b * SS + s] == 0 ? -1e30f : 0.0f);
    }
    __syncthreads();
    if (tid < 128) red[tid] = sc[tid];
    __syncthreads();
#pragma unroll
    for (int off = 64; off > 0; off >>= 1) {
        if (tid < off) red[tid] = fmaxf(red[tid], red[tid + off]);
        __syncthreads();
    }
    float mx = red[0];
    __syncthreads();
    float e = 0.0f;
    if (tid < 128) { e = ex2f((sc[tid] - mx) * 1.4426950408889634f); red[tid] = e; }
    __syncthreads();
#pragma unroll
    for (int off = 64; off > 0; off >>= 1) {
        if (tid < off) red[tid] += red[tid + off];
        __syncthreads();
    }
    if (tid < 128) wsm[(long)blk * SS + tid] = e * rcpf(red[0]);
}

// ---------------- batched context (values staged in smem, hi only out) -----------
#define CTX_SMEM ((SS * 128 + SS) * 4)
__global__ __launch_bounds__(128)
void ctx_batch_kernel(const float* __restrict__ wsm, const float* __restrict__ values,
                      __half* __restrict__ c16hi) {
    extern __shared__ float csm[];
    float* val = csm;               // [SS][128]
    float* wv = csm + SS * 128;     // [SS]
    const int b = blockIdx.x;
    const int h0 = blockIdx.y * 128;
    const int tid = threadIdx.x;
    for (int s = 0; s < SS; s++)
        val[s * 128 + tid] = values[(long)(b * SS + s) * HH + h0 + tid];
    __syncthreads();
    for (int t = 0; t < TT; t++) {
        wv[tid] = wsm[((long)b * TT + t) * SS + tid];
        __syncthreads();
        float acc = 0.0f;
#pragma unroll 16
        for (int s = 0; s < SS; s++) acc += wv[s] * val[s * 128 + tid];
        long co = ((long)b * TT + t) * H2 + HH + h0 + tid;
        c16hi[co] = __float2half_rn(acc);
        __syncthreads();
    }
}

__global__ void copyh_kernel(const float* __restrict__ h, float* __restrict__ out) {
    int i = blockIdx.x * 256 + threadIdx.x;
    if (i < BB * HH) out[i] = h[i];
}

// ---------------- launch ----------------------------------------------------------
extern "C" void kernel_launch(void* const* d_in, const int* in_sizes, int n_in,
                              void* d_out, int out_size) {
    const float* enc_out = (const float*)d_in[0];
    const float* enc_hid = (const float*)d_in[1];
    const int*   mask    = (const int*)d_in[2];
    const int*   tgt     = (const int*)d_in[3];
    const float* emb     = (const float*)d_in[4];
    const float* Wq   = (const float*)d_in[5];
    const float* bq   = (const float*)d_in[6];
    const float* Wv   = (const float*)d_in[7];
    const float* bv   = (const float*)d_in[8];
    const float* wc   = (const float*)d_in[9];
    const float* bc   = (const float*)d_in[10];
    const float* Wih  = (const float*)d_in[11];
    const float* bih  = (const float*)d_in[12];
    const float* Whh  = (const float*)d_in[13];
    const float* bhh  = (const float*)d_in[14];
    const float* Wproj = (const float*)d_in[15];
    const float* bproj = (const float*)d_in[16];
    const float* Wout  = (const float*)d_in[17];
    const float* bout  = (const float*)d_in[18];
    float* out = (float*)d_out;

    float *values, *vw, *gi, *qwp, *h, *gh, *qw_all, *wsm;
    __nv_bfloat16 *hhi, *hlo, *ahi, *alo, *a2hi, *a2lo, *whi, *wlo, *whhThi, *whhTlo;
    __half *c16hi, *c16lo, *w16;
    cudaGetSymbolAddress((void**)&values, g_values);
    cudaGetSymbolAddress((void**)&vw, g_vw);
    cudaGetSymbolAddress((void**)&gi, g_gi);
    cudaGetSymbolAddress((void**)&qwp, g_qwp);
    cudaGetSymbolAddress((void**)&h, g_h);
    cudaGetSymbolAddress((void**)&gh, g_gh);
    cudaGetSymbolAddress((void**)&qw_all, g_qw_all);
    cudaGetSymbolAddress((void**)&wsm, g_wsm);
    cudaGetSymbolAddress((void**)&hhi, g_hhi);
    cudaGetSymbolAddress((void**)&hlo, g_hlo);
    cudaGetSymbolAddress((void**)&ahi, g_ahi);
    cudaGetSymbolAddress((void**)&alo, g_alo);
    cudaGetSymbolAddress((void**)&a2hi, g_a2hi);
    cudaGetSymbolAddress((void**)&a2lo, g_a2lo);
    cudaGetSymbolAddress((void**)&whi, g_whi);
    cudaGetSymbolAddress((void**)&wlo, g_wlo);
    cudaGetSymbolAddress((void**)&whhThi, g_whhThi);
    cudaGetSymbolAddress((void**)&whhTlo, g_whhTlo);
    cudaGetSymbolAddress((void**)&c16hi, g_c16hi);
    cudaGetSymbolAddress((void**)&c16lo, g_c16lo);
    cudaGetSymbolAddress((void**)&w16, g_w16);

    cudaFuncSetAttribute(mma_gemm_kernel, cudaFuncAttributeMaxDynamicSharedMemorySize, MM_SMEM);
    cudaFuncSetAttribute(mma_f16_kernel<true>, cudaFuncAttributeMaxDynamicSharedMemorySize, F6_SMEM_MAX);
    cudaFuncSetAttribute(mma_f16_kernel<false>, cudaFuncAttributeMaxDynamicSharedMemorySize, 2 * 2 * F6_MAT);
    cudaFuncSetAttribute(rnn_gemm_kernel, cudaFuncAttributeMaxDynamicSharedMemorySize, RN_SMEM);
    cudaFuncSetAttribute(ctx_batch_kernel, cudaFuncAttributeMaxDynamicSharedMemorySize, CTX_SMEM);

    // ---- weight prep ----
    wconv_kernel<<<dim3(H3 / 32, HH / 32), dim3(32, 8)>>>(Whh, whhThi, whhTlo, HH, H3);
    wconv16_kernel<<<dim3(HH / 32, HH / 32), dim3(32, 8)>>>(Wq, w16, HH, HH);

    // ---- Phase A (bf16 3-product HMMA) ----
    wconv_kernel<<<dim3(HH / 32, H2 / 32), dim3(32, 8)>>>(Wproj, whi, wlo, H2, HH);
    aconv_kernel<<<(4096 * 2048) / 256, 256>>>(enc_out, ahi, alo, 4096 * 2048);
    mma_gemm_kernel<<<dim3(4096 / 128, HH / 128), 256, MM_SMEM>>>(
        ahi, alo, whi, wlo, bproj, values, H2, HH, a2hi, a2lo);
    wconv_kernel<<<dim3(HH / 32, HH / 32), dim3(32, 8)>>>(Wv, whi, wlo, HH, HH);
    mma_gemm_kernel<<<dim3(4096 / 128, HH / 128), 256, MM_SMEM>>>(
        a2hi, a2lo, whi, wlo, bv, vw, HH, HH, nullptr, nullptr);
    wconv_kernel<<<dim3(H3 / 32, HH / 32), dim3(32, 8)>>>(Wih, whi, wlo, HH, H3);
    aconv_gather_kernel<<<(BB * TT * HH) / 256, 256>>>(emb, tgt, ahi, alo, BB * TT * HH);
    mma_gemm_kernel<<<dim3((BB * TT) / 128, H3 / 128), 256, MM_SMEM>>>(
        ahi, alo, whi, wlo, bih, gi, HH, H3, nullptr, nullptr);
    // h0
    gemm_m32_kernel<<<dim3(HH / 32, KSPLIT), 256, (H2 / KSPLIT) * 33 * 4>>>(enc_hid, Wproj, qwp, HH, H2, KSPLIT);
    reduce8_bias_kernel<<<(BB * HH + 255) / 256, 256>>>(qwp, bproj, h, BB * HH, HH);
    hconv_kernel<<<(BB * HH + 255) / 256, 256>>>(h, hhi, hlo);
    rnn_gemm_kernel<<<H3 / 64, 256, RN_SMEM>>>(hhi, hlo, whhThi, whhTlo, gh);

    // ---- Phase B: minimal serial recurrence (2 kernels/step) ----
    for (int t = 0; t < TT; t++) {
        gates_kernel<<<(BB * HH) / 256, 256>>>(gi, gh, bhh, h, hhi, hlo, c16hi, c16lo, t);
        if (t + 1 < TT)
            rnn_gemm_kernel<<<H3 / 64, 256, RN_SMEM>>>(hhi, hlo, whhThi, whhTlo, gh);
    }

    // ---- batched attention (post-recurrence) ----
    mma_f16_kernel<true><<<dim3((BB * TT) / 128, HH / 128), 256, 2 * 3 * F6_MAT>>>(
        c16hi, c16lo, w16, bq, qw_all, HH, HH, H2);
    scores_batch_kernel<<<BB * TT, 256>>>(qw_all, wc, bc, mask, vw, wsm);
    ctx_batch_kernel<<<dim3(BB, HH / 128), 128, CTX_SMEM>>>(wsm, values, c16hi);

    // ---- Phase C: logits = combined @ Wout + bout (fp16 SINGLE-product) ----
    wconv16_kernel<<<dim3(VV / 32, H2 / 32), dim3(32, 8)>>>(Wout, w16, H2, VV);
    mma_f16_kernel<false><<<dim3((BB * TT) / 128, VV / 128), 256, 2 * 2 * F6_MAT>>>(
        c16hi, nullptr, w16, bout, out, H2, VV, H2);

    long btv = (long)BB * TT * VV;
    if ((long)out_size >= btv + BB * HH)
        copyh_kernel<<<(BB * HH + 255) / 256, 256>>>(h, out + btv);
}

// round 15
// speedup vs baseline: 5.3602x; 1.0306x over previous
#include <cuda_runtime.h>
#include <cuda_bf16.h>
#include <cuda_fp16.h>
#include <cstdint>

#define BB 32
#define SS 128
#define TT 96
#define HH 1024
#define VV 32000
#define H3 3072
#define H2 2048
#define KSPLIT 8

// ---------------- scratch (static device globals; no allocation) ----------------
__device__ float g_values[BB * SS * HH];
__device__ float g_vw[BB * SS * HH];
__device__ float g_gi[BB * TT * H3];
__device__ float g_qwp[KSPLIT * BB * HH];
__device__ float g_h[BB * HH];
__device__ float g_gh[BB * H3];
__device__ float g_qw_all[BB * TT * HH];
__device__ float g_wsm[BB * TT * SS];
__device__ __nv_bfloat16 g_hhi[BB * HH];
__device__ __nv_bfloat16 g_hlo[BB * HH];
__device__ __nv_bfloat16 g_ahi[4096 * 2048];      // enc_out conv (stream2)
__device__ __nv_bfloat16 g_alo[4096 * 2048];
__device__ __nv_bfloat16 g_a2hi[4096 * 1024];     // values hi/lo (stream2)
__device__ __nv_bfloat16 g_a2lo[4096 * 1024];
__device__ __nv_bfloat16 g_whi[2048 * 2048];      // Wproj/Wv conv (stream2)
__device__ __nv_bfloat16 g_wlo[2048 * 2048];
__device__ __nv_bfloat16 g_wihhi[H3 * HH];        // Wih conv (main)
__device__ __nv_bfloat16 g_wihlo[H3 * HH];
__device__ __nv_bfloat16 g_eihi[BB * TT * HH];    // emb gather (main)
__device__ __nv_bfloat16 g_eilo[BB * TT * HH];
__device__ __nv_bfloat16 g_whhThi[H3 * HH];
__device__ __nv_bfloat16 g_whhTlo[H3 * HH];
__device__ __half g_c16hi[BB * TT * H2];
__device__ __half g_c16lo[BB * TT * H2];
__device__ __half g_w16[32000u * 2048u];          // Wout fp16 (stream2)
__device__ __half g_w16q[HH * HH];                // Wq fp16 (stream2)

// ---------------- fast transcendentals ------------------------------------------
__device__ __forceinline__ float ex2f(float x) {
    float y; asm("ex2.approx.f32 %0, %1;" : "=f"(y) : "f"(x)); return y;
}
__device__ __forceinline__ float rcpf(float x) {
    float y; asm("rcp.approx.f32 %0, %1;" : "=f"(y) : "f"(x)); return y;
}
__device__ __forceinline__ float sigmf(float x) {
    return rcpf(1.0f + ex2f(-1.4426950408889634f * x));
}
__device__ __forceinline__ float tanhx(float x) {
    float e = ex2f(2.8853900817779268f * x);
    return 1.0f - 2.0f * rcpf(e + 1.0f);
}

__device__ __forceinline__ uint32_t smem_to_u32(const void* p) {
    uint32_t a;
    asm("{ .reg .u64 t; cvta.to.shared.u64 t, %1; cvt.u32.u64 %0, t; }" : "=r"(a) : "l"(p));
    return a;
}

// ---------------- mma.sync primitives --------------------------------------------
__device__ __forceinline__ void ldsm_x4(uint32_t* r, uint32_t addr) {
    asm volatile("ldmatrix.sync.aligned.m8n8.x4.shared.b16 {%0,%1,%2,%3}, [%4];"
        : "=r"(r[0]), "=r"(r[1]), "=r"(r[2]), "=r"(r[3]) : "r"(addr));
}
__device__ __forceinline__ void mma16816(float* d, const uint32_t* a, uint32_t b0, uint32_t b1) {
    asm volatile("mma.sync.aligned.m16n8k16.row.col.f32.bf16.bf16.f32 "
        "{%0,%1,%2,%3}, {%4,%5,%6,%7}, {%8,%9}, {%0,%1,%2,%3};"
        : "+f"(d[0]), "+f"(d[1]), "+f"(d[2]), "+f"(d[3])
        : "r"(a[0]), "r"(a[1]), "r"(a[2]), "r"(a[3]), "r"(b0), "r"(b1));
}
__device__ __forceinline__ void mma16816h(float* d, const uint32_t* a, uint32_t b0, uint32_t b1) {
    asm volatile("mma.sync.aligned.m16n8k16.row.col.f32.f16.f16.f32 "
        "{%0,%1,%2,%3}, {%4,%5,%6,%7}, {%8,%9}, {%0,%1,%2,%3};"
        : "+f"(d[0]), "+f"(d[1]), "+f"(d[2]), "+f"(d[3])
        : "r"(a[0]), "r"(a[1]), "r"(a[2]), "r"(a[3]), "r"(b0), "r"(b1));
}
__device__ __forceinline__ void cp16(uint32_t dst, const void* src) {
    asm volatile("cp.async.cg.shared.global [%0], [%1], 16;" :: "r"(dst), "l"(src));
}

// ---------------- conversion kernels ---------------------------------------------
__global__ void wconv_kernel(const float* __restrict__ W, __nv_bfloat16* __restrict__ whi,
                             __nv_bfloat16* __restrict__ wlo, int K, int N) {
    __shared__ float t[32][33];
    int n0 = blockIdx.x * 32, k0 = blockIdx.y * 32;
    int tx = threadIdx.x, ty = threadIdx.y;
#pragma unroll
    for (int j = 0; j < 4; j++)
        t[ty + 8 * j][tx] = W[(long)(k0 + ty + 8 * j) * N + n0 + tx];
    __syncthreads();
#pragma unroll
    for (int j = 0; j < 4; j++) {
        int n = n0 + ty + 8 * j;
        float x = t[tx][ty + 8 * j];
        __nv_bfloat16 h = __float2bfloat16(x);
        float r = x - __bfloat162float(h);
        long o = (long)n * K + k0 + tx;
        whi[o] = h;
        wlo[o] = __float2bfloat16(r);
    }
}

__global__ void wconv16_kernel(const float* __restrict__ W, __half* __restrict__ w16,
                               int K, int N) {
    __shared__ float t[32][33];
    int n0 = blockIdx.x * 32, k0 = blockIdx.y * 32;
    int tx = threadIdx.x, ty = threadIdx.y;
#pragma unroll
    for (int j = 0; j < 4; j++)
        t[ty + 8 * j][tx] = W[(long)(k0 + ty + 8 * j) * N + n0 + tx];
    __syncthreads();
#pragma unroll
    for (int j = 0; j < 4; j++) {
        int n = n0 + ty + 8 * j;
        w16[(long)n * K + k0 + tx] = __float2half_rn(t[tx][ty + 8 * j]);
    }
}

__global__ void aconv_kernel(const float* __restrict__ A, __nv_bfloat16* __restrict__ ahi,
                             __nv_bfloat16* __restrict__ alo, int n) {
    int i = blockIdx.x * 256 + threadIdx.x;
    if (i >= n) return;
    float x = A[i];
    __nv_bfloat16 h = __float2bfloat16(x);
    ahi[i] = h;
    alo[i] = __float2bfloat16(x - __bfloat162float(h));
}

__global__ void aconv_gather_kernel(const float* __restrict__ emb, const int* __restrict__ idx,
                                    __nv_bfloat16* __restrict__ ahi, __nv_bfloat16* __restrict__ alo,
                                    int n) {
    int i = blockIdx.x * 256 + threadIdx.x;
    if (i >= n) return;
    int r = i >> 10, k = i & 1023;
    float x = emb[(long)idx[r] * HH + k];
    __nv_bfloat16 h = __float2bfloat16(x);
    ahi[i] = h;
    alo[i] = __float2bfloat16(x - __bfloat162float(h));
}

// ---------------- bf16 3-product HMMA GEMM ----------------------------------------
#define MM_PITCH 40
#define MM_MAT (128 * MM_PITCH * 2)
#define MM_STAGE (4 * MM_MAT)
#define MM_SMEM (2 * MM_STAGE)

__global__ __launch_bounds__(256, 2)
void mma_gemm_kernel(const __nv_bfloat16* __restrict__ Ahi, const __nv_bfloat16* __restrict__ Alo,
                     const __nv_bfloat16* __restrict__ Bhi, const __nv_bfloat16* __restrict__ Blo,
                     const float* __restrict__ bias, float* __restrict__ C, int K, int N,
                     __nv_bfloat16* __restrict__ Chi, __nv_bfloat16* __restrict__ Clo) {
    extern __shared__ __align__(16) char smem[];
    const uint32_t sb = smem_to_u32(smem);
    const int tid = threadIdx.x;
    const int wid = tid >> 5, lane = tid & 31;
    const int m0 = blockIdx.x * 128, n0 = blockIdx.y * 128;
    const int wm = (wid >> 1) * 32;
    const int wn = (wid & 1) * 64;
    const int NC = K >> 5;

    const __nv_bfloat16* gp0 = Ahi + (long)m0 * K;
    const __nv_bfloat16* gp1 = Alo + (long)m0 * K;
    const __nv_bfloat16* gp2 = Bhi + (long)n0 * K;
    const __nv_bfloat16* gp3 = Blo + (long)n0 * K;

    const __nv_bfloat16* gptr[8];
    uint32_t soff[8];
#pragma unroll
    for (int j = 0; j < 8; j++) {
        int i = tid + j * 256;
        int mat = i >> 9, r = (i >> 2) & 127, s = i & 3;
        const __nv_bfloat16* g = (mat == 0) ? gp0 : (mat == 1) ? gp1 : (mat == 2) ? gp2 : gp3;
        gptr[j] = g + (long)r * K + s * 8;
        soff[j] = (uint32_t)(mat * MM_MAT + r * (MM_PITCH * 2) + s * 16);
    }

    float acc[2][8][4];
#pragma unroll
    for (int a = 0; a < 2; a++)
#pragma unroll
        for (int b = 0; b < 8; b++)
#pragma unroll
            for (int c = 0; c < 4; c++) acc[a][b][c] = 0.0f;

    const int arow = lane & 15;
    const int acol = (lane >> 4) << 3;
    const int brow = ((lane >> 4) << 3) + (lane & 7);
    const int bcol = ((lane >> 3) & 1) << 3;

    auto issue = [&](int c, int buf) {
        const uint32_t b0 = sb + buf * MM_STAGE;
#pragma unroll
        for (int j = 0; j < 8; j++) cp16(b0 + soff[j], gptr[j] + c * 32);
        asm volatile("cp.async.commit_group;" ::: "memory");
    };

    issue(0, 0);

    for (int c = 0; c < NC; c++) {
        const int buf = c & 1;
        if (c + 1 < NC) {
            issue(c + 1, buf ^ 1);
            asm volatile("cp.async.wait_group 1;" ::: "memory");
        } else {
            asm volatile("cp.async.wait_group 0;" ::: "memory");
        }
        __syncthreads();

        const uint32_t base = sb + buf * MM_STAGE;
#pragma unroll
        for (int ks = 0; ks < 2; ks++) {
            const int kc = ks * 16;
            uint32_t ah[2][4], al[2][4], bb[4][4];
#pragma unroll
            for (int tm = 0; tm < 2; tm++) {
                uint32_t ad = base + (uint32_t)(((wm + tm * 16 + arow) * MM_PITCH + kc + acol) * 2);
                ldsm_x4(ah[tm], ad);
                ldsm_x4(al[tm], ad + MM_MAT);
            }
#pragma unroll
            for (int gn = 0; gn < 4; gn++) {
                uint32_t bd = base + 2 * MM_MAT +
                    (uint32_t)(((wn + gn * 16 + brow) * MM_PITCH + kc + bcol) * 2);
                ldsm_x4(bb[gn], bd);
            }
#pragma unroll
            for (int tm = 0; tm < 2; tm++)
#pragma unroll
                for (int j = 0; j < 8; j++) {
                    uint32_t b0 = bb[j >> 1][(j & 1) * 2];
                    uint32_t b1 = bb[j >> 1][(j & 1) * 2 + 1];
                    mma16816(acc[tm][j], ah[tm], b0, b1);
                    mma16816(acc[tm][j], al[tm], b0, b1);
                }
#pragma unroll
            for (int gn = 0; gn < 4; gn++) {
                uint32_t bd = base + 3 * MM_MAT +
                    (uint32_t)(((wn + gn * 16 + brow) * MM_PITCH + kc + bcol) * 2);
                ldsm_x4(bb[gn], bd);
            }
#pragma unroll
            for (int tm = 0; tm < 2; tm++)
#pragma unroll
                for (int j = 0; j < 8; j++)
                    mma16816(acc[tm][j], ah[tm],
                             bb[j >> 1][(j & 1) * 2], bb[j >> 1][(j & 1) * 2 + 1]);
        }
        __syncthreads();
    }

#pragma unroll
    for (int tm = 0; tm < 2; tm++) {
        const int r0 = m0 + wm + tm * 16 + (lane >> 2);
#pragma unroll
        for (int j = 0; j < 8; j++) {
            const int col = n0 + wn + j * 8 + (lane & 3) * 2;
            float b0 = bias[col], b1 = bias[col + 1];
            float v0 = acc[tm][j][0] + b0, v1 = acc[tm][j][1] + b1;
            float v2 = acc[tm][j][2] + b0, v3 = acc[tm][j][3] + b1;
            long o0 = (long)r0 * N + col;
            long o1 = o0 + 8 * (long)N;
            C[o0] = v0; C[o0 + 1] = v1;
            C[o1] = v2; C[o1 + 1] = v3;
            if (Chi) {
                __nv_bfloat16 t0 = __float2bfloat16(v0), t1 = __float2bfloat16(v1);
                __nv_bfloat16 t2 = __float2bfloat16(v2), t3 = __float2bfloat16(v3);
                Chi[o0] = t0; Chi[o0 + 1] = t1; Chi[o1] = t2; Chi[o1 + 1] = t3;
                Clo[o0] = __float2bfloat16(v0 - __bfloat162float(t0));
                Clo[o0 + 1] = __float2bfloat16(v1 - __bfloat162float(t1));
                Clo[o1] = __float2bfloat16(v2 - __bfloat162float(t2));
                Clo[o1 + 1] = __float2bfloat16(v3 - __bfloat162float(t3));
            }
        }
    }
}

// ---------------- fp16 HMMA GEMM (TWO: A hi+lo; else single) ----------------------
#define F6_MAT (128 * MM_PITCH * 2)
#define F6_SMEM_MAX (2 * 3 * F6_MAT)

template <bool TWO>
__global__ __launch_bounds__(256, 2)
void mma_f16_kernel(const __half* __restrict__ Ahi, const __half* __restrict__ Alo,
                    const __half* __restrict__ Bf, const float* __restrict__ bias,
                    float* __restrict__ C, int K, int N, int lda) {
    constexpr int MATS = TWO ? 3 : 2;
    constexpr int STAGE = MATS * F6_MAT;
    constexpr int NCP = MATS * 2;
    extern __shared__ __align__(16) char smem[];
    const uint32_t sb = smem_to_u32(smem);
    const int tid = threadIdx.x;
    const int wid = tid >> 5, lane = tid & 31;
    const int m0 = blockIdx.x * 128, n0 = blockIdx.y * 128;
    const int wm = (wid >> 1) * 32;
    const int wn = (wid & 1) * 64;
    const int NC = K >> 5;
    const int bmat = (MATS - 1) * F6_MAT;

    const __half* gp0 = Ahi + (long)m0 * lda;
    const __half* gp1 = TWO ? (Alo + (long)m0 * lda) : nullptr;
    const __half* gp2 = Bf + (long)n0 * K;

    const __half* gptr[NCP];
    uint32_t soff[NCP];
#pragma unroll
    for (int j = 0; j < NCP; j++) {
        int i = tid + j * 256;
        int mat = i >> 9, r = (i >> 2) & 127, s = i & 3;
        const __half* g;
        if (mat == 0) g = gp0 + (long)r * lda;
        else if (TWO && mat == 1) g = gp1 + (long)r * lda;
        else g = gp2 + (long)r * K;
        gptr[j] = g + s * 8;
        soff[j] = (uint32_t)(mat * F6_MAT + r * (MM_PITCH * 2) + s * 16);
    }

    float acc[2][8][4];
#pragma unroll
    for (int a = 0; a < 2; a++)
#pragma unroll
        for (int b = 0; b < 8; b++)
#pragma unroll
            for (int c = 0; c < 4; c++) acc[a][b][c] = 0.0f;

    const int arow = lane & 15;
    const int acol = (lane >> 4) << 3;
    const int brow = ((lane >> 4) << 3) + (lane & 7);
    const int bcol = ((lane >> 3) & 1) << 3;

    auto issue = [&](int c, int buf) {
        const uint32_t b0 = sb + buf * STAGE;
#pragma unroll
        for (int j = 0; j < NCP; j++) cp16(b0 + soff[j], gptr[j] + c * 32);
        asm volatile("cp.async.commit_group;" ::: "memory");
    };

    issue(0, 0);

    for (int c = 0; c < NC; c++) {
        const int buf = c & 1;
        if (c + 1 < NC) {
            issue(c + 1, buf ^ 1);
            asm volatile("cp.async.wait_group 1;" ::: "memory");
        } else {
            asm volatile("cp.async.wait_group 0;" ::: "memory");
        }
        __syncthreads();

        const uint32_t base = sb + buf * STAGE;
#pragma unroll
        for (int ks = 0; ks < 2; ks++) {
            const int kc = ks * 16;
            uint32_t ah[2][4], al[2][4], bb[4][4];
#pragma unroll
            for (int tm = 0; tm < 2; tm++) {
                uint32_t ad = base + (uint32_t)(((wm + tm * 16 + arow) * MM_PITCH + kc + acol) * 2);
                ldsm_x4(ah[tm], ad);
                if (TWO) ldsm_x4(al[tm], ad + F6_MAT);
            }
#pragma unroll
            for (int gn = 0; gn < 4; gn++) {
                uint32_t bd = base + bmat +
                    (uint32_t)(((wn + gn * 16 + brow) * MM_PITCH + kc + bcol) * 2);
                ldsm_x4(bb[gn], bd);
            }
#pragma unroll
            for (int tm = 0; tm < 2; tm++)
#pragma unroll
                for (int j = 0; j < 8; j++) {
                    uint32_t b0 = bb[j >> 1][(j & 1) * 2];
                    uint32_t b1 = bb[j >> 1][(j & 1) * 2 + 1];
                    mma16816h(acc[tm][j], ah[tm], b0, b1);
                    if (TWO) mma16816h(acc[tm][j], al[tm], b0, b1);
                }
        }
        __syncthreads();
    }

#pragma unroll
    for (int tm = 0; tm < 2; tm++) {
        const int r0 = m0 + wm + tm * 16 + (lane >> 2);
#pragma unroll
        for (int j = 0; j < 8; j++) {
            const int col = n0 + wn + j * 8 + (lane & 3) * 2;
            float b0 = bias[col], b1 = bias[col + 1];
            long o0 = (long)r0 * N + col;
            long o1 = o0 + 8 * (long)N;
            C[o0] = acc[tm][j][0] + b0;
            C[o0 + 1] = acc[tm][j][1] + b1;
            C[o1] = acc[tm][j][2] + b0;
            C[o1 + 1] = acc[tm][j][3] + b1;
        }
    }
}

// ---------------- recurrence HMMA GEMM: gh[32,3072] = h @ Whh^T -------------------
#define RN_PITCH 72
#define RN_AMAT (32 * RN_PITCH * 2)
#define RN_BMAT (64 * RN_PITCH * 2)
#define RN_STAGE (2 * RN_AMAT + 2 * RN_BMAT)
#define RN_SMEM (2 * RN_STAGE)

__global__ __launch_bounds__(256, 2)
void rnn_gemm_kernel(const __nv_bfloat16* __restrict__ hhi, const __nv_bfloat16* __restrict__ hlo,
                     const __nv_bfloat16* __restrict__ bhi, const __nv_bfloat16* __restrict__ blo,
                     float* __restrict__ gh) {
    extern __shared__ __align__(16) char smem[];
    const uint32_t sb = smem_to_u32(smem);
    const int tid = threadIdx.x;
    const int wid = tid >> 5, lane = tid & 31;
    const int n0 = blockIdx.x * 64;
    const int wm2 = wid >> 2;
    const int wn2 = wid & 3;

    const __nv_bfloat16* gptr[6];
    uint32_t soff[6];
#pragma unroll
    for (int j = 0; j < 6; j++) {
        int i = tid + j * 256;
        if (i < 512) {
            int ii = i & 255;
            int r = ii >> 3, s = ii & 7;
            const __nv_bfloat16* g = (i < 256) ? hhi : hlo;
            gptr[j] = g + r * HH + s * 8;
            soff[j] = (uint32_t)((i < 256 ? 0 : RN_AMAT) + r * (RN_PITCH * 2) + s * 16);
        } else {
            int ii = (i - 512) & 511;
            int r = ii >> 3, s = ii & 7;
            const __nv_bfloat16* g = (i < 1024) ? bhi : blo;
            gptr[j] = g + (long)(n0 + r) * HH + s * 8;
            soff[j] = (uint32_t)(2 * RN_AMAT + (i < 1024 ? 0 : RN_BMAT) + r * (RN_PITCH * 2) + s * 16);
        }
    }

    float acc[2][4];
#pragma unroll
    for (int j = 0; j < 2; j++)
#pragma unroll
        for (int c = 0; c < 4; c++) acc[j][c] = 0.0f;

    const int arow = lane & 15;
    const int acol = (lane >> 4) << 3;
    const int brow = ((lane >> 4) << 3) + (lane & 7);
    const int bcol = ((lane >> 3) & 1) << 3;

    auto issue = [&](int c, int buf) {
        const uint32_t b0 = sb + buf * RN_STAGE;
#pragma unroll
        for (int j = 0; j < 6; j++) cp16(b0 + soff[j], gptr[j] + c * 64);
        asm volatile("cp.async.commit_group;" ::: "memory");
    };

    issue(0, 0);
    const int NC = HH / 64;
    for (int c = 0; c < NC; c++) {
        const int buf = c & 1;
        if (c + 1 < NC) {
            issue(c + 1, buf ^ 1);
            asm volatile("cp.async.wait_group 1;" ::: "memory");
        } else {
            asm volatile("cp.async.wait_group 0;" ::: "memory");
        }
        __syncthreads();

        const uint32_t base = sb + buf * RN_STAGE;
#pragma unroll
        for (int ks = 0; ks < 4; ks++) {
            const int kc = ks * 16;
            uint32_t ah[4], al[4], bh[4], bl[4];
            uint32_t ad = base + (uint32_t)(((wm2 * 16 + arow) * RN_PITCH + kc + acol) * 2);
            ldsm_x4(ah, ad);
            ldsm_x4(al, ad + RN_AMAT);
            uint32_t bd = base + 2 * RN_AMAT +
                (uint32_t)(((wn2 * 16 + brow) * RN_PITCH + kc + bcol) * 2);
            ldsm_x4(bh, bd);
            ldsm_x4(bl, bd + RN_BMAT);
#pragma unroll
            for (int j = 0; j < 2; j++) {
                mma16816(acc[j], ah, bh[j * 2], bh[j * 2 + 1]);
                mma16816(acc[j], al, bh[j * 2], bh[j * 2 + 1]);
                mma16816(acc[j], ah, bl[j * 2], bl[j * 2 + 1]);
            }
        }
        __syncthreads();
    }

    const int row = wm2 * 16 + (lane >> 2);
#pragma unroll
    for (int j = 0; j < 2; j++) {
        const int col = n0 + wn2 * 16 + j * 8 + (lane & 3) * 2;
        gh[row * H3 + col] = acc[j][0];
        gh[row * H3 + col + 1] = acc[j][1];
        gh[(row + 8) * H3 + col] = acc[j][2];
        gh[(row + 8) * H3 + col + 1] = acc[j][3];
    }
}

// ---------------- small-M fp32 split-K GEMM (h0 only) ----------------------------
__global__ void gemm_m32_kernel(const float* __restrict__ A, const float* __restrict__ Bm,
                                float* __restrict__ Cp, int N, int K, int ksplit) {
    extern __shared__ float sh[];
    const int kslice = K / ksplit;
    const int tid = threadIdx.x;
    const int k0 = blockIdx.y * kslice;

    for (int i = tid; i < 32 * kslice; i += 256) {
        int b = i / kslice;
        int k = i - b * kslice;
        sh[k * 33 + b] = A[b * K + k0 + k];
    }
    __syncthreads();

    const int w = tid >> 5, lane = tid & 31;
    const int n0 = blockIdx.x * 32 + w * 4;
    const float* Bp = Bm + (long)k0 * N + n0;
    float a0 = 0.f, a1 = 0.f, a2 = 0.f, a3 = 0.f;
#pragma unroll 8
    for (int k = 0; k < kslice; k++) {
        float4 wv = *(const float4*)(Bp + (long)k * N);
        float a = sh[k * 33 + lane];
        a0 += a * wv.x; a1 += a * wv.y; a2 += a * wv.z; a3 += a * wv.w;
    }
    float4* o = (float4*)(Cp + ((long)blockIdx.y * 32 + lane) * N + n0);
    *o = make_float4(a0, a1, a2, a3);
}

__global__ void reduce8_bias_kernel(const float* __restrict__ part, const float* __restrict__ bias,
                                    float* __restrict__ out, int n, int biasN) {
    int i = blockIdx.x * 256 + threadIdx.x;
    if (i >= n) return;
    float s = bias[i % biasN];
#pragma unroll
    for (int p = 0; p < KSPLIT; p++) s += part[(long)p * n + i];
    out[i] = s;
}

__global__ void hconv_kernel(const float* __restrict__ h, __nv_bfloat16* __restrict__ hhi,
                             __nv_bfloat16* __restrict__ hlo) {
    int i = blockIdx.x * 256 + threadIdx.x;
    if (i >= BB * HH) return;
    float x = h[i];
    __nv_bfloat16 t = __float2bfloat16(x);
    hhi[i] = t;
    hlo[i] = __float2bfloat16(x - __bfloat162float(t));
}

// ---------------- fused GRU gates ------------------------------------------------
__global__ void gates_kernel(const float* __restrict__ gi, const float* __restrict__ gh,
                             const float* __restrict__ bhh, float* __restrict__ h,
                             __nv_bfloat16* __restrict__ hhi, __nv_bfloat16* __restrict__ hlo,
                             __half* __restrict__ c16hi, __half* __restrict__ c16lo, int t) {
    int i = blockIdx.x * 256 + threadIdx.x;
    int b = i >> 10;
    int n = i & 1023;
    const float* g = gh + (long)b * H3;
    float hr = bhh[n] + g[n];
    float hz = bhh[HH + n] + g[HH + n];
    float hn = bhh[2 * HH + n] + g[2 * HH + n];
    const float* gir = gi + ((long)b * TT + t) * H3;
    float r = sigmf(gir[n] + hr);
    float z = sigmf(gir[HH + n] + hz);
    float nn = tanhx(gir[2 * HH + n] + r * hn);
    float hv = (1.0f - z) * nn + z * h[i];
    h[i] = hv;
    __nv_bfloat16 th = __float2bfloat16(hv);
    hhi[i] = th;
    hlo[i] = __float2bfloat16(hv - __bfloat162float(th));
    long co = ((long)b * TT + t) * H2 + n;
    __half f = __float2half_rn(hv);
    c16hi[co] = f;
    c16lo[co] = __float2half_rn(hv - __half2float(f));
}

// ---------------- batched scores + softmax ---------------------------------------
__global__ __launch_bounds__(256)
void scores_batch_kernel(const float* __restrict__ qw_all, const float* __restrict__ wc_g,
                         const float* __restrict__ bc, const int* __restrict__ mask,
                         const float* __restrict__ vw, float* __restrict__ wsm) {
    __shared__ float q[HH];
    __shared__ float wcs[HH];
    __shared__ float sc[SS];
    __shared__ float red[SS];
    const int blk = blockIdx.x;
    const int b = blk / TT;
    const int tid = threadIdx.x;
    for (int i = tid; i < HH; i += 256) {
        q[i] = qw_all[(long)blk * HH + i];
        wcs[i] = wc_g[i];
    }
    __syncthreads();
    const int w = tid >> 5, lane = tid & 31;
#pragma unroll
    for (int si = 0; si < 16; si++) {
        const int s = w * 16 + si;
        const float* v = vw + (long)(b * SS + s) * HH;
        float a = 0.0f;
        for (int hh = lane; hh < HH; hh += 32)
            a += wcs[hh] * tanhx(q[hh] + v[hh]);
#pragma unroll
        for (int off = 16; off > 0; off >>= 1) a += __shfl_xor_sync(0xffffffffu, a, off);
        if (lane == 0)
            sc[s] = a + bc[0] + (mask[b * SS + s] == 0 ? -1e30f : 0.0f);
    }
    __syncthreads();
    if (tid < 128) red[tid] = sc[tid];
    __syncthreads();
#pragma unroll
    for (int off = 64; off > 0; off >>= 1) {
        if (tid < off) red[tid] = fmaxf(red[tid], red[tid + off]);
        __syncthreads();
    }
    float mx = red[0];
    __syncthreads();
    float e = 0.0f;
    if (tid < 128) { e = ex2f((sc[tid] - mx) * 1.4426950408889634f); red[tid] = e; }
    __syncthreads();
#pragma unroll
    for (int off = 64; off > 0; off >>= 1) {
        if (tid < off) red[tid] += red[tid + off];
        __syncthreads();
    }
    if (tid < 128) wsm[(long)blk * SS + tid] = e * rcpf(red[0]);
}

// ---------------- batched context ------------------------------------------------
#define CTX_SMEM ((SS * 128 + SS) * 4)
__global__ __launch_bounds__(128)
void ctx_batch_kernel(const float* __restrict__ wsm, const float* __restrict__ values,
                      __half* __restrict__ c16hi) {
    extern __shared__ float csm[];
    float* val = csm;
    float* wv = csm + SS * 128;
    const int b = blockIdx.x;
    const int h0 = blockIdx.y * 128;
    const int tid = threadIdx.x;
    for (int s = 0; s < SS; s++)
        val[s * 128 + tid] = values[(long)(b * SS + s) * HH + h0 + tid];
    __syncthreads();
    for (int t = 0; t < TT; t++) {
        wv[tid] = wsm[((long)b * TT + t) * SS + tid];
        __syncthreads();
        float acc = 0.0f;
#pragma unroll 16
        for (int s = 0; s < SS; s++) acc += wv[s] * val[s * 128 + tid];
        long co = ((long)b * TT + t) * H2 + HH + h0 + tid;
        c16hi[co] = __float2half_rn(acc);
        __syncthreads();
    }
}

__global__ void copyh_kernel(const float* __restrict__ h, float* __restrict__ out) {
    int i = blockIdx.x * 256 + threadIdx.x;
    if (i < BB * HH) out[i] = h[i];
}

// ---------------- launch ----------------------------------------------------------
extern "C" void kernel_launch(void* const* d_in, const int* in_sizes, int n_in,
                              void* d_out, int out_size) {
    const float* enc_out = (const float*)d_in[0];
    const float* enc_hid = (const float*)d_in[1];
    const int*   mask    = (const int*)d_in[2];
    const int*   tgt     = (const int*)d_in[3];
    const float* emb     = (const float*)d_in[4];
    const float* Wq   = (const float*)d_in[5];
    const float* bq   = (const float*)d_in[6];
    const float* Wv   = (const float*)d_in[7];
    const float* bv   = (const float*)d_in[8];
    const float* wc   = (const float*)d_in[9];
    const float* bc   = (const float*)d_in[10];
    const float* Wih  = (const float*)d_in[11];
    const float* bih  = (const float*)d_in[12];
    const float* Whh  = (const float*)d_in[13];
    const float* bhh  = (const float*)d_in[14];
    const float* Wproj = (const float*)d_in[15];
    const float* bproj = (const float*)d_in[16];
    const float* Wout  = (const float*)d_in[17];
    const float* bout  = (const float*)d_in[18];
    float* out = (float*)d_out;

    float *values, *vw, *gi, *qwp, *h, *gh, *qw_all, *wsm;
    __nv_bfloat16 *hhi, *hlo, *ahi, *alo, *a2hi, *a2lo, *whi, *wlo;
    __nv_bfloat16 *wihhi, *wihlo, *eihi, *eilo, *whhThi, *whhTlo;
    __half *c16hi, *c16lo, *w16, *w16q;
    cudaGetSymbolAddress((void**)&values, g_values);
    cudaGetSymbolAddress((void**)&vw, g_vw);
    cudaGetSymbolAddress((void**)&gi, g_gi);
    cudaGetSymbolAddress((void**)&qwp, g_qwp);
    cudaGetSymbolAddress((void**)&h, g_h);
    cudaGetSymbolAddress((void**)&gh, g_gh);
    cudaGetSymbolAddress((void**)&qw_all, g_qw_all);
    cudaGetSymbolAddress((void**)&wsm, g_wsm);
    cudaGetSymbolAddress((void**)&hhi, g_hhi);
    cudaGetSymbolAddress((void**)&hlo, g_hlo);
    cudaGetSymbolAddress((void**)&ahi, g_ahi);
    cudaGetSymbolAddress((void**)&alo, g_alo);
    cudaGetSymbolAddress((void**)&a2hi, g_a2hi);
    cudaGetSymbolAddress((void**)&a2lo, g_a2lo);
    cudaGetSymbolAddress((void**)&whi, g_whi);
    cudaGetSymbolAddress((void**)&wlo, g_wlo);
    cudaGetSymbolAddress((void**)&wihhi, g_wihhi);
    cudaGetSymbolAddress((void**)&wihlo, g_wihlo);
    cudaGetSymbolAddress((void**)&eihi, g_eihi);
    cudaGetSymbolAddress((void**)&eilo, g_eilo);
    cudaGetSymbolAddress((void**)&whhThi, g_whhThi);
    cudaGetSymbolAddress((void**)&whhTlo, g_whhTlo);
    cudaGetSymbolAddress((void**)&c16hi, g_c16hi);
    cudaGetSymbolAddress((void**)&c16lo, g_c16lo);
    cudaGetSymbolAddress((void**)&w16, g_w16);
    cudaGetSymbolAddress((void**)&w16q, g_w16q);

    cudaFuncSetAttribute(mma_gemm_kernel, cudaFuncAttributeMaxDynamicSharedMemorySize, MM_SMEM);
    cudaFuncSetAttribute(mma_f16_kernel<true>, cudaFuncAttributeMaxDynamicSharedMemorySize, F6_SMEM_MAX);
    cudaFuncSetAttribute(mma_f16_kernel<false>, cudaFuncAttributeMaxDynamicSharedMemorySize, 2 * 2 * F6_MAT);
    cudaFuncSetAttribute(rnn_gemm_kernel, cudaFuncAttributeMaxDynamicSharedMemorySize, RN_SMEM);
    cudaFuncSetAttribute(ctx_batch_kernel, cudaFuncAttributeMaxDynamicSharedMemorySize, CTX_SMEM);

    // one-time stream/event resources (host-side only; per-call work is identical)
    static cudaStream_t s2 = nullptr;
    static cudaEvent_t evF = nullptr, evJ = nullptr;
    static bool tried = false;
    if (!tried) {
        tried = true;
        if (cudaStreamCreateWithFlags(&s2, cudaStreamNonBlocking) != cudaSuccess) s2 = nullptr;
        if (s2) {
            if (cudaEventCreateWithFlags(&evF, cudaEventDisableTiming) != cudaSuccess ||
                cudaEventCreateWithFlags(&evJ, cudaEventDisableTiming) != cudaSuccess) {
                s2 = nullptr;
            }
        }
    }
    const bool fork = (s2 != nullptr);
    cudaStream_t sA = fork ? s2 : (cudaStream_t)0;   // side work stream

    // ---- fork ----
    if (fork) {
        cudaEventRecord(evF, 0);
        cudaStreamWaitEvent(s2, evF, 0);
    }

    // ---- side stream: everything h-independent, consumed post-loop ----
    // values = enc_out @ Wproj + bproj ; vw = values @ Wv + bv
    wconv_kernel<<<dim3(HH / 32, H2 / 32), dim3(32, 8), 0, sA>>>(Wproj, whi, wlo, H2, HH);
    aconv_kernel<<<(4096 * 2048) / 256, 256, 0, sA>>>(enc_out, ahi, alo, 4096 * 2048);
    mma_gemm_kernel<<<dim3(4096 / 128, HH / 128), 256, MM_SMEM, sA>>>(
        ahi, alo, whi, wlo, bproj, values, H2, HH, a2hi, a2lo);
    wconv_kernel<<<dim3(HH / 32, HH / 32), dim3(32, 8), 0, sA>>>(Wv, whi, wlo, HH, HH);
    mma_gemm_kernel<<<dim3(4096 / 128, HH / 128), 256, MM_SMEM, sA>>>(
        a2hi, a2lo, whi, wlo, bv, vw, HH, HH, nullptr, nullptr);
    wconv16_kernel<<<dim3(VV / 32, H2 / 32), dim3(32, 8), 0, sA>>>(Wout, w16, H2, VV);
    wconv16_kernel<<<dim3(HH / 32, HH / 32), dim3(32, 8), 0, sA>>>(Wq, w16q, HH, HH);
    if (fork) cudaEventRecord(evJ, s2);

    // ---- main stream: gi path + h0 + serial recurrence ----
    wconv_kernel<<<dim3(H3 / 32, HH / 32), dim3(32, 8)>>>(Whh, whhThi, whhTlo, HH, H3);
    wconv_kernel<<<dim3(H3 / 32, HH / 32), dim3(32, 8)>>>(Wih, wihhi, wihlo, HH, H3);
    aconv_gather_kernel<<<(BB * TT * HH) / 256, 256>>>(emb, tgt, eihi, eilo, BB * TT * HH);
    mma_gemm_kernel<<<dim3((BB * TT) / 128, H3 / 128), 256, MM_SMEM>>>(
        eihi, eilo, wihhi, wihlo, bih, gi, HH, H3, nullptr, nullptr);
    gemm_m32_kernel<<<dim3(HH / 32, KSPLIT), 256, (H2 / KSPLIT) * 33 * 4>>>(enc_hid, Wproj, qwp, HH, H2, KSPLIT);
    reduce8_bias_kernel<<<(BB * HH + 255) / 256, 256>>>(qwp, bproj, h, BB * HH, HH);
    hconv_kernel<<<(BB * HH + 255) / 256, 256>>>(h, hhi, hlo);
    rnn_gemm_kernel<<<H3 / 64, 256, RN_SMEM>>>(hhi, hlo, whhThi, whhTlo, gh);

    for (int t = 0; t < TT; t++) {
        gates_kernel<<<(BB * HH) / 256, 256>>>(gi, gh, bhh, h, hhi, hlo, c16hi, c16lo, t);
        if (t + 1 < TT)
            rnn_gemm_kernel<<<H3 / 64, 256, RN_SMEM>>>(hhi, hlo, whhThi, whhTlo, gh);
    }

    // ---- join ----
    if (fork) cudaStreamWaitEvent((cudaStream_t)0, evJ, 0);

    // ---- batched attention (needs c16 from loop + vw/values/w16q from side) ----
    mma_f16_kernel<true><<<dim3((BB * TT) / 128, HH / 128), 256, 2 * 3 * F6_MAT>>>(
        c16hi, c16lo, w16q, bq, qw_all, HH, HH, H2);
    scores_batch_kernel<<<BB * TT, 256>>>(qw_all, wc, bc, mask, vw, wsm);
    ctx_batch_kernel<<<dim3(BB, HH / 128), 128, CTX_SMEM>>>(wsm, values, c16hi);

    // ---- Phase C: logits (fp16 single-product) ----
    mma_f16_kernel<false><<<dim3((BB * TT) / 128, VV / 128), 256, 2 * 2 * F6_MAT>>>(
        c16hi, nullptr, w16, bout, out, H2, VV, H2);

    long btv = (long)BB * TT * VV;
    if ((long)out_size >= btv + BB * HH)
        copyh_kernel<<<(BB * HH + 255) / 256, 256>>>(h, out + btv);
}